// round 1
// baseline (speedup 1.0000x reference)
#include <cuda_runtime.h>
#include <cuda_bf16.h>
#include <math.h>

// Problem constants (fixed by the reference)
#define B_   2
#define T_   1024
#define S_   2048
#define D_   4096
#define NQ   32
#define NKV  8
#define HD   128
#define GQA  (NQ / NKV)   // 4
#define MTOT (B_ * T_)    // 2048

#define NEG_INF (-INFINITY)

// -------- scratch (device globals; allocation-free) --------
__device__ float g_q[(size_t)MTOT * NQ * HD];    // 32 MB  [b*T+t][n*H+h]
__device__ float g_k[(size_t)MTOT * NKV * HD];   //  8 MB
__device__ float g_v[(size_t)MTOT * NKV * HD];   //  8 MB
__device__ float g_o[(size_t)MTOT * NQ * HD];    // 32 MB  attention output (BTNH)
__device__ int   g_start[B_];
__device__ int   g_first[B_];

// ============================================================
// 1) segment scan: start[b] = #leading positions before first nonzero,
//    first[b] = argmax(segment_ids[b])
// ============================================================
__global__ void startfirst_kernel(const int* __restrict__ seg) {
    int b = blockIdx.x;
    const int* s = seg + (size_t)b * T_;
    __shared__ int sh_min, sh_max, sh_first;
    if (threadIdx.x == 0) { sh_min = T_; sh_max = INT_MIN; sh_first = T_; }
    __syncthreads();
    int lmin = T_, lmax = INT_MIN;
    for (int t = threadIdx.x; t < T_; t += blockDim.x) {
        int v = s[t];
        if (v != 0 && t < lmin) lmin = t;
        if (v > lmax) lmax = v;
    }
    atomicMin(&sh_min, lmin);
    atomicMax(&sh_max, lmax);
    __syncthreads();
    int mx = sh_max;
    int lfirst = T_;
    for (int t = threadIdx.x; t < T_; t += blockDim.x)
        if (s[t] == mx && t < lfirst) lfirst = t;
    atomicMin(&sh_first, lfirst);
    __syncthreads();
    if (threadIdx.x == 0) { g_start[b] = sh_min; g_first[b] = sh_first; }
}

// ============================================================
// 2) SGEMM: C[M x Ncols] = A[M x K] * Bm[K x Ncols], all row-major fp32
//    BM=BN=128, BK=16, 256 threads, 8x8 per-thread microtile.
//    M fixed by grid (grid.y * 128), K and Ncols multiples of 16/128.
// ============================================================
__global__ __launch_bounds__(256) void sgemm_kernel(
    const float* __restrict__ A, const float* __restrict__ Bm,
    float* __restrict__ C, int Ncols, int K)
{
    __shared__ float As[16][132];
    __shared__ float Bs[16][132];

    const int tid  = threadIdx.x;
    const int row0 = blockIdx.y * 128;
    const int col0 = blockIdx.x * 128;
    const int rc   = (tid >> 4) * 8;   // 0..120
    const int cc   = (tid & 15) * 8;   // 0..120

    float acc[8][8];
#pragma unroll
    for (int i = 0; i < 8; ++i)
#pragma unroll
        for (int j = 0; j < 8; ++j) acc[i][j] = 0.f;

    for (int k0 = 0; k0 < K; k0 += 16) {
        // load A tile (128x16) transposed into As
#pragma unroll
        for (int i = 0; i < 2; ++i) {
            int f  = tid + 256 * i;      // 0..511 float4 id
            int r  = f >> 2;             // 0..127
            int kq = f & 3;              // 0..3
            float4 v = *reinterpret_cast<const float4*>(
                &A[(size_t)(row0 + r) * K + k0 + kq * 4]);
            As[kq * 4 + 0][r] = v.x;
            As[kq * 4 + 1][r] = v.y;
            As[kq * 4 + 2][r] = v.z;
            As[kq * 4 + 3][r] = v.w;
        }
        // load B tile (16x128)
#pragma unroll
        for (int i = 0; i < 2; ++i) {
            int f  = tid + 256 * i;
            int kk = f >> 5;             // 0..15
            int c4 = f & 31;             // 0..31
            *reinterpret_cast<float4*>(&Bs[kk][c4 * 4]) =
                *reinterpret_cast<const float4*>(
                    &Bm[(size_t)(k0 + kk) * Ncols + col0 + c4 * 4]);
        }
        __syncthreads();

#pragma unroll
        for (int kk = 0; kk < 16; ++kk) {
            float a[8], bb[8];
            *reinterpret_cast<float4*>(&a[0])  = *reinterpret_cast<float4*>(&As[kk][rc]);
            *reinterpret_cast<float4*>(&a[4])  = *reinterpret_cast<float4*>(&As[kk][rc + 4]);
            *reinterpret_cast<float4*>(&bb[0]) = *reinterpret_cast<float4*>(&Bs[kk][cc]);
            *reinterpret_cast<float4*>(&bb[4]) = *reinterpret_cast<float4*>(&Bs[kk][cc + 4]);
#pragma unroll
            for (int i = 0; i < 8; ++i)
#pragma unroll
                for (int j = 0; j < 8; ++j)
                    acc[i][j] = fmaf(a[i], bb[j], acc[i][j]);
        }
        __syncthreads();
    }

#pragma unroll
    for (int i = 0; i < 8; ++i) {
        float4 o0 = make_float4(acc[i][0], acc[i][1], acc[i][2], acc[i][3]);
        float4 o1 = make_float4(acc[i][4], acc[i][5], acc[i][6], acc[i][7]);
        size_t base = (size_t)(row0 + rc + i) * Ncols + col0 + cc;
        *reinterpret_cast<float4*>(&C[base])     = o0;
        *reinterpret_cast<float4*>(&C[base + 4]) = o1;
    }
}

// ============================================================
// 3) fused RMSNorm + RoPE over q (heads 0..NQ-1) and k (heads NQ..NQ+NKV-1)
//    one 128-thread block per (b*T+t, head)
// ============================================================
__global__ __launch_bounds__(128) void ropenorm_kernel(
    const float* __restrict__ qscale, const float* __restrict__ kscale,
    const int* __restrict__ seg)
{
    const int bt = blockIdx.x;            // b*T + t
    const int b  = bt >> 10;              // T_=1024
    const int t  = bt & (T_ - 1);
    const int hd = blockIdx.y;
    const int h  = threadIdx.x;
    const int lane = h & 31, wid = h >> 5;

    float* buf;
    const float* sc;
    if (hd < NQ) { buf = &g_q[((size_t)bt * NQ + hd) * HD];        sc = qscale; }
    else         { buf = &g_k[((size_t)bt * NKV + (hd - NQ)) * HD]; sc = kscale; }

    float v = buf[h];
    float ss = v * v;
#pragma unroll
    for (int off = 16; off; off >>= 1) ss += __shfl_xor_sync(0xffffffffu, ss, off);
    __shared__ float red[4];
    if (lane == 0) red[wid] = ss;
    __syncthreads();
    float tot = red[0] + red[1] + red[2] + red[3];
    float xn = sc[h] * v * rsqrtf(tot * (1.0f / HD) + 1e-6f);

    __shared__ float row[HD];
    row[h] = xn;
    __syncthreads();

    int segv  = seg[bt];
    int first = g_first[b];
    float pos = (segv != 0) ? (float)(t - first) : 1073741824.0f;
    int k2 = (h < 64) ? h : (h - 64);
    // inv_freq = 1e6^(-2k/128) = exp2(-(2k/128)*log2(1e6))
    float invf = exp2f((-2.0f * (float)k2 / 128.0f) * 19.931568569324174f);
    float ang = pos * invf;
    float s_, c_;
    __sincosf(ang, &s_, &c_);
    // fp32-accurate sin/cos (positions are small; use precise version)
    s_ = sinf(ang); c_ = cosf(ang);

    float r;
    if (h < 64) r = xn * c_ - row[h + 64] * s_;
    else        r = xn * c_ + row[h - 64] * s_;
    buf[h] = r;
}

// ============================================================
// 4) attention: one block = (8 query rows) x (one q head) x (batch)
//    online softmax, 32-key smem tiles, GQA kv head = n/4
// ============================================================
__global__ __launch_bounds__(256) void attn_kernel() {
    __shared__ float Qs[8][133];
    __shared__ float Ks[32][133];
    __shared__ float Vs[32][133];
    __shared__ float Ps[8][32];

    const int tid  = threadIdx.x;
    const int wid  = tid >> 5;
    const int lane = tid & 31;
    const int b  = blockIdx.z;
    const int n  = blockIdx.y;
    const int kh = n >> 2;                 // GQA = 4
    const int t0 = blockIdx.x * 8;
    const float SCALE = 0.08838834764831845f;  // 1/sqrt(128)

    // load 8 query rows (pre-scaled)
    for (int idx = tid; idx < 8 * HD; idx += 256) {
        int w = idx >> 7, d = idx & 127;
        Qs[w][d] = g_q[((size_t)(b * T_ + t0 + w) * NQ + n) * HD + d] * SCALE;
    }
    const int start = g_start[b];
    const int t_my  = t0 + wid;
    const int t_max = t0 + 7;

    float m = NEG_INF, l = 0.f;
    float acc0 = 0.f, acc1 = 0.f, acc2 = 0.f, acc3 = 0.f;

    int s_begin = (start >> 5) << 5;
    __syncthreads();

    for (int s0 = s_begin; s0 <= t_max; s0 += 32) {
        // cooperative K/V tile load
        for (int idx = tid; idx < 32 * HD; idx += 256) {
            int sl = idx >> 7, d = idx & 127;
            int s = s0 + sl;
            float kv = 0.f, vv = 0.f;
            if (s < T_) {
                size_t base = ((size_t)(b * T_ + s) * NKV + kh) * HD + d;
                kv = g_k[base];
                vv = g_v[base];
            }
            Ks[sl][d] = kv;
            Vs[sl][d] = vv;
        }
        __syncthreads();

        if (s0 <= t_my) {  // warp has at least one valid key in this tile
            int s = s0 + lane;
            bool valid = (s >= start) && (s <= t_my);
            float sc = 0.f;
#pragma unroll 16
            for (int d = 0; d < HD; ++d)
                sc = fmaf(Qs[wid][d], Ks[lane][d], sc);
            float score = valid ? sc : NEG_INF;

            float mt = score;
#pragma unroll
            for (int off = 16; off; off >>= 1)
                mt = fmaxf(mt, __shfl_xor_sync(0xffffffffu, mt, off));
            float m_new = fmaxf(m, mt);
            float alpha = (m_new == NEG_INF) ? 1.0f : __expf(m - m_new);
            float p = valid ? __expf(score - m_new) : 0.f;
            float psum = p;
#pragma unroll
            for (int off = 16; off; off >>= 1)
                psum += __shfl_xor_sync(0xffffffffu, psum, off);
            l = l * alpha + psum;
            m = m_new;
            Ps[wid][lane] = p;
            __syncwarp();

            acc0 *= alpha; acc1 *= alpha; acc2 *= alpha; acc3 *= alpha;
#pragma unroll 8
            for (int sl = 0; sl < 32; ++sl) {
                float p_s = Ps[wid][sl];
                acc0 = fmaf(p_s, Vs[sl][lane],      acc0);
                acc1 = fmaf(p_s, Vs[sl][lane + 32], acc1);
                acc2 = fmaf(p_s, Vs[sl][lane + 64], acc2);
                acc3 = fmaf(p_s, Vs[sl][lane + 96], acc3);
            }
        }
        __syncthreads();
    }

    float invl = (l > 0.f) ? (1.0f / l) : 0.f;
    size_t ob = ((size_t)(b * T_ + t_my) * NQ + n) * HD + lane;
    g_o[ob]      = acc0 * invl;
    g_o[ob + 32] = acc1 * invl;
    g_o[ob + 64] = acc2 * invl;
    g_o[ob + 96] = acc3 * invl;
}

// ============================================================
// launch
// ============================================================
extern "C" void kernel_launch(void* const* d_in, const int* in_sizes, int n_in,
                              void* d_out, int out_size) {
    const float* x       = (const float*)d_in[0];
    const float* wq      = (const float*)d_in[1];
    const float* wk      = (const float*)d_in[2];
    const float* wv      = (const float*)d_in[3];
    const float* wo      = (const float*)d_in[4];
    const float* q_scale = (const float*)d_in[5];
    const float* k_scale = (const float*)d_in[6];
    const int*   seg     = (const int*)d_in[9];
    float* out = (float*)d_out;

    float *pq, *pk, *pv, *po;
    cudaGetSymbolAddress((void**)&pq, g_q);
    cudaGetSymbolAddress((void**)&pk, g_k);
    cudaGetSymbolAddress((void**)&pv, g_v);
    cudaGetSymbolAddress((void**)&po, g_o);

    startfirst_kernel<<<B_, 256>>>(seg);

    // projections: M = 2048 (grid.y = 16), K = 4096
    sgemm_kernel<<<dim3(NQ * HD / 128, MTOT / 128), 256>>>(x, wq, pq, NQ * HD, D_);
    sgemm_kernel<<<dim3(NKV * HD / 128, MTOT / 128), 256>>>(x, wk, pk, NKV * HD, D_);
    sgemm_kernel<<<dim3(NKV * HD / 128, MTOT / 128), 256>>>(x, wv, pv, NKV * HD, D_);

    ropenorm_kernel<<<dim3(MTOT, NQ + NKV), 128>>>(q_scale, k_scale, seg);

    attn_kernel<<<dim3(T_ / 8, NQ, B_), 256>>>();

    // output projection: [2048, 4096(NH)] @ [4096, 4096] -> d_out
    sgemm_kernel<<<dim3(D_ / 128, MTOT / 128), 256>>>(po, wo, out, D_, NQ * HD);
}

// round 3
// speedup vs baseline: 1.8834x; 1.8834x over previous
#include <cuda_runtime.h>
#include <math.h>
#include <stdint.h>

// Problem constants
#define B_   2
#define T_   1024
#define D_   4096
#define NQ   32
#define NKV  8
#define HD   128
#define MTOT (B_ * T_)    // 2048

#define NEG_INF (-INFINITY)

// -------- scratch (device globals; allocation-free) --------
__device__ __align__(256) float g_q[(size_t)MTOT * NQ * HD];     // 32 MB
__device__ __align__(256) float g_k[(size_t)MTOT * NKV * HD];    //  8 MB
__device__ __align__(256) float g_v[(size_t)MTOT * NKV * HD];    //  8 MB
__device__ __align__(256) float g_o[(size_t)MTOT * NQ * HD];     // 32 MB
__device__ __align__(256) float g_xr[(size_t)MTOT * D_];         // 32 MB
__device__ __align__(256) float g_wq_r[(size_t)D_ * NQ * HD];    // 64 MB
__device__ __align__(256) float g_wk_r[(size_t)D_ * NKV * HD];   // 16 MB
__device__ __align__(256) float g_wv_r[(size_t)D_ * NKV * HD];   // 16 MB
__device__ __align__(256) float g_wo_r[(size_t)NQ * HD * D_];    // 64 MB
__device__ int g_start[B_];
__device__ int g_first[B_];

// ============================================================
// helpers
// ============================================================
__device__ __forceinline__ uint32_t smem_u32(const void* p) {
    uint32_t a;
    asm("{ .reg .u64 t; cvta.to.shared.u64 t, %1; cvt.u32.u64 %0, t; }" : "=r"(a) : "l"(p));
    return a;
}
__device__ __forceinline__ float tf32r(float v) {
    uint32_t u;
    asm("cvt.rna.tf32.f32 %0, %1;" : "=r"(u) : "f"(v));
    return __uint_as_float(u);
}

#define CP_ASYNC16(saddr, gptr) \
    asm volatile("cp.async.cg.shared.global [%0], [%1], 16;" :: "r"(saddr), "l"(gptr) : "memory")
#define CP_COMMIT() asm volatile("cp.async.commit_group;" ::: "memory")
#define CP_WAIT2()  asm volatile("cp.async.wait_group 2;" ::: "memory")

__device__ __forceinline__ void mma_tf32(float c[4],
                                         uint32_t a0, uint32_t a1, uint32_t a2, uint32_t a3,
                                         uint32_t b0, uint32_t b1) {
    asm volatile(
        "mma.sync.aligned.m16n8k8.row.col.f32.tf32.tf32.f32 "
        "{%0,%1,%2,%3}, {%4,%5,%6,%7}, {%8,%9}, {%0,%1,%2,%3};"
        : "+f"(c[0]), "+f"(c[1]), "+f"(c[2]), "+f"(c[3])
        : "r"(a0), "r"(a1), "r"(a2), "r"(a3), "r"(b0), "r"(b1));
}

// ============================================================
// 1) segment scan
// ============================================================
__global__ void startfirst_kernel(const int* __restrict__ seg) {
    int b = blockIdx.x;
    const int* s = seg + (size_t)b * T_;
    __shared__ int sh_min, sh_max, sh_first;
    if (threadIdx.x == 0) { sh_min = T_; sh_max = INT_MIN; sh_first = T_; }
    __syncthreads();
    int lmin = T_, lmax = INT_MIN;
    for (int t = threadIdx.x; t < T_; t += blockDim.x) {
        int v = s[t];
        if (v != 0 && t < lmin) lmin = t;
        if (v > lmax) lmax = v;
    }
    atomicMin(&sh_min, lmin);
    atomicMax(&sh_max, lmax);
    __syncthreads();
    int mx = sh_max;
    int lfirst = T_;
    for (int t = threadIdx.x; t < T_; t += blockDim.x)
        if (s[t] == mx && t < lfirst) lfirst = t;
    atomicMin(&sh_first, lfirst);
    __syncthreads();
    if (threadIdx.x == 0) { g_start[b] = sh_min; g_first[b] = sh_first; }
}

// ============================================================
// 2) tf32 round-copy (element-wise, float4)
// ============================================================
__global__ void round_copy_kernel(const float4* __restrict__ src, float4* __restrict__ dst) {
    int i = blockIdx.x * blockDim.x + threadIdx.x;
    float4 v = src[i];
    v.x = tf32r(v.x); v.y = tf32r(v.y); v.z = tf32r(v.z); v.w = tf32r(v.w);
    dst[i] = v;
}

// ============================================================
// 3) tf32 mma.sync GEMM: C[M x N] = A[M x K] * Bg[K x N]
//    A, Bg row-major fp32 pre-rounded to tf32.
//    BM=BN=128, BK=16, 8 warps (2x4), warp tile 64x32, 4-stage cp.async.
// ============================================================
#define GSTAGES 4
#define A_STRIDE_F 20                       // floats per A smem row (conflict-free)
#define B_STRIDE_F 136                      // floats per B smem row (conflict-free)
#define A_TILE_BYTES (128 * A_STRIDE_F * 4) // 10240
#define B_TILE_BYTES (16 * B_STRIDE_F * 4)  //  8704
#define STAGE_BYTES (A_TILE_BYTES + B_TILE_BYTES) // 18944
#define GEMM_SMEM (GSTAGES * STAGE_BYTES)         // 75776

__global__ __launch_bounds__(256, 2)
void gemm_mma_kernel(const float* __restrict__ A, const float* __restrict__ Bg,
                     float* __restrict__ C, int N, int K) {
    extern __shared__ char smem[];
    const uint32_t sb = smem_u32(smem);
    const int tid  = threadIdx.x;
    const int wid  = tid >> 5;
    const int lane = tid & 31;
    const int g    = lane >> 2;     // 0..7
    const int r    = lane & 3;      // 0..3
    const int row0 = blockIdx.y * 128;
    const int col0 = blockIdx.x * 128;
    const int wm   = (wid >> 2) * 64;   // 0 / 64
    const int wn   = (wid & 3) * 32;    // 0..96

    float acc[4][4][4];
#pragma unroll
    for (int a = 0; a < 4; ++a)
#pragma unroll
        for (int b = 0; b < 4; ++b)
#pragma unroll
            for (int c = 0; c < 4; ++c) acc[a][b][c] = 0.f;

    const int KS = K >> 4;

    // ---- stage loader ----
    auto load_stage = [&](int st, int k0) {
        uint32_t abase = sb + st * STAGE_BYTES;
        uint32_t bbase = abase + A_TILE_BYTES;
#pragma unroll
        for (int j = 0; j < 2; ++j) {
            int f  = tid + 256 * j;        // 0..511
            int rr = f >> 2, cc = f & 3;
            CP_ASYNC16(abase + rr * (A_STRIDE_F * 4) + cc * 16,
                       A + (size_t)(row0 + rr) * K + k0 + cc * 4);
        }
#pragma unroll
        for (int j = 0; j < 2; ++j) {
            int f  = tid + 256 * j;
            int kk = f >> 5, cc = f & 31;
            CP_ASYNC16(bbase + kk * (B_STRIDE_F * 4) + cc * 16,
                       Bg + (size_t)(k0 + kk) * N + col0 + cc * 4);
        }
    };

    auto compute_stage = [&](int st) {
        const float* As = (const float*)(smem + st * STAGE_BYTES);
        const float* Bs = (const float*)(smem + st * STAGE_BYTES + A_TILE_BYTES);
#pragma unroll
        for (int ks = 0; ks < 2; ++ks) {
            const int k = ks * 8;
            uint32_t bf[4][2];
#pragma unroll
            for (int nt = 0; nt < 4; ++nt) {
                int n = wn + nt * 8 + g;
                bf[nt][0] = __float_as_uint(Bs[(k + r)     * B_STRIDE_F + n]);
                bf[nt][1] = __float_as_uint(Bs[(k + r + 4) * B_STRIDE_F + n]);
            }
#pragma unroll
            for (int mt = 0; mt < 4; ++mt) {
                int m = wm + mt * 16;
                uint32_t a0 = __float_as_uint(As[(m + g)     * A_STRIDE_F + k + r]);
                uint32_t a1 = __float_as_uint(As[(m + g + 8) * A_STRIDE_F + k + r]);
                uint32_t a2 = __float_as_uint(As[(m + g)     * A_STRIDE_F + k + r + 4]);
                uint32_t a3 = __float_as_uint(As[(m + g + 8) * A_STRIDE_F + k + r + 4]);
#pragma unroll
                for (int nt = 0; nt < 4; ++nt)
                    mma_tf32(acc[mt][nt], a0, a1, a2, a3, bf[nt][0], bf[nt][1]);
            }
        }
    };

    // ---- prologue: 3 stages in flight ----
    load_stage(0, 0);  CP_COMMIT();
    load_stage(1, 16); CP_COMMIT();
    load_stage(2, 32); CP_COMMIT();

    for (int i = 0; i < KS; ++i) {
        CP_WAIT2();
        __syncthreads();
        if (i + 3 < KS) load_stage((i + 3) & 3, (i + 3) << 4);
        CP_COMMIT();
        compute_stage(i & 3);
    }

    // ---- epilogue ----
#pragma unroll
    for (int mt = 0; mt < 4; ++mt) {
        int mrow = row0 + wm + mt * 16;
#pragma unroll
        for (int nt = 0; nt < 4; ++nt) {
            int ncol = col0 + wn + nt * 8 + 2 * r;
            *reinterpret_cast<float2*>(&C[(size_t)(mrow + g) * N + ncol]) =
                make_float2(acc[mt][nt][0], acc[mt][nt][1]);
            *reinterpret_cast<float2*>(&C[(size_t)(mrow + g + 8) * N + ncol]) =
                make_float2(acc[mt][nt][2], acc[mt][nt][3]);
        }
    }
}

// ============================================================
// 4) fused RMSNorm + RoPE
// ============================================================
__global__ __launch_bounds__(128) void ropenorm_kernel(
    const float* __restrict__ qscale, const float* __restrict__ kscale,
    const int* __restrict__ seg)
{
    const int bt = blockIdx.x;
    const int b  = bt >> 10;
    const int t  = bt & (T_ - 1);
    const int hd = blockIdx.y;
    const int h  = threadIdx.x;
    const int lane = h & 31, wid = h >> 5;

    float* buf;
    const float* sc;
    if (hd < NQ) { buf = &g_q[((size_t)bt * NQ + hd) * HD];         sc = qscale; }
    else         { buf = &g_k[((size_t)bt * NKV + (hd - NQ)) * HD]; sc = kscale; }

    float v = buf[h];
    float ss = v * v;
#pragma unroll
    for (int off = 16; off; off >>= 1) ss += __shfl_xor_sync(0xffffffffu, ss, off);
    __shared__ float red[4];
    if (lane == 0) red[wid] = ss;
    __syncthreads();
    float tot = red[0] + red[1] + red[2] + red[3];
    float xn = sc[h] * v * rsqrtf(tot * (1.0f / HD) + 1e-6f);

    __shared__ float row[HD];
    row[h] = xn;
    __syncthreads();

    int segv  = seg[bt];
    int first = g_first[b];
    float pos = (segv != 0) ? (float)(t - first) : 1073741824.0f;
    int k2 = (h < 64) ? h : (h - 64);
    float invf = exp2f((-2.0f * (float)k2 / 128.0f) * 19.931568569324174f);
    float ang = pos * invf;
    float s_ = sinf(ang), c_ = cosf(ang);

    float rr;
    if (h < 64) rr = xn * c_ - row[h + 64] * s_;
    else        rr = xn * c_ + row[h - 64] * s_;
    buf[h] = rr;
}

// ============================================================
// 5) attention (online softmax; stores tf32-rounded output)
// ============================================================
__global__ __launch_bounds__(256) void attn_kernel() {
    __shared__ float Qs[8][133];
    __shared__ float Ks[32][133];
    __shared__ float Vs[32][133];
    __shared__ float Ps[8][32];

    const int tid  = threadIdx.x;
    const int wid  = tid >> 5;
    const int lane = tid & 31;
    const int b  = blockIdx.z;
    const int n  = blockIdx.y;
    const int kh = n >> 2;
    const int t0 = blockIdx.x * 8;
    const float SCALE = 0.08838834764831845f;

    for (int idx = tid; idx < 8 * HD; idx += 256) {
        int w = idx >> 7, d = idx & 127;
        Qs[w][d] = g_q[((size_t)(b * T_ + t0 + w) * NQ + n) * HD + d] * SCALE;
    }
    const int start = g_start[b];
    const int t_my  = t0 + wid;
    const int t_max = t0 + 7;

    float m = NEG_INF, l = 0.f;
    float acc0 = 0.f, acc1 = 0.f, acc2 = 0.f, acc3 = 0.f;

    int s_begin = (start >> 5) << 5;
    __syncthreads();

    for (int s0 = s_begin; s0 <= t_max; s0 += 32) {
        for (int idx = tid; idx < 32 * HD; idx += 256) {
            int sl = idx >> 7, d = idx & 127;
            int s = s0 + sl;
            float kv = 0.f, vv = 0.f;
            if (s < T_) {
                size_t base = ((size_t)(b * T_ + s) * NKV + kh) * HD + d;
                kv = g_k[base];
                vv = g_v[base];
            }
            Ks[sl][d] = kv;
            Vs[sl][d] = vv;
        }
        __syncthreads();

        if (s0 <= t_my) {
            int s = s0 + lane;
            bool valid = (s >= start) && (s <= t_my);
            float sc = 0.f;
#pragma unroll 16
            for (int d = 0; d < HD; ++d)
                sc = fmaf(Qs[wid][d], Ks[lane][d], sc);
            float score = valid ? sc : NEG_INF;

            float mt = score;
#pragma unroll
            for (int off = 16; off; off >>= 1)
                mt = fmaxf(mt, __shfl_xor_sync(0xffffffffu, mt, off));
            float m_new = fmaxf(m, mt);
            float alpha = (m_new == NEG_INF) ? 1.0f : __expf(m - m_new);
            float p = valid ? __expf(score - m_new) : 0.f;
            float psum = p;
#pragma unroll
            for (int off = 16; off; off >>= 1)
                psum += __shfl_xor_sync(0xffffffffu, psum, off);
            l = l * alpha + psum;
            m = m_new;
            Ps[wid][lane] = p;
            __syncwarp();

            acc0 *= alpha; acc1 *= alpha; acc2 *= alpha; acc3 *= alpha;
#pragma unroll 8
            for (int sl = 0; sl < 32; ++sl) {
                float p_s = Ps[wid][sl];
                acc0 = fmaf(p_s, Vs[sl][lane],      acc0);
                acc1 = fmaf(p_s, Vs[sl][lane + 32], acc1);
                acc2 = fmaf(p_s, Vs[sl][lane + 64], acc2);
                acc3 = fmaf(p_s, Vs[sl][lane + 96], acc3);
            }
        }
        __syncthreads();
    }

    float invl = (l > 0.f) ? (1.0f / l) : 0.f;
    size_t ob = ((size_t)(b * T_ + t_my) * NQ + n) * HD + lane;
    g_o[ob]      = tf32r(acc0 * invl);
    g_o[ob + 32] = tf32r(acc1 * invl);
    g_o[ob + 64] = tf32r(acc2 * invl);
    g_o[ob + 96] = tf32r(acc3 * invl);
}

// ============================================================
// launch
// ============================================================
extern "C" void kernel_launch(void* const* d_in, const int* in_sizes, int n_in,
                              void* d_out, int out_size) {
    const float* x       = (const float*)d_in[0];
    const float* wq      = (const float*)d_in[1];
    const float* wk      = (const float*)d_in[2];
    const float* wv      = (const float*)d_in[3];
    const float* wo      = (const float*)d_in[4];
    const float* q_scale = (const float*)d_in[5];
    const float* k_scale = (const float*)d_in[6];
    const int*   seg     = (const int*)d_in[9];
    float* out = (float*)d_out;

    float *pq, *pk, *pv, *po, *pxr, *pwq, *pwk, *pwv, *pwo;
    cudaGetSymbolAddress((void**)&pq, g_q);
    cudaGetSymbolAddress((void**)&pk, g_k);
    cudaGetSymbolAddress((void**)&pv, g_v);
    cudaGetSymbolAddress((void**)&po, g_o);
    cudaGetSymbolAddress((void**)&pxr, g_xr);
    cudaGetSymbolAddress((void**)&pwq, g_wq_r);
    cudaGetSymbolAddress((void**)&pwk, g_wk_r);
    cudaGetSymbolAddress((void**)&pwv, g_wv_r);
    cudaGetSymbolAddress((void**)&pwo, g_wo_r);

    cudaFuncSetAttribute(gemm_mma_kernel, cudaFuncAttributeMaxDynamicSharedMemorySize,
                         GEMM_SMEM);

    startfirst_kernel<<<B_, 256>>>(seg);

    // tf32 pre-round inputs and weights
    round_copy_kernel<<<(MTOT * D_ / 4) / 256, 256>>>((const float4*)x, (float4*)pxr);
    round_copy_kernel<<<((size_t)D_ * NQ * HD / 4) / 256, 256>>>((const float4*)wq, (float4*)pwq);
    round_copy_kernel<<<((size_t)D_ * NKV * HD / 4) / 256, 256>>>((const float4*)wk, (float4*)pwk);
    round_copy_kernel<<<((size_t)D_ * NKV * HD / 4) / 256, 256>>>((const float4*)wv, (float4*)pwv);
    round_copy_kernel<<<((size_t)NQ * HD * D_ / 4) / 256, 256>>>((const float4*)wo, (float4*)pwo);

    // projections: q (N=4096), k/v (N=1024), K=4096
    gemm_mma_kernel<<<dim3(NQ * HD / 128, MTOT / 128), 256, GEMM_SMEM>>>(pxr, pwq, pq, NQ * HD, D_);
    gemm_mma_kernel<<<dim3(NKV * HD / 128, MTOT / 128), 256, GEMM_SMEM>>>(pxr, pwk, pk, NKV * HD, D_);
    gemm_mma_kernel<<<dim3(NKV * HD / 128, MTOT / 128), 256, GEMM_SMEM>>>(pxr, pwv, pv, NKV * HD, D_);

    ropenorm_kernel<<<dim3(MTOT, NQ + NKV), 128>>>(q_scale, k_scale, seg);

    attn_kernel<<<dim3(T_ / 8, NQ, B_), 256>>>();

    // output projection: [2048, 4096] @ [4096, 4096] -> d_out
    gemm_mma_kernel<<<dim3(D_ / 128, MTOT / 128), 256, GEMM_SMEM>>>(po, pwo, out, D_, NQ * HD);
}

// round 4
// speedup vs baseline: 2.3790x; 1.2631x over previous
#include <cuda_runtime.h>
#include <math.h>
#include <stdint.h>

// Problem constants
#define B_   2
#define T_   1024
#define D_   4096
#define NQ   32
#define NKV  8
#define HD   128
#define MTOT (B_ * T_)      // 2048
#define QKV_N 6144          // 4096 q + 1024 k + 1024 v
#define K_OFF 4096
#define V_OFF 5120

#define NEG_INF (-INFINITY)

// -------- scratch (device globals; allocation-free) --------
__device__ __align__(256) float g_qkv[(size_t)MTOT * QKV_N];    // 48 MB
__device__ __align__(256) float g_o[(size_t)MTOT * NQ * HD];    // 32 MB
__device__ __align__(256) float g_xr[(size_t)MTOT * D_];        // 32 MB
__device__ __align__(256) float g_wqkv[(size_t)D_ * QKV_N];     // 96 MB
__device__ __align__(256) float g_wo_r[(size_t)NQ * HD * D_];   // 64 MB
__device__ int g_start[B_];
__device__ int g_first[B_];

// ============================================================
// helpers
// ============================================================
__device__ __forceinline__ uint32_t smem_u32(const void* p) {
    uint32_t a;
    asm("{ .reg .u64 t; cvta.to.shared.u64 t, %1; cvt.u32.u64 %0, t; }" : "=r"(a) : "l"(p));
    return a;
}
__device__ __forceinline__ float tf32r(float v) {
    uint32_t u;
    asm("cvt.rna.tf32.f32 %0, %1;" : "=r"(u) : "f"(v));
    return __uint_as_float(u);
}

#define CP_ASYNC16(saddr, gptr) \
    asm volatile("cp.async.cg.shared.global [%0], [%1], 16;" :: "r"(saddr), "l"(gptr) : "memory")
#define CP_COMMIT() asm volatile("cp.async.commit_group;" ::: "memory")
#define CP_WAIT2()  asm volatile("cp.async.wait_group 2;" ::: "memory")

__device__ __forceinline__ void mma_tf32(float c[4],
                                         uint32_t a0, uint32_t a1, uint32_t a2, uint32_t a3,
                                         uint32_t b0, uint32_t b1) {
    asm volatile(
        "mma.sync.aligned.m16n8k8.row.col.f32.tf32.tf32.f32 "
        "{%0,%1,%2,%3}, {%4,%5,%6,%7}, {%8,%9}, {%0,%1,%2,%3};"
        : "+f"(c[0]), "+f"(c[1]), "+f"(c[2]), "+f"(c[3])
        : "r"(a0), "r"(a1), "r"(a2), "r"(a3), "r"(b0), "r"(b1));
}

// ============================================================
// 1) segment scan
// ============================================================
__global__ void startfirst_kernel(const int* __restrict__ seg) {
    int b = blockIdx.x;
    const int* s = seg + (size_t)b * T_;
    __shared__ int sh_min, sh_max, sh_first;
    if (threadIdx.x == 0) { sh_min = T_; sh_max = INT_MIN; sh_first = T_; }
    __syncthreads();
    int lmin = T_, lmax = INT_MIN;
    for (int t = threadIdx.x; t < T_; t += blockDim.x) {
        int v = s[t];
        if (v != 0 && t < lmin) lmin = t;
        if (v > lmax) lmax = v;
    }
    atomicMin(&sh_min, lmin);
    atomicMax(&sh_max, lmax);
    __syncthreads();
    int mx = sh_max;
    int lfirst = T_;
    for (int t = threadIdx.x; t < T_; t += blockDim.x)
        if (s[t] == mx && t < lfirst) lfirst = t;
    atomicMin(&sh_first, lfirst);
    __syncthreads();
    if (threadIdx.x == 0) { g_start[b] = sh_min; g_first[b] = sh_first; }
}

// ============================================================
// 2) tf32 round-copy kernels
// ============================================================
__global__ void round_copy_kernel(const float4* __restrict__ src, float4* __restrict__ dst) {
    int i = blockIdx.x * blockDim.x + threadIdx.x;
    float4 v = src[i];
    v.x = tf32r(v.x); v.y = tf32r(v.y); v.z = tf32r(v.z); v.w = tf32r(v.w);
    dst[i] = v;
}

// pack wq|wk|wv rows into combined [D][6144] buffer, tf32-rounded
__global__ void pack_wqkv_kernel(const float4* __restrict__ wq, const float4* __restrict__ wk,
                                 const float4* __restrict__ wv, float4* __restrict__ dst) {
    int i = blockIdx.x * blockDim.x + threadIdx.x;   // over D * 1536 float4s
    int row = i / (QKV_N / 4);
    int c4  = i % (QKV_N / 4);
    float4 v;
    if (c4 < 1024)       v = wq[(size_t)row * 1024 + c4];
    else if (c4 < 1280)  v = wk[(size_t)row * 256 + (c4 - 1024)];
    else                 v = wv[(size_t)row * 256 + (c4 - 1280)];
    v.x = tf32r(v.x); v.y = tf32r(v.y); v.z = tf32r(v.z); v.w = tf32r(v.w);
    dst[i] = v;
}

// ============================================================
// 3) tf32 mma.sync GEMM (as R3): C[M x N] = A[M x K] * Bg[K x N]
// ============================================================
#define GSTAGES 4
#define A_STRIDE_F 20
#define B_STRIDE_F 136
#define A_TILE_BYTES (128 * A_STRIDE_F * 4)
#define B_TILE_BYTES (16 * B_STRIDE_F * 4)
#define STAGE_BYTES (A_TILE_BYTES + B_TILE_BYTES)
#define GEMM_SMEM (GSTAGES * STAGE_BYTES)

__global__ __launch_bounds__(256, 2)
void gemm_mma_kernel(const float* __restrict__ A, const float* __restrict__ Bg,
                     float* __restrict__ C, int N, int K) {
    extern __shared__ char smem[];
    const uint32_t sb = smem_u32(smem);
    const int tid  = threadIdx.x;
    const int wid  = tid >> 5;
    const int lane = tid & 31;
    const int g    = lane >> 2;
    const int r    = lane & 3;
    const int row0 = blockIdx.y * 128;
    const int col0 = blockIdx.x * 128;
    const int wm   = (wid >> 2) * 64;
    const int wn   = (wid & 3) * 32;

    float acc[4][4][4];
#pragma unroll
    for (int a = 0; a < 4; ++a)
#pragma unroll
        for (int b = 0; b < 4; ++b)
#pragma unroll
            for (int c = 0; c < 4; ++c) acc[a][b][c] = 0.f;

    const int KS = K >> 4;

    auto load_stage = [&](int st, int k0) {
        uint32_t abase = sb + st * STAGE_BYTES;
        uint32_t bbase = abase + A_TILE_BYTES;
#pragma unroll
        for (int j = 0; j < 2; ++j) {
            int f  = tid + 256 * j;
            int rr = f >> 2, cc = f & 3;
            CP_ASYNC16(abase + rr * (A_STRIDE_F * 4) + cc * 16,
                       A + (size_t)(row0 + rr) * K + k0 + cc * 4);
        }
#pragma unroll
        for (int j = 0; j < 2; ++j) {
            int f  = tid + 256 * j;
            int kk = f >> 5, cc = f & 31;
            CP_ASYNC16(bbase + kk * (B_STRIDE_F * 4) + cc * 16,
                       Bg + (size_t)(k0 + kk) * N + col0 + cc * 4);
        }
    };

    auto compute_stage = [&](int st) {
        const float* As = (const float*)(smem + st * STAGE_BYTES);
        const float* Bs = (const float*)(smem + st * STAGE_BYTES + A_TILE_BYTES);
#pragma unroll
        for (int ks = 0; ks < 2; ++ks) {
            const int k = ks * 8;
            uint32_t bf[4][2];
#pragma unroll
            for (int nt = 0; nt < 4; ++nt) {
                int n = wn + nt * 8 + g;
                bf[nt][0] = __float_as_uint(Bs[(k + r)     * B_STRIDE_F + n]);
                bf[nt][1] = __float_as_uint(Bs[(k + r + 4) * B_STRIDE_F + n]);
            }
#pragma unroll
            for (int mt = 0; mt < 4; ++mt) {
                int m = wm + mt * 16;
                uint32_t a0 = __float_as_uint(As[(m + g)     * A_STRIDE_F + k + r]);
                uint32_t a1 = __float_as_uint(As[(m + g + 8) * A_STRIDE_F + k + r]);
                uint32_t a2 = __float_as_uint(As[(m + g)     * A_STRIDE_F + k + r + 4]);
                uint32_t a3 = __float_as_uint(As[(m + g + 8) * A_STRIDE_F + k + r + 4]);
#pragma unroll
                for (int nt = 0; nt < 4; ++nt)
                    mma_tf32(acc[mt][nt], a0, a1, a2, a3, bf[nt][0], bf[nt][1]);
            }
        }
    };

    load_stage(0, 0);  CP_COMMIT();
    load_stage(1, 16); CP_COMMIT();
    load_stage(2, 32); CP_COMMIT();

    for (int i = 0; i < KS; ++i) {
        CP_WAIT2();
        __syncthreads();
        if (i + 3 < KS) load_stage((i + 3) & 3, (i + 3) << 4);
        CP_COMMIT();
        compute_stage(i & 3);
    }

#pragma unroll
    for (int mt = 0; mt < 4; ++mt) {
        int mrow = row0 + wm + mt * 16;
#pragma unroll
        for (int nt = 0; nt < 4; ++nt) {
            int ncol = col0 + wn + nt * 8 + 2 * r;
            *reinterpret_cast<float2*>(&C[(size_t)(mrow + g) * N + ncol]) =
                make_float2(acc[mt][nt][0], acc[mt][nt][1]);
            *reinterpret_cast<float2*>(&C[(size_t)(mrow + g + 8) * N + ncol]) =
                make_float2(acc[mt][nt][2], acc[mt][nt][3]);
        }
    }
}

// ============================================================
// 4) fused RMSNorm + RoPE over combined qkv buffer
//    grid.y: 0..31 = q heads, 32..39 = k heads (v untouched)
// ============================================================
__global__ __launch_bounds__(128) void ropenorm_kernel(
    const float* __restrict__ qscale, const float* __restrict__ kscale,
    const int* __restrict__ seg)
{
    const int bt = blockIdx.x;
    const int b  = bt >> 10;
    const int t  = bt & (T_ - 1);
    const int hd = blockIdx.y;
    const int h  = threadIdx.x;
    const int lane = h & 31, wid = h >> 5;

    float* buf;
    const float* sc;
    if (hd < NQ) { buf = &g_qkv[(size_t)bt * QKV_N + hd * HD];                 sc = qscale; }
    else         { buf = &g_qkv[(size_t)bt * QKV_N + K_OFF + (hd - NQ) * HD]; sc = kscale; }

    float v = buf[h];
    float ss = v * v;
#pragma unroll
    for (int off = 16; off; off >>= 1) ss += __shfl_xor_sync(0xffffffffu, ss, off);
    __shared__ float red[4];
    if (lane == 0) red[wid] = ss;
    __syncthreads();
    float tot = red[0] + red[1] + red[2] + red[3];
    float xn = sc[h] * v * rsqrtf(tot * (1.0f / HD) + 1e-6f);

    __shared__ float row[HD];
    row[h] = xn;
    __syncthreads();

    int segv  = seg[bt];
    int first = g_first[b];
    float pos = (segv != 0) ? (float)(t - first) : 1073741824.0f;
    int k2 = (h < 64) ? h : (h - 64);
    float invf = exp2f((-2.0f * (float)k2 / 128.0f) * 19.931568569324174f);
    float ang = pos * invf;
    float s_ = sinf(ang), c_ = cosf(ang);

    float rr;
    if (h < 64) rr = xn * c_ - row[h + 64] * s_;
    else        rr = xn * c_ + row[h - 64] * s_;
    buf[h] = rr;
}

// ============================================================
// 5) attention: 32 queries/block (4 per warp), float4 smem paths
// ============================================================
#define ATT_STRIDE 132   // floats per smem row (conflict-free for LDS.128)
#define ATT_SMEM_FLOATS (96 * ATT_STRIDE + 32 * 32)
#define ATT_SMEM_BYTES (ATT_SMEM_FLOATS * 4)

__global__ __launch_bounds__(256) void attn_kernel() {
    extern __shared__ float sm[];
    float* Qs = sm;                       // 32 rows x 132
    float* Ks = sm + 32 * ATT_STRIDE;     // 32 rows x 132
    float* Vs = sm + 64 * ATT_STRIDE;     // 32 rows x 132
    float* Ps = sm + 96 * ATT_STRIDE;     // 32 qrows x 32 keys

    const int tid  = threadIdx.x;
    const int wid  = tid >> 5;
    const int lane = tid & 31;
    const int b  = blockIdx.z;
    const int n  = blockIdx.y;
    const int kh = n >> 2;
    const int t0 = blockIdx.x * 32;
    const float SCALE = 0.08838834764831845f;

    // load 32 query rows, pre-scaled
    for (int idx = tid; idx < 1024; idx += 256) {
        int r = idx >> 5, c4 = idx & 31;
        const float4* row = reinterpret_cast<const float4*>(
            g_qkv + (size_t)(b * T_ + t0 + r) * QKV_N + n * HD);
        float4 v = row[c4];
        v.x *= SCALE; v.y *= SCALE; v.z *= SCALE; v.w *= SCALE;
        *reinterpret_cast<float4*>(Qs + r * ATT_STRIDE + 4 * c4) = v;
    }

    const int start = g_start[b];
    const int t_w   = t0 + wid * 4 + 3;   // warp's max query pos

    float m[4], l[4];
    float4 acc[4];
#pragma unroll
    for (int qi = 0; qi < 4; ++qi) {
        m[qi] = NEG_INF; l[qi] = 0.f;
        acc[qi] = make_float4(0.f, 0.f, 0.f, 0.f);
    }

    int s_begin = start & ~31;
    __syncthreads();

    for (int s0 = s_begin; s0 <= t0 + 31; s0 += 32) {
        // cooperative K/V tile load (float4)
        for (int idx = tid; idx < 1024; idx += 256) {
            int sl = idx >> 5, c4 = idx & 31;
            int s = s0 + sl;
            float4 kv = make_float4(0.f, 0.f, 0.f, 0.f), vv = kv;
            if (s < T_) {
                const float4* row = reinterpret_cast<const float4*>(
                    g_qkv + (size_t)(b * T_ + s) * QKV_N + K_OFF + kh * HD);
                kv = row[c4];
                vv = row[c4 + 256];   // V is +1024 floats
            }
            *reinterpret_cast<float4*>(Ks + sl * ATT_STRIDE + 4 * c4) = kv;
            *reinterpret_cast<float4*>(Vs + sl * ATT_STRIDE + 4 * c4) = vv;
        }
        __syncthreads();

        if (s0 <= t_w) {
            float ascale[4];
            const float4* krow = reinterpret_cast<const float4*>(Ks + lane * ATT_STRIDE);
#pragma unroll
            for (int qi = 0; qi < 4; ++qi) {
                const int t_q = t0 + wid * 4 + qi;
                float p = 0.f;
                ascale[qi] = 1.f;
                if (s0 <= t_q) {
                    const float4* qrow = reinterpret_cast<const float4*>(
                        Qs + (wid * 4 + qi) * ATT_STRIDE);
                    float sc = 0.f;
#pragma unroll
                    for (int i = 0; i < 32; ++i) {
                        float4 qa = qrow[i], kb = krow[i];
                        sc = fmaf(qa.x, kb.x, sc);
                        sc = fmaf(qa.y, kb.y, sc);
                        sc = fmaf(qa.z, kb.z, sc);
                        sc = fmaf(qa.w, kb.w, sc);
                    }
                    int s = s0 + lane;
                    bool valid = (s >= start) && (s <= t_q);
                    float score = valid ? sc : NEG_INF;
                    float mt = score;
#pragma unroll
                    for (int off = 16; off; off >>= 1)
                        mt = fmaxf(mt, __shfl_xor_sync(0xffffffffu, mt, off));
                    float m_new = fmaxf(m[qi], mt);
                    float alpha = (m_new == NEG_INF) ? 1.0f : __expf(m[qi] - m_new);
                    p = valid ? __expf(score - m_new) : 0.f;
                    float psum = p;
#pragma unroll
                    for (int off = 16; off; off >>= 1)
                        psum += __shfl_xor_sync(0xffffffffu, psum, off);
                    l[qi] = l[qi] * alpha + psum;
                    m[qi] = m_new;
                    ascale[qi] = alpha;
                }
                Ps[(wid * 4 + qi) * 32 + lane] = p;
            }
            __syncwarp();

#pragma unroll
            for (int qi = 0; qi < 4; ++qi) {
                acc[qi].x *= ascale[qi]; acc[qi].y *= ascale[qi];
                acc[qi].z *= ascale[qi]; acc[qi].w *= ascale[qi];
            }
#pragma unroll 8
            for (int sl = 0; sl < 32; ++sl) {
                float4 vv = *reinterpret_cast<const float4*>(Vs + sl * ATT_STRIDE + 4 * lane);
#pragma unroll
                for (int qi = 0; qi < 4; ++qi) {
                    float p = Ps[(wid * 4 + qi) * 32 + sl];
                    acc[qi].x = fmaf(p, vv.x, acc[qi].x);
                    acc[qi].y = fmaf(p, vv.y, acc[qi].y);
                    acc[qi].z = fmaf(p, vv.z, acc[qi].z);
                    acc[qi].w = fmaf(p, vv.w, acc[qi].w);
                }
            }
        }
        __syncthreads();
    }

#pragma unroll
    for (int qi = 0; qi < 4; ++qi) {
        const int t_q = t0 + wid * 4 + qi;
        float invl = (l[qi] > 0.f) ? (1.0f / l[qi]) : 0.f;
        float4 o;
        o.x = tf32r(acc[qi].x * invl);
        o.y = tf32r(acc[qi].y * invl);
        o.z = tf32r(acc[qi].z * invl);
        o.w = tf32r(acc[qi].w * invl);
        *reinterpret_cast<float4*>(
            &g_o[((size_t)(b * T_ + t_q) * NQ + n) * HD + 4 * lane]) = o;
    }
}

// ============================================================
// launch
// ============================================================
extern "C" void kernel_launch(void* const* d_in, const int* in_sizes, int n_in,
                              void* d_out, int out_size) {
    const float* x       = (const float*)d_in[0];
    const float* wq      = (const float*)d_in[1];
    const float* wk      = (const float*)d_in[2];
    const float* wv      = (const float*)d_in[3];
    const float* wo      = (const float*)d_in[4];
    const float* q_scale = (const float*)d_in[5];
    const float* k_scale = (const float*)d_in[6];
    const int*   seg     = (const int*)d_in[9];
    float* out = (float*)d_out;

    float *pqkv, *po, *pxr, *pwqkv, *pwo;
    cudaGetSymbolAddress((void**)&pqkv, g_qkv);
    cudaGetSymbolAddress((void**)&po, g_o);
    cudaGetSymbolAddress((void**)&pxr, g_xr);
    cudaGetSymbolAddress((void**)&pwqkv, g_wqkv);
    cudaGetSymbolAddress((void**)&pwo, g_wo_r);

    cudaFuncSetAttribute(gemm_mma_kernel, cudaFuncAttributeMaxDynamicSharedMemorySize,
                         GEMM_SMEM);
    cudaFuncSetAttribute(attn_kernel, cudaFuncAttributeMaxDynamicSharedMemorySize,
                         ATT_SMEM_BYTES);

    startfirst_kernel<<<B_, 256>>>(seg);

    // tf32 pre-round
    round_copy_kernel<<<(MTOT * D_ / 4) / 256, 256>>>((const float4*)x, (float4*)pxr);
    pack_wqkv_kernel<<<((size_t)D_ * QKV_N / 4) / 256, 256>>>(
        (const float4*)wq, (const float4*)wk, (const float4*)wv, (float4*)pwqkv);
    round_copy_kernel<<<((size_t)NQ * HD * D_ / 4) / 256, 256>>>((const float4*)wo, (float4*)pwo);

    // fused q/k/v projection: N=6144, K=4096
    gemm_mma_kernel<<<dim3(QKV_N / 128, MTOT / 128), 256, GEMM_SMEM>>>(
        pxr, pwqkv, pqkv, QKV_N, D_);

    ropenorm_kernel<<<dim3(MTOT, NQ + NKV), 128>>>(q_scale, k_scale, seg);

    attn_kernel<<<dim3(T_ / 32, NQ, B_), 256, ATT_SMEM_BYTES>>>();

    // output projection: [2048, 4096] @ [4096, 4096] -> d_out
    gemm_mma_kernel<<<dim3(D_ / 128, MTOT / 128), 256, GEMM_SMEM>>>(po, pwo, out, D_, NQ * HD);
}

// round 5
// speedup vs baseline: 2.5449x; 1.0698x over previous
#include <cuda_runtime.h>
#include <math.h>
#include <stdint.h>

// Problem constants
#define B_   2
#define T_   1024
#define D_   4096
#define NQ   32
#define NKV  8
#define HD   128
#define MTOT (B_ * T_)      // 2048
#define QKV_N 6144          // 4096 q + 1024 k + 1024 v
#define K_OFF 4096

#define NEG_INF (-INFINITY)

// -------- scratch (device globals; allocation-free) --------
__device__ __align__(256) float g_qkv[(size_t)MTOT * QKV_N];    // 48 MB
__device__ __align__(256) float g_o[(size_t)MTOT * NQ * HD];    // 32 MB
__device__ __align__(256) float g_xr[(size_t)MTOT * D_];        // 32 MB
__device__ __align__(256) float g_wqkv[(size_t)D_ * QKV_N];     // 96 MB
__device__ __align__(256) float g_wo_r[(size_t)NQ * HD * D_];   // 64 MB
__device__ int g_start[B_];
__device__ int g_first[B_];

// ============================================================
// helpers
// ============================================================
__device__ __forceinline__ uint32_t smem_u32(const void* p) {
    uint32_t a;
    asm("{ .reg .u64 t; cvta.to.shared.u64 t, %1; cvt.u32.u64 %0, t; }" : "=r"(a) : "l"(p));
    return a;
}
__device__ __forceinline__ float tf32r(float v) {
    uint32_t u;
    asm("cvt.rna.tf32.f32 %0, %1;" : "=r"(u) : "f"(v));
    return __uint_as_float(u);
}

#define CP_ASYNC16(saddr, gptr) \
    asm volatile("cp.async.cg.shared.global [%0], [%1], 16;" :: "r"(saddr), "l"(gptr) : "memory")
#define CP_COMMIT() asm volatile("cp.async.commit_group;" ::: "memory")
#define CP_WAIT1()  asm volatile("cp.async.wait_group 1;" ::: "memory")

__device__ __forceinline__ void mma_tf32(float c[4],
                                         uint32_t a0, uint32_t a1, uint32_t a2, uint32_t a3,
                                         uint32_t b0, uint32_t b1) {
    asm volatile(
        "mma.sync.aligned.m16n8k8.row.col.f32.tf32.tf32.f32 "
        "{%0,%1,%2,%3}, {%4,%5,%6,%7}, {%8,%9}, {%0,%1,%2,%3};"
        : "+f"(c[0]), "+f"(c[1]), "+f"(c[2]), "+f"(c[3])
        : "r"(a0), "r"(a1), "r"(a2), "r"(a3), "r"(b0), "r"(b1));
}

// ============================================================
// 1) segment scan
// ============================================================
__global__ void startfirst_kernel(const int* __restrict__ seg) {
    int b = blockIdx.x;
    const int* s = seg + (size_t)b * T_;
    __shared__ int sh_min, sh_max, sh_first;
    if (threadIdx.x == 0) { sh_min = T_; sh_max = INT_MIN; sh_first = T_; }
    __syncthreads();
    int lmin = T_, lmax = INT_MIN;
    for (int t = threadIdx.x; t < T_; t += blockDim.x) {
        int v = s[t];
        if (v != 0 && t < lmin) lmin = t;
        if (v > lmax) lmax = v;
    }
    atomicMin(&sh_min, lmin);
    atomicMax(&sh_max, lmax);
    __syncthreads();
    int mx = sh_max;
    int lfirst = T_;
    for (int t = threadIdx.x; t < T_; t += blockDim.x)
        if (s[t] == mx && t < lfirst) lfirst = t;
    atomicMin(&sh_first, lfirst);
    __syncthreads();
    if (threadIdx.x == 0) { g_start[b] = sh_min; g_first[b] = sh_first; }
}

// ============================================================
// 2) tf32 round-copy kernels
// ============================================================
__global__ void round_copy_kernel(const float4* __restrict__ src, float4* __restrict__ dst) {
    int i = blockIdx.x * blockDim.x + threadIdx.x;
    float4 v = src[i];
    v.x = tf32r(v.x); v.y = tf32r(v.y); v.z = tf32r(v.z); v.w = tf32r(v.w);
    dst[i] = v;
}

// pack wq|wk|wv rows into combined [D][6144] buffer, tf32-rounded
__global__ void pack_wqkv_kernel(const float4* __restrict__ wq, const float4* __restrict__ wk,
                                 const float4* __restrict__ wv, float4* __restrict__ dst) {
    int i = blockIdx.x * blockDim.x + threadIdx.x;   // over D * 1536 float4s
    int row = i / (QKV_N / 4);
    int c4  = i % (QKV_N / 4);
    float4 v;
    if (c4 < 1024)       v = wq[(size_t)row * 1024 + c4];
    else if (c4 < 1280)  v = wk[(size_t)row * 256 + (c4 - 1024)];
    else                 v = wv[(size_t)row * 256 + (c4 - 1280)];
    v.x = tf32r(v.x); v.y = tf32r(v.y); v.z = tf32r(v.z); v.w = tf32r(v.w);
    dst[i] = v;
}

// ============================================================
// 3) tf32 mma.sync GEMM v2: BK=32, 3-stage cp.async, BM=BN=128,
//    8 warps (2x4), warp tile 64x32
// ============================================================
#define A_STRIDE_F 36                        // floats per A smem row
#define B_STRIDE_F 136                       // floats per B smem row
#define A_TILE_BYTES (128 * A_STRIDE_F * 4)  // 18432
#define B_TILE_BYTES (32 * B_STRIDE_F * 4)   // 17408
#define STAGE_BYTES (A_TILE_BYTES + B_TILE_BYTES) // 35840
#define GSTAGES 3
#define GEMM_SMEM (GSTAGES * STAGE_BYTES)         // 107520

__global__ __launch_bounds__(256, 2)
void gemm_mma_kernel(const float* __restrict__ A, const float* __restrict__ Bg,
                     float* __restrict__ C, int N, int K) {
    extern __shared__ char smem[];
    const uint32_t sb = smem_u32(smem);
    const int tid  = threadIdx.x;
    const int wid  = tid >> 5;
    const int lane = tid & 31;
    const int g    = lane >> 2;
    const int r    = lane & 3;
    const int row0 = blockIdx.y * 128;
    const int col0 = blockIdx.x * 128;
    const int wm   = (wid >> 2) * 64;
    const int wn   = (wid & 3) * 32;

    float acc[4][4][4];
#pragma unroll
    for (int a = 0; a < 4; ++a)
#pragma unroll
        for (int b = 0; b < 4; ++b)
#pragma unroll
            for (int c = 0; c < 4; ++c) acc[a][b][c] = 0.f;

    const int KS = K >> 5;   // BK = 32

    auto load_stage = [&](int st, int k0) {
        uint32_t abase = sb + st * STAGE_BYTES;
        uint32_t bbase = abase + A_TILE_BYTES;
#pragma unroll
        for (int j = 0; j < 4; ++j) {
            int f  = tid + 256 * j;        // 0..1023
            int rr = f >> 3, cc = f & 7;
            CP_ASYNC16(abase + rr * (A_STRIDE_F * 4) + cc * 16,
                       A + (size_t)(row0 + rr) * K + k0 + cc * 4);
        }
#pragma unroll
        for (int j = 0; j < 4; ++j) {
            int f  = tid + 256 * j;
            int kk = f >> 5, c4 = f & 31;
            CP_ASYNC16(bbase + kk * (B_STRIDE_F * 4) + c4 * 16,
                       Bg + (size_t)(k0 + kk) * N + col0 + c4 * 4);
        }
    };

    auto compute_stage = [&](int st) {
        const float* As = (const float*)(smem + st * STAGE_BYTES);
        const float* Bs = (const float*)(smem + st * STAGE_BYTES + A_TILE_BYTES);
#pragma unroll
        for (int ks = 0; ks < 4; ++ks) {
            const int k = ks * 8;
            uint32_t bf[4][2];
#pragma unroll
            for (int nt = 0; nt < 4; ++nt) {
                int n = wn + nt * 8 + g;
                bf[nt][0] = __float_as_uint(Bs[(k + r)     * B_STRIDE_F + n]);
                bf[nt][1] = __float_as_uint(Bs[(k + r + 4) * B_STRIDE_F + n]);
            }
#pragma unroll
            for (int mt = 0; mt < 4; ++mt) {
                int m = wm + mt * 16;
                uint32_t a0 = __float_as_uint(As[(m + g)     * A_STRIDE_F + k + r]);
                uint32_t a1 = __float_as_uint(As[(m + g + 8) * A_STRIDE_F + k + r]);
                uint32_t a2 = __float_as_uint(As[(m + g)     * A_STRIDE_F + k + r + 4]);
                uint32_t a3 = __float_as_uint(As[(m + g + 8) * A_STRIDE_F + k + r + 4]);
#pragma unroll
                for (int nt = 0; nt < 4; ++nt)
                    mma_tf32(acc[mt][nt], a0, a1, a2, a3, bf[nt][0], bf[nt][1]);
            }
        }
    };

    // prologue: 2 stages in flight
    load_stage(0, 0);  CP_COMMIT();
    load_stage(1, 32); CP_COMMIT();

    for (int i = 0; i < KS; ++i) {
        CP_WAIT1();          // stage i arrived (pending: i, i+1 -> wait<=1)
        __syncthreads();     // all warps done with stage i-1; stage i visible
        if (i + 2 < KS) load_stage((i + 2) % 3, (i + 2) << 5);
        CP_COMMIT();
        compute_stage(i % 3);
    }

#pragma unroll
    for (int mt = 0; mt < 4; ++mt) {
        int mrow = row0 + wm + mt * 16;
#pragma unroll
        for (int nt = 0; nt < 4; ++nt) {
            int ncol = col0 + wn + nt * 8 + 2 * r;
            *reinterpret_cast<float2*>(&C[(size_t)(mrow + g) * N + ncol]) =
                make_float2(acc[mt][nt][0], acc[mt][nt][1]);
            *reinterpret_cast<float2*>(&C[(size_t)(mrow + g + 8) * N + ncol]) =
                make_float2(acc[mt][nt][2], acc[mt][nt][3]);
        }
    }
}

// ============================================================
// 4) fused RMSNorm + RoPE over combined qkv buffer
// ============================================================
__global__ __launch_bounds__(128) void ropenorm_kernel(
    const float* __restrict__ qscale, const float* __restrict__ kscale,
    const int* __restrict__ seg)
{
    const int bt = blockIdx.x;
    const int b  = bt >> 10;
    const int t  = bt & (T_ - 1);
    const int hd = blockIdx.y;
    const int h  = threadIdx.x;
    const int lane = h & 31, wid = h >> 5;

    float* buf;
    const float* sc;
    if (hd < NQ) { buf = &g_qkv[(size_t)bt * QKV_N + hd * HD];                 sc = qscale; }
    else         { buf = &g_qkv[(size_t)bt * QKV_N + K_OFF + (hd - NQ) * HD]; sc = kscale; }

    float v = buf[h];
    float ss = v * v;
#pragma unroll
    for (int off = 16; off; off >>= 1) ss += __shfl_xor_sync(0xffffffffu, ss, off);
    __shared__ float red[4];
    if (lane == 0) red[wid] = ss;
    __syncthreads();
    float tot = red[0] + red[1] + red[2] + red[3];
    float xn = sc[h] * v * rsqrtf(tot * (1.0f / HD) + 1e-6f);

    __shared__ float row[HD];
    row[h] = xn;
    __syncthreads();

    int segv  = seg[bt];
    int first = g_first[b];
    float pos = (segv != 0) ? (float)(t - first) : 1073741824.0f;
    int k2 = (h < 64) ? h : (h - 64);
    float invf = exp2f((-2.0f * (float)k2 / 128.0f) * 19.931568569324174f);
    float ang = pos * invf;
    float s_ = sinf(ang), c_ = cosf(ang);

    float rr;
    if (h < 64) rr = xn * c_ - row[h + 64] * s_;
    else        rr = xn * c_ + row[h - 64] * s_;
    buf[h] = rr;
}

// ============================================================
// 5) attention: 32 queries/block (4 per warp), float4 smem paths
// ============================================================
#define ATT_STRIDE 132
#define ATT_SMEM_FLOATS (96 * ATT_STRIDE + 32 * 32)
#define ATT_SMEM_BYTES (ATT_SMEM_FLOATS * 4)

__global__ __launch_bounds__(256) void attn_kernel() {
    extern __shared__ float sm[];
    float* Qs = sm;
    float* Ks = sm + 32 * ATT_STRIDE;
    float* Vs = sm + 64 * ATT_STRIDE;
    float* Ps = sm + 96 * ATT_STRIDE;

    const int tid  = threadIdx.x;
    const int wid  = tid >> 5;
    const int lane = tid & 31;
    const int b  = blockIdx.z;
    const int n  = blockIdx.y;
    const int kh = n >> 2;
    const int t0 = blockIdx.x * 32;
    const float SCALE = 0.08838834764831845f;

    for (int idx = tid; idx < 1024; idx += 256) {
        int r = idx >> 5, c4 = idx & 31;
        const float4* row = reinterpret_cast<const float4*>(
            g_qkv + (size_t)(b * T_ + t0 + r) * QKV_N + n * HD);
        float4 v = row[c4];
        v.x *= SCALE; v.y *= SCALE; v.z *= SCALE; v.w *= SCALE;
        *reinterpret_cast<float4*>(Qs + r * ATT_STRIDE + 4 * c4) = v;
    }

    const int start = g_start[b];
    const int t_w   = t0 + wid * 4 + 3;

    float m[4], l[4];
    float4 acc[4];
#pragma unroll
    for (int qi = 0; qi < 4; ++qi) {
        m[qi] = NEG_INF; l[qi] = 0.f;
        acc[qi] = make_float4(0.f, 0.f, 0.f, 0.f);
    }

    int s_begin = start & ~31;
    __syncthreads();

    for (int s0 = s_begin; s0 <= t0 + 31; s0 += 32) {
        for (int idx = tid; idx < 1024; idx += 256) {
            int sl = idx >> 5, c4 = idx & 31;
            int s = s0 + sl;
            float4 kv = make_float4(0.f, 0.f, 0.f, 0.f), vv = kv;
            if (s < T_) {
                const float4* row = reinterpret_cast<const float4*>(
                    g_qkv + (size_t)(b * T_ + s) * QKV_N + K_OFF + kh * HD);
                kv = row[c4];
                vv = row[c4 + 256];
            }
            *reinterpret_cast<float4*>(Ks + sl * ATT_STRIDE + 4 * c4) = kv;
            *reinterpret_cast<float4*>(Vs + sl * ATT_STRIDE + 4 * c4) = vv;
        }
        __syncthreads();

        if (s0 <= t_w) {
            float ascale[4];
            const float4* krow = reinterpret_cast<const float4*>(Ks + lane * ATT_STRIDE);
#pragma unroll
            for (int qi = 0; qi < 4; ++qi) {
                const int t_q = t0 + wid * 4 + qi;
                float p = 0.f;
                ascale[qi] = 1.f;
                if (s0 <= t_q) {
                    const float4* qrow = reinterpret_cast<const float4*>(
                        Qs + (wid * 4 + qi) * ATT_STRIDE);
                    float sc = 0.f;
#pragma unroll
                    for (int i = 0; i < 32; ++i) {
                        float4 qa = qrow[i], kb = krow[i];
                        sc = fmaf(qa.x, kb.x, sc);
                        sc = fmaf(qa.y, kb.y, sc);
                        sc = fmaf(qa.z, kb.z, sc);
                        sc = fmaf(qa.w, kb.w, sc);
                    }
                    int s = s0 + lane;
                    bool valid = (s >= start) && (s <= t_q);
                    float score = valid ? sc : NEG_INF;
                    float mt = score;
#pragma unroll
                    for (int off = 16; off; off >>= 1)
                        mt = fmaxf(mt, __shfl_xor_sync(0xffffffffu, mt, off));
                    float m_new = fmaxf(m[qi], mt);
                    float alpha = (m_new == NEG_INF) ? 1.0f : __expf(m[qi] - m_new);
                    p = valid ? __expf(score - m_new) : 0.f;
                    float psum = p;
#pragma unroll
                    for (int off = 16; off; off >>= 1)
                        psum += __shfl_xor_sync(0xffffffffu, psum, off);
                    l[qi] = l[qi] * alpha + psum;
                    m[qi] = m_new;
                    ascale[qi] = alpha;
                }
                Ps[(wid * 4 + qi) * 32 + lane] = p;
            }
            __syncwarp();

#pragma unroll
            for (int qi = 0; qi < 4; ++qi) {
                acc[qi].x *= ascale[qi]; acc[qi].y *= ascale[qi];
                acc[qi].z *= ascale[qi]; acc[qi].w *= ascale[qi];
            }
#pragma unroll 8
            for (int sl = 0; sl < 32; ++sl) {
                float4 vv = *reinterpret_cast<const float4*>(Vs + sl * ATT_STRIDE + 4 * lane);
#pragma unroll
                for (int qi = 0; qi < 4; ++qi) {
                    float p = Ps[(wid * 4 + qi) * 32 + sl];
                    acc[qi].x = fmaf(p, vv.x, acc[qi].x);
                    acc[qi].y = fmaf(p, vv.y, acc[qi].y);
                    acc[qi].z = fmaf(p, vv.z, acc[qi].z);
                    acc[qi].w = fmaf(p, vv.w, acc[qi].w);
                }
            }
        }
        __syncthreads();
    }

#pragma unroll
    for (int qi = 0; qi < 4; ++qi) {
        const int t_q = t0 + wid * 4 + qi;
        float invl = (l[qi] > 0.f) ? (1.0f / l[qi]) : 0.f;
        float4 o;
        o.x = tf32r(acc[qi].x * invl);
        o.y = tf32r(acc[qi].y * invl);
        o.z = tf32r(acc[qi].z * invl);
        o.w = tf32r(acc[qi].w * invl);
        *reinterpret_cast<float4*>(
            &g_o[((size_t)(b * T_ + t_q) * NQ + n) * HD + 4 * lane]) = o;
    }
}

// ============================================================
// launch
// ============================================================
extern "C" void kernel_launch(void* const* d_in, const int* in_sizes, int n_in,
                              void* d_out, int out_size) {
    const float* x       = (const float*)d_in[0];
    const float* wq      = (const float*)d_in[1];
    const float* wk      = (const float*)d_in[2];
    const float* wv      = (const float*)d_in[3];
    const float* wo      = (const float*)d_in[4];
    const float* q_scale = (const float*)d_in[5];
    const float* k_scale = (const float*)d_in[6];
    const int*   seg     = (const int*)d_in[9];
    float* out = (float*)d_out;

    float *pqkv, *po, *pxr, *pwqkv, *pwo;
    cudaGetSymbolAddress((void**)&pqkv, g_qkv);
    cudaGetSymbolAddress((void**)&po, g_o);
    cudaGetSymbolAddress((void**)&pxr, g_xr);
    cudaGetSymbolAddress((void**)&pwqkv, g_wqkv);
    cudaGetSymbolAddress((void**)&pwo, g_wo_r);

    cudaFuncSetAttribute(gemm_mma_kernel, cudaFuncAttributeMaxDynamicSharedMemorySize,
                         GEMM_SMEM);
    cudaFuncSetAttribute(attn_kernel, cudaFuncAttributeMaxDynamicSharedMemorySize,
                         ATT_SMEM_BYTES);

    startfirst_kernel<<<B_, 256>>>(seg);

    // tf32 pre-round (wo copy deferred until after attention)
    round_copy_kernel<<<(MTOT * D_ / 4) / 256, 256>>>((const float4*)x, (float4*)pxr);
    pack_wqkv_kernel<<<((size_t)D_ * QKV_N / 4) / 256, 256>>>(
        (const float4*)wq, (const float4*)wk, (const float4*)wv, (float4*)pwqkv);

    // fused q/k/v projection: N=6144, K=4096
    gemm_mma_kernel<<<dim3(QKV_N / 128, MTOT / 128), 256, GEMM_SMEM>>>(
        pxr, pwqkv, pqkv, QKV_N, D_);

    ropenorm_kernel<<<dim3(MTOT, NQ + NKV), 128>>>(q_scale, k_scale, seg);

    attn_kernel<<<dim3(T_ / 32, NQ, B_), 256, ATT_SMEM_BYTES>>>();

    round_copy_kernel<<<((size_t)NQ * HD * D_ / 4) / 256, 256>>>((const float4*)wo, (float4*)pwo);

    // output projection: [2048, 4096] @ [4096, 4096] -> d_out
    gemm_mma_kernel<<<dim3(D_ / 128, MTOT / 128), 256, GEMM_SMEM>>>(po, pwo, out, D_, NQ * HD);
}

// round 6
// speedup vs baseline: 3.0033x; 1.1801x over previous
#include <cuda_runtime.h>
#include <cuda_fp16.h>
#include <math.h>
#include <stdint.h>

// Problem constants
#define B_   2
#define T_   1024
#define D_   4096
#define NQ   32
#define NKV  8
#define HD   128
#define MTOT (B_ * T_)      // 2048
#define QKV_N 6144          // 4096 q + 1024 k + 1024 v
#define K_OFF 4096

#define NEG_INF (-INFINITY)

// -------- scratch (device globals; allocation-free) --------
__device__ __align__(256) float  g_qkv[(size_t)MTOT * QKV_N];     // 48 MB (f32 qkv)
__device__ __align__(256) __half g_oh[(size_t)MTOT * NQ * HD];    // 16 MB (attn out, f16)
__device__ __align__(256) __half g_xh[(size_t)MTOT * D_];         // 16 MB (x, f16)
__device__ __align__(256) __half g_wqkvh[(size_t)QKV_N * D_];     // 48 MB ([n][k] transposed)
__device__ __align__(256) __half g_woh[(size_t)D_ * NQ * HD];     // 32 MB ([d][nh] transposed)
__device__ int g_start[B_];
__device__ int g_first[B_];

// ============================================================
// helpers
// ============================================================
__device__ __forceinline__ uint32_t smem_u32(const void* p) {
    uint32_t a;
    asm("{ .reg .u64 t; cvta.to.shared.u64 t, %1; cvt.u32.u64 %0, t; }" : "=r"(a) : "l"(p));
    return a;
}

#define CP_ASYNC16(saddr, gptr) \
    asm volatile("cp.async.cg.shared.global [%0], [%1], 16;" :: "r"(saddr), "l"(gptr) : "memory")
#define CP_COMMIT() asm volatile("cp.async.commit_group;" ::: "memory")
#define CP_WAIT3()  asm volatile("cp.async.wait_group 3;" ::: "memory")

#define LDSM4(r0, r1, r2, r3, addr) \
    asm volatile("ldmatrix.sync.aligned.m8n8.x4.shared.b16 {%0,%1,%2,%3}, [%4];" \
        : "=r"(r0), "=r"(r1), "=r"(r2), "=r"(r3) : "r"(addr))

__device__ __forceinline__ void mma_f16(float c[4],
                                        uint32_t a0, uint32_t a1, uint32_t a2, uint32_t a3,
                                        uint32_t b0, uint32_t b1) {
    asm volatile(
        "mma.sync.aligned.m16n8k16.row.col.f32.f16.f16.f32 "
        "{%0,%1,%2,%3}, {%4,%5,%6,%7}, {%8,%9}, {%0,%1,%2,%3};"
        : "+f"(c[0]), "+f"(c[1]), "+f"(c[2]), "+f"(c[3])
        : "r"(a0), "r"(a1), "r"(a2), "r"(a3), "r"(b0), "r"(b1));
}

// ============================================================
// 1) segment scan
// ============================================================
__global__ void startfirst_kernel(const int* __restrict__ seg) {
    int b = blockIdx.x;
    const int* s = seg + (size_t)b * T_;
    __shared__ int sh_min, sh_max, sh_first;
    if (threadIdx.x == 0) { sh_min = T_; sh_max = INT_MIN; sh_first = T_; }
    __syncthreads();
    int lmin = T_, lmax = INT_MIN;
    for (int t = threadIdx.x; t < T_; t += blockDim.x) {
        int v = s[t];
        if (v != 0 && t < lmin) lmin = t;
        if (v > lmax) lmax = v;
    }
    atomicMin(&sh_min, lmin);
    atomicMax(&sh_max, lmax);
    __syncthreads();
    int mx = sh_max;
    int lfirst = T_;
    for (int t = threadIdx.x; t < T_; t += blockDim.x)
        if (s[t] == mx && t < lfirst) lfirst = t;
    atomicMin(&sh_first, lfirst);
    __syncthreads();
    if (threadIdx.x == 0) { g_start[b] = sh_min; g_first[b] = sh_first; }
}

// ============================================================
// 2) conversions
// ============================================================
__global__ void f32_to_f16_kernel(const float4* __restrict__ src, __half2* __restrict__ dst) {
    int i = blockIdx.x * blockDim.x + threadIdx.x;
    float4 v = src[i];
    dst[2 * i]     = __floats2half2_rn(v.x, v.y);
    dst[2 * i + 1] = __floats2half2_rn(v.z, v.w);
}

// transpose f32 [R][C] -> f16 [C][R]
__global__ void transpose_f16_kernel(const float* __restrict__ in, __half* __restrict__ out,
                                     int R, int C) {
    __shared__ float tile[32][33];
    int x  = blockIdx.x * 32 + threadIdx.x;
    int y0 = blockIdx.y * 32;
#pragma unroll
    for (int j = threadIdx.y; j < 32; j += 8)
        tile[j][threadIdx.x] = in[(size_t)(y0 + j) * C + x];
    __syncthreads();
    int ox  = y0 + threadIdx.x;
    int oy0 = blockIdx.x * 32;
#pragma unroll
    for (int j = threadIdx.y; j < 32; j += 8)
        out[(size_t)(oy0 + j) * R + ox] = __float2half(tile[threadIdx.x][j]);
}

// ============================================================
// 3) fp16 mma.sync GEMM: C[M x N] = A[M x K] * Bt[N x K]^T  (f32 out)
//    BM=BN=128, BK=32, 5-stage cp.async, 8 warps (2x4), warp tile 64x32,
//    ldmatrix fragments.
// ============================================================
#define GSTAGES 5
#define H_STRIDE 40                           // halves per smem row (80B, conflict-free)
#define TILE_BYTES (128 * H_STRIDE * 2)       // 10240
#define STAGE_BYTES (2 * TILE_BYTES)          // 20480
#define GEMM_SMEM (GSTAGES * STAGE_BYTES)     // 102400

__global__ __launch_bounds__(256, 2)
void gemm_f16_kernel(const __half* __restrict__ A, const __half* __restrict__ Bt,
                     float* __restrict__ C, int N, int K) {
    extern __shared__ char smem[];
    const uint32_t sb = smem_u32(smem);
    const int tid  = threadIdx.x;
    const int wid  = tid >> 5;
    const int lane = tid & 31;
    const int g    = lane >> 2;
    const int r    = lane & 3;
    const int row0 = blockIdx.y * 128;
    const int col0 = blockIdx.x * 128;
    const int wm   = (wid >> 2) * 64;
    const int wn   = (wid & 3) * 32;
    const int lrow = lane & 15;
    const int lk8  = (lane >> 4) * 8;   // 0 or 8 (halves)

    float acc[4][4][4];
#pragma unroll
    for (int a = 0; a < 4; ++a)
#pragma unroll
        for (int b = 0; b < 4; ++b)
#pragma unroll
            for (int c = 0; c < 4; ++c) acc[a][b][c] = 0.f;

    const int KS = K >> 5;   // BK = 32

    auto load_stage = [&](int st, int k0) {
        uint32_t abase = sb + st * STAGE_BYTES;
        uint32_t bbase = abase + TILE_BYTES;
#pragma unroll
        for (int j = 0; j < 2; ++j) {
            int f  = tid + 256 * j;     // 0..511
            int rr = f >> 2, cc = f & 3;
            CP_ASYNC16(abase + rr * 80 + cc * 16,
                       A + (size_t)(row0 + rr) * K + k0 + cc * 8);
            CP_ASYNC16(bbase + rr * 80 + cc * 16,
                       Bt + (size_t)(col0 + rr) * K + k0 + cc * 8);
        }
    };

    auto compute_stage = [&](int st) {
        uint32_t abase = sb + st * STAGE_BYTES;
        uint32_t bbase = abase + TILE_BYTES;
#pragma unroll
        for (int ks = 0; ks < 2; ++ks) {
            const int kb = ks * 16 + lk8;     // half offset within BK
            uint32_t br[2][4];
#pragma unroll
            for (int ntp = 0; ntp < 2; ++ntp) {
                uint32_t addr = bbase + (uint32_t)(wn + ntp * 16 + lrow) * 80 + kb * 2;
                LDSM4(br[ntp][0], br[ntp][1], br[ntp][2], br[ntp][3], addr);
            }
#pragma unroll
            for (int mt = 0; mt < 4; ++mt) {
                uint32_t a0, a1, a2, a3;
                uint32_t addr = abase + (uint32_t)(wm + mt * 16 + lrow) * 80 + kb * 2;
                LDSM4(a0, a1, a2, a3, addr);
                mma_f16(acc[mt][0], a0, a1, a2, a3, br[0][0], br[0][2]);
                mma_f16(acc[mt][1], a0, a1, a2, a3, br[0][1], br[0][3]);
                mma_f16(acc[mt][2], a0, a1, a2, a3, br[1][0], br[1][2]);
                mma_f16(acc[mt][3], a0, a1, a2, a3, br[1][1], br[1][3]);
            }
        }
    };

    // prologue: 4 stages in flight
    load_stage(0, 0);   CP_COMMIT();
    load_stage(1, 32);  CP_COMMIT();
    load_stage(2, 64);  CP_COMMIT();
    load_stage(3, 96);  CP_COMMIT();

    int slot = 0, lslot = 4;
    for (int i = 0; i < KS; ++i) {
        CP_WAIT3();
        __syncthreads();
        if (i + 4 < KS) load_stage(lslot, (i + 4) << 5);
        CP_COMMIT();
        compute_stage(slot);
        if (++slot == GSTAGES) slot = 0;
        if (++lslot == GSTAGES) lslot = 0;
    }

#pragma unroll
    for (int mt = 0; mt < 4; ++mt) {
        int mrow = row0 + wm + mt * 16;
#pragma unroll
        for (int nt = 0; nt < 4; ++nt) {
            int ncol = col0 + wn + nt * 8 + 2 * r;
            *reinterpret_cast<float2*>(&C[(size_t)(mrow + g) * N + ncol]) =
                make_float2(acc[mt][nt][0], acc[mt][nt][1]);
            *reinterpret_cast<float2*>(&C[(size_t)(mrow + g + 8) * N + ncol]) =
                make_float2(acc[mt][nt][2], acc[mt][nt][3]);
        }
    }
}

// fp16-out variant epilogue is handled by writing f32 then separate use; O-proj
// writes f32 directly to d_out, QKV writes f32 to g_qkv. (single kernel reused)

// ============================================================
// 4) fused RMSNorm + RoPE over combined qkv buffer (f32)
// ============================================================
__global__ __launch_bounds__(128) void ropenorm_kernel(
    const float* __restrict__ qscale, const float* __restrict__ kscale,
    const int* __restrict__ seg)
{
    const int bt = blockIdx.x;
    const int b  = bt >> 10;
    const int t  = bt & (T_ - 1);
    const int hd = blockIdx.y;
    const int h  = threadIdx.x;
    const int lane = h & 31, wid = h >> 5;

    float* buf;
    const float* sc;
    if (hd < NQ) { buf = &g_qkv[(size_t)bt * QKV_N + hd * HD];                 sc = qscale; }
    else         { buf = &g_qkv[(size_t)bt * QKV_N + K_OFF + (hd - NQ) * HD]; sc = kscale; }

    float v = buf[h];
    float ss = v * v;
#pragma unroll
    for (int off = 16; off; off >>= 1) ss += __shfl_xor_sync(0xffffffffu, ss, off);
    __shared__ float red[4];
    if (lane == 0) red[wid] = ss;
    __syncthreads();
    float tot = red[0] + red[1] + red[2] + red[3];
    float xn = sc[h] * v * rsqrtf(tot * (1.0f / HD) + 1e-6f);

    __shared__ float row[HD];
    row[h] = xn;
    __syncthreads();

    int segv  = seg[bt];
    int first = g_first[b];
    float pos = (segv != 0) ? (float)(t - first) : 1073741824.0f;
    int k2 = (h < 64) ? h : (h - 64);
    float invf = exp2f((-2.0f * (float)k2 / 128.0f) * 19.931568569324174f);
    float ang = pos * invf;
    float s_ = sinf(ang), c_ = cosf(ang);

    float rr;
    if (h < 64) rr = xn * c_ - row[h + 64] * s_;
    else        rr = xn * c_ + row[h - 64] * s_;
    buf[h] = rr;
}

// ============================================================
// 5) attention: 32 queries/block (4 per warp), f32 math, f16 output
// ============================================================
#define ATT_STRIDE 132
#define ATT_SMEM_FLOATS (96 * ATT_STRIDE + 32 * 32)
#define ATT_SMEM_BYTES (ATT_SMEM_FLOATS * 4)

__global__ __launch_bounds__(256) void attn_kernel() {
    extern __shared__ float sm[];
    float* Qs = sm;
    float* Ks = sm + 32 * ATT_STRIDE;
    float* Vs = sm + 64 * ATT_STRIDE;
    float* Ps = sm + 96 * ATT_STRIDE;

    const int tid  = threadIdx.x;
    const int wid  = tid >> 5;
    const int lane = tid & 31;
    const int b  = blockIdx.z;
    const int n  = blockIdx.y;
    const int kh = n >> 2;
    const int t0 = blockIdx.x * 32;
    const float SCALE = 0.08838834764831845f;

    for (int idx = tid; idx < 1024; idx += 256) {
        int r = idx >> 5, c4 = idx & 31;
        const float4* row = reinterpret_cast<const float4*>(
            g_qkv + (size_t)(b * T_ + t0 + r) * QKV_N + n * HD);
        float4 v = row[c4];
        v.x *= SCALE; v.y *= SCALE; v.z *= SCALE; v.w *= SCALE;
        *reinterpret_cast<float4*>(Qs + r * ATT_STRIDE + 4 * c4) = v;
    }

    const int start = g_start[b];
    const int t_w   = t0 + wid * 4 + 3;

    float m[4], l[4];
    float4 acc[4];
#pragma unroll
    for (int qi = 0; qi < 4; ++qi) {
        m[qi] = NEG_INF; l[qi] = 0.f;
        acc[qi] = make_float4(0.f, 0.f, 0.f, 0.f);
    }

    int s_begin = start & ~31;
    __syncthreads();

    for (int s0 = s_begin; s0 <= t0 + 31; s0 += 32) {
        for (int idx = tid; idx < 1024; idx += 256) {
            int sl = idx >> 5, c4 = idx & 31;
            int s = s0 + sl;
            float4 kv = make_float4(0.f, 0.f, 0.f, 0.f), vv = kv;
            if (s < T_) {
                const float4* row = reinterpret_cast<const float4*>(
                    g_qkv + (size_t)(b * T_ + s) * QKV_N + K_OFF + kh * HD);
                kv = row[c4];
                vv = row[c4 + 256];
            }
            *reinterpret_cast<float4*>(Ks + sl * ATT_STRIDE + 4 * c4) = kv;
            *reinterpret_cast<float4*>(Vs + sl * ATT_STRIDE + 4 * c4) = vv;
        }
        __syncthreads();

        if (s0 <= t_w) {
            float ascale[4];
            const float4* krow = reinterpret_cast<const float4*>(Ks + lane * ATT_STRIDE);
#pragma unroll
            for (int qi = 0; qi < 4; ++qi) {
                const int t_q = t0 + wid * 4 + qi;
                float p = 0.f;
                ascale[qi] = 1.f;
                if (s0 <= t_q) {
                    const float4* qrow = reinterpret_cast<const float4*>(
                        Qs + (wid * 4 + qi) * ATT_STRIDE);
                    float sc = 0.f;
#pragma unroll
                    for (int i = 0; i < 32; ++i) {
                        float4 qa = qrow[i], kb = krow[i];
                        sc = fmaf(qa.x, kb.x, sc);
                        sc = fmaf(qa.y, kb.y, sc);
                        sc = fmaf(qa.z, kb.z, sc);
                        sc = fmaf(qa.w, kb.w, sc);
                    }
                    int s = s0 + lane;
                    bool valid = (s >= start) && (s <= t_q);
                    float score = valid ? sc : NEG_INF;
                    float mt = score;
#pragma unroll
                    for (int off = 16; off; off >>= 1)
                        mt = fmaxf(mt, __shfl_xor_sync(0xffffffffu, mt, off));
                    float m_new = fmaxf(m[qi], mt);
                    float alpha = (m_new == NEG_INF) ? 1.0f : __expf(m[qi] - m_new);
                    p = valid ? __expf(score - m_new) : 0.f;
                    float psum = p;
#pragma unroll
                    for (int off = 16; off; off >>= 1)
                        psum += __shfl_xor_sync(0xffffffffu, psum, off);
                    l[qi] = l[qi] * alpha + psum;
                    m[qi] = m_new;
                    ascale[qi] = alpha;
                }
                Ps[(wid * 4 + qi) * 32 + lane] = p;
            }
            __syncwarp();

#pragma unroll
            for (int qi = 0; qi < 4; ++qi) {
                acc[qi].x *= ascale[qi]; acc[qi].y *= ascale[qi];
                acc[qi].z *= ascale[qi]; acc[qi].w *= ascale[qi];
            }
#pragma unroll 8
            for (int sl = 0; sl < 32; ++sl) {
                float4 vv = *reinterpret_cast<const float4*>(Vs + sl * ATT_STRIDE + 4 * lane);
#pragma unroll
                for (int qi = 0; qi < 4; ++qi) {
                    float p = Ps[(wid * 4 + qi) * 32 + sl];
                    acc[qi].x = fmaf(p, vv.x, acc[qi].x);
                    acc[qi].y = fmaf(p, vv.y, acc[qi].y);
                    acc[qi].z = fmaf(p, vv.z, acc[qi].z);
                    acc[qi].w = fmaf(p, vv.w, acc[qi].w);
                }
            }
        }
        __syncthreads();
    }

#pragma unroll
    for (int qi = 0; qi < 4; ++qi) {
        const int t_q = t0 + wid * 4 + qi;
        float invl = (l[qi] > 0.f) ? (1.0f / l[qi]) : 0.f;
        __half2* dst = reinterpret_cast<__half2*>(
            &g_oh[((size_t)(b * T_ + t_q) * NQ + n) * HD + 4 * lane]);
        dst[0] = __floats2half2_rn(acc[qi].x * invl, acc[qi].y * invl);
        dst[1] = __floats2half2_rn(acc[qi].z * invl, acc[qi].w * invl);
    }
}

// ============================================================
// launch
// ============================================================
extern "C" void kernel_launch(void* const* d_in, const int* in_sizes, int n_in,
                              void* d_out, int out_size) {
    const float* x       = (const float*)d_in[0];
    const float* wq      = (const float*)d_in[1];
    const float* wk      = (const float*)d_in[2];
    const float* wv      = (const float*)d_in[3];
    const float* wo      = (const float*)d_in[4];
    const float* q_scale = (const float*)d_in[5];
    const float* k_scale = (const float*)d_in[6];
    const int*   seg     = (const int*)d_in[9];
    float* out = (float*)d_out;

    float  *pqkv;
    __half *poh, *pxh, *pwqkvh, *pwoh;
    cudaGetSymbolAddress((void**)&pqkv, g_qkv);
    cudaGetSymbolAddress((void**)&poh, g_oh);
    cudaGetSymbolAddress((void**)&pxh, g_xh);
    cudaGetSymbolAddress((void**)&pwqkvh, g_wqkvh);
    cudaGetSymbolAddress((void**)&pwoh, g_woh);

    cudaFuncSetAttribute(gemm_f16_kernel, cudaFuncAttributeMaxDynamicSharedMemorySize,
                         GEMM_SMEM);
    cudaFuncSetAttribute(attn_kernel, cudaFuncAttributeMaxDynamicSharedMemorySize,
                         ATT_SMEM_BYTES);

    startfirst_kernel<<<B_, 256>>>(seg);

    // x -> fp16 (row-major [m][k])
    f32_to_f16_kernel<<<(MTOT * D_ / 4) / 256, 256>>>(
        (const float4*)x, (__half2*)pxh);
    // weights -> fp16, transposed to [n][k] (packed q|k|v) and [d][nh]
    transpose_f16_kernel<<<dim3(D_ / 32, D_ / 32), dim3(32, 8)>>>(
        wq, pwqkvh, D_, NQ * HD);                       // wait: wq is [D][4096]
    // NOTE: transpose kernel signature: in [R][C] -> out [C][R]; wq: R=D rows, C=4096
    transpose_f16_kernel<<<dim3(NKV * HD / 32, D_ / 32), dim3(32, 8)>>>(
        wk, pwqkvh + (size_t)K_OFF * D_, D_, NKV * HD);
    transpose_f16_kernel<<<dim3(NKV * HD / 32, D_ / 32), dim3(32, 8)>>>(
        wv, pwqkvh + (size_t)(K_OFF + NKV * HD) * D_, D_, NKV * HD);

    // fused q/k/v projection: N=6144, K=4096, f32 out
    gemm_f16_kernel<<<dim3(QKV_N / 128, MTOT / 128), 256, GEMM_SMEM>>>(
        pxh, pwqkvh, pqkv, QKV_N, D_);

    ropenorm_kernel<<<dim3(MTOT, NQ + NKV), 128>>>(q_scale, k_scale, seg);

    attn_kernel<<<dim3(T_ / 32, NQ, B_), 256, ATT_SMEM_BYTES>>>();

    transpose_f16_kernel<<<dim3(D_ / 32, NQ * HD / 32), dim3(32, 8)>>>(
        wo, pwoh, NQ * HD, D_);

    // output projection: [2048, 4096] @ [4096, 4096] -> d_out (f32)
    gemm_f16_kernel<<<dim3(D_ / 128, MTOT / 128), 256, GEMM_SMEM>>>(
        poh, pwoh, out, D_, NQ * HD);
}

// round 8
// speedup vs baseline: 6.7704x; 2.2543x over previous
#include <cuda_runtime.h>
#include <cuda_fp16.h>
#include <math.h>
#include <stdint.h>

// Problem constants
#define B_   2
#define T_   1024
#define D_   4096
#define NQ   32
#define NKV  8
#define HD   128
#define MTOT (B_ * T_)      // 2048
#define QKV_N 6144          // 4096 q + 1024 k + 1024 v
#define K_OFF 4096
#define V_OFF 5120

#define NEG_INF (-INFINITY)

// -------- scratch (device globals; allocation-free) --------
__device__ __align__(256) float  g_qkv[(size_t)MTOT * QKV_N];     // 48 MB (f32 qkv)
__device__ __align__(256) __half g_qh[(size_t)MTOT * NQ * HD];    // 16 MB (q fp16, pre-scaled)
__device__ __align__(256) __half g_kh[(size_t)MTOT * NKV * HD];   //  4 MB
__device__ __align__(256) __half g_vh[(size_t)MTOT * NKV * HD];   //  4 MB
__device__ __align__(256) __half g_oh[(size_t)MTOT * NQ * HD];    // 16 MB (attn out, f16)
__device__ __align__(256) __half g_xh[(size_t)MTOT * D_];         // 16 MB (x, f16)
__device__ __align__(256) __half g_wqkvh[(size_t)QKV_N * D_];     // 48 MB ([n][k])
__device__ __align__(256) __half g_woh[(size_t)D_ * NQ * HD];     // 32 MB ([d][nh])
__device__ int g_start[B_];
__device__ int g_first[B_];

// ============================================================
// helpers
// ============================================================
__device__ __forceinline__ uint32_t smem_u32(const void* p) {
    uint32_t a;
    asm("{ .reg .u64 t; cvta.to.shared.u64 t, %1; cvt.u32.u64 %0, t; }" : "=r"(a) : "l"(p));
    return a;
}
__device__ __forceinline__ uint32_t h2_as_u32(__half2 h) {
    return *reinterpret_cast<uint32_t*>(&h);
}

#define CP_ASYNC16(saddr, gptr) \
    asm volatile("cp.async.cg.shared.global [%0], [%1], 16;" :: "r"(saddr), "l"(gptr) : "memory")
#define CP_COMMIT() asm volatile("cp.async.commit_group;" ::: "memory")
#define CP_WAIT3()  asm volatile("cp.async.wait_group 3;" ::: "memory")
#define CP_WAIT1()  asm volatile("cp.async.wait_group 1;" ::: "memory")

#define LDSM4(r0, r1, r2, r3, addr) \
    asm volatile("ldmatrix.sync.aligned.m8n8.x4.shared.b16 {%0,%1,%2,%3}, [%4];" \
        : "=r"(r0), "=r"(r1), "=r"(r2), "=r"(r3) : "r"(addr))
#define LDSM4T(r0, r1, r2, r3, addr) \
    asm volatile("ldmatrix.sync.aligned.m8n8.x4.trans.shared.b16 {%0,%1,%2,%3}, [%4];" \
        : "=r"(r0), "=r"(r1), "=r"(r2), "=r"(r3) : "r"(addr))

__device__ __forceinline__ void mma_f16(float c[4],
                                        uint32_t a0, uint32_t a1, uint32_t a2, uint32_t a3,
                                        uint32_t b0, uint32_t b1) {
    asm volatile(
        "mma.sync.aligned.m16n8k16.row.col.f32.f16.f16.f32 "
        "{%0,%1,%2,%3}, {%4,%5,%6,%7}, {%8,%9}, {%0,%1,%2,%3};"
        : "+f"(c[0]), "+f"(c[1]), "+f"(c[2]), "+f"(c[3])
        : "r"(a0), "r"(a1), "r"(a2), "r"(a3), "r"(b0), "r"(b1));
}

// ============================================================
// 1) segment scan
// ============================================================
__global__ void startfirst_kernel(const int* __restrict__ seg) {
    int b = blockIdx.x;
    const int* s = seg + (size_t)b * T_;
    __shared__ int sh_min, sh_max, sh_first;
    if (threadIdx.x == 0) { sh_min = T_; sh_max = INT_MIN; sh_first = T_; }
    __syncthreads();
    int lmin = T_, lmax = INT_MIN;
    for (int t = threadIdx.x; t < T_; t += blockDim.x) {
        int v = s[t];
        if (v != 0 && t < lmin) lmin = t;
        if (v > lmax) lmax = v;
    }
    atomicMin(&sh_min, lmin);
    atomicMax(&sh_max, lmax);
    __syncthreads();
    int mx = sh_max;
    int lfirst = T_;
    for (int t = threadIdx.x; t < T_; t += blockDim.x)
        if (s[t] == mx && t < lfirst) lfirst = t;
    atomicMin(&sh_first, lfirst);
    __syncthreads();
    if (threadIdx.x == 0) { g_start[b] = sh_min; g_first[b] = sh_first; }
}

// ============================================================
// 2) conversions
// ============================================================
__global__ void f32_to_f16_kernel(const float4* __restrict__ src, __half2* __restrict__ dst) {
    int i = blockIdx.x * blockDim.x + threadIdx.x;
    float4 v = src[i];
    dst[2 * i]     = __floats2half2_rn(v.x, v.y);
    dst[2 * i + 1] = __floats2half2_rn(v.z, v.w);
}

// transpose f32 [R][C] -> f16 [C][R]
__global__ void transpose_f16_kernel(const float* __restrict__ in, __half* __restrict__ out,
                                     int R, int C) {
    __shared__ float tile[32][33];
    int x  = blockIdx.x * 32 + threadIdx.x;
    int y0 = blockIdx.y * 32;
#pragma unroll
    for (int j = threadIdx.y; j < 32; j += 8)
        tile[j][threadIdx.x] = in[(size_t)(y0 + j) * C + x];
    __syncthreads();
    int ox  = y0 + threadIdx.x;
    int oy0 = blockIdx.x * 32;
#pragma unroll
    for (int j = threadIdx.y; j < 32; j += 8)
        out[(size_t)(oy0 + j) * R + ox] = __float2half(tile[threadIdx.x][j]);
}

// ============================================================
// 3) fp16 mma.sync GEMM
// ============================================================
#define GSTAGES 5
#define H_STRIDE 40
#define TILE_BYTES (128 * H_STRIDE * 2)
#define STAGE_BYTES (2 * TILE_BYTES)
#define GEMM_SMEM (GSTAGES * STAGE_BYTES)

__global__ __launch_bounds__(256, 2)
void gemm_f16_kernel(const __half* __restrict__ A, const __half* __restrict__ Bt,
                     float* __restrict__ C, int N, int K) {
    extern __shared__ char smem[];
    const uint32_t sb = smem_u32(smem);
    const int tid  = threadIdx.x;
    const int wid  = tid >> 5;
    const int lane = tid & 31;
    const int g    = lane >> 2;
    const int r    = lane & 3;
    const int row0 = blockIdx.y * 128;
    const int col0 = blockIdx.x * 128;
    const int wm   = (wid >> 2) * 64;
    const int wn   = (wid & 3) * 32;
    const int lrow = lane & 15;
    const int lk8  = (lane >> 4) * 8;

    float acc[4][4][4];
#pragma unroll
    for (int a = 0; a < 4; ++a)
#pragma unroll
        for (int b = 0; b < 4; ++b)
#pragma unroll
            for (int c = 0; c < 4; ++c) acc[a][b][c] = 0.f;

    const int KS = K >> 5;

    auto load_stage = [&](int st, int k0) {
        uint32_t abase = sb + st * STAGE_BYTES;
        uint32_t bbase = abase + TILE_BYTES;
#pragma unroll
        for (int j = 0; j < 2; ++j) {
            int f  = tid + 256 * j;
            int rr = f >> 2, cc = f & 3;
            CP_ASYNC16(abase + rr * 80 + cc * 16,
                       A + (size_t)(row0 + rr) * K + k0 + cc * 8);
            CP_ASYNC16(bbase + rr * 80 + cc * 16,
                       Bt + (size_t)(col0 + rr) * K + k0 + cc * 8);
        }
    };

    auto compute_stage = [&](int st) {
        uint32_t abase = sb + st * STAGE_BYTES;
        uint32_t bbase = abase + TILE_BYTES;
#pragma unroll
        for (int ks = 0; ks < 2; ++ks) {
            const int kb = ks * 16 + lk8;
            uint32_t br[2][4];
#pragma unroll
            for (int ntp = 0; ntp < 2; ++ntp) {
                uint32_t addr = bbase + (uint32_t)(wn + ntp * 16 + lrow) * 80 + kb * 2;
                LDSM4(br[ntp][0], br[ntp][1], br[ntp][2], br[ntp][3], addr);
            }
#pragma unroll
            for (int mt = 0; mt < 4; ++mt) {
                uint32_t a0, a1, a2, a3;
                uint32_t addr = abase + (uint32_t)(wm + mt * 16 + lrow) * 80 + kb * 2;
                LDSM4(a0, a1, a2, a3, addr);
                mma_f16(acc[mt][0], a0, a1, a2, a3, br[0][0], br[0][2]);
                mma_f16(acc[mt][1], a0, a1, a2, a3, br[0][1], br[0][3]);
                mma_f16(acc[mt][2], a0, a1, a2, a3, br[1][0], br[1][2]);
                mma_f16(acc[mt][3], a0, a1, a2, a3, br[1][1], br[1][3]);
            }
        }
    };

    load_stage(0, 0);   CP_COMMIT();
    load_stage(1, 32);  CP_COMMIT();
    load_stage(2, 64);  CP_COMMIT();
    load_stage(3, 96);  CP_COMMIT();

    int slot = 0, lslot = 4;
    for (int i = 0; i < KS; ++i) {
        CP_WAIT3();
        __syncthreads();
        if (i + 4 < KS) load_stage(lslot, (i + 4) << 5);
        CP_COMMIT();
        compute_stage(slot);
        if (++slot == GSTAGES) slot = 0;
        if (++lslot == GSTAGES) lslot = 0;
    }

#pragma unroll
    for (int mt = 0; mt < 4; ++mt) {
        int mrow = row0 + wm + mt * 16;
#pragma unroll
        for (int nt = 0; nt < 4; ++nt) {
            int ncol = col0 + wn + nt * 8 + 2 * r;
            *reinterpret_cast<float2*>(&C[(size_t)(mrow + g) * N + ncol]) =
                make_float2(acc[mt][nt][0], acc[mt][nt][1]);
            *reinterpret_cast<float2*>(&C[(size_t)(mrow + g + 8) * N + ncol]) =
                make_float2(acc[mt][nt][2], acc[mt][nt][3]);
        }
    }
}

// ============================================================
// 4) fused RMSNorm + RoPE -> fp16 outputs (q pre-scaled), v convert
// ============================================================
__global__ __launch_bounds__(128) void ropenorm_kernel(
    const float* __restrict__ qscale, const float* __restrict__ kscale,
    const int* __restrict__ seg)
{
    const int bt = blockIdx.x;
    const int b  = bt >> 10;
    const int t  = bt & (T_ - 1);
    const int hd = blockIdx.y;
    const int h  = threadIdx.x;
    const int lane = h & 31, wid = h >> 5;

    if (hd >= NQ + NKV) {   // v: convert only
        int vh = hd - NQ - NKV;
        float v = g_qkv[(size_t)bt * QKV_N + V_OFF + vh * HD + h];
        g_vh[((size_t)bt * NKV + vh) * HD + h] = __float2half(v);
        return;
    }

    const float* buf;
    const float* sc;
    __half* outp;
    float oscale = 1.0f;
    if (hd < NQ) {
        buf = &g_qkv[(size_t)bt * QKV_N + hd * HD];
        sc = qscale;
        outp = &g_qh[((size_t)bt * NQ + hd) * HD];
        oscale = 0.08838834764831845f;   // 1/sqrt(128)
    } else {
        buf = &g_qkv[(size_t)bt * QKV_N + K_OFF + (hd - NQ) * HD];
        sc = kscale;
        outp = &g_kh[((size_t)bt * NKV + (hd - NQ)) * HD];
    }

    float v = buf[h];
    float ss = v * v;
#pragma unroll
    for (int off = 16; off; off >>= 1) ss += __shfl_xor_sync(0xffffffffu, ss, off);
    __shared__ float red[4];
    if (lane == 0) red[wid] = ss;
    __syncthreads();
    float tot = red[0] + red[1] + red[2] + red[3];
    float xn = sc[h] * v * rsqrtf(tot * (1.0f / HD) + 1e-6f);

    __shared__ float row[HD];
    row[h] = xn;
    __syncthreads();

    int segv  = seg[bt];
    int first = g_first[b];
    float pos = (segv != 0) ? (float)(t - first) : 1073741824.0f;
    int k2 = (h < 64) ? h : (h - 64);
    float invf = exp2f((-2.0f * (float)k2 / 128.0f) * 19.931568569324174f);
    float ang = pos * invf;
    float s_ = sinf(ang), c_ = cosf(ang);

    float rr;
    if (h < 64) rr = xn * c_ - row[h + 64] * s_;
    else        rr = xn * c_ + row[h - 64] * s_;
    outp[h] = __float2half(rr * oscale);
}

// ============================================================
// 5) flash attention: BM=64 q x BN=64 k, 4 warps, fp16 mma
// ============================================================
#define FA_STRIDE 136
#define FA_TILE_B (64 * FA_STRIDE * 2)
#define FA_SMEM (5 * FA_TILE_B)

__global__ __launch_bounds__(128)
void fattn_kernel() {
    extern __shared__ char smem[];
    const uint32_t sb = smem_u32(smem);
    const uint32_t qbase = sb;
    const uint32_t kbase0 = sb + FA_TILE_B;
    const uint32_t vbase0 = sb + 2 * FA_TILE_B;

    const int tid  = threadIdx.x;
    const int wid  = tid >> 5;
    const int lane = tid & 31;
    const int g    = lane >> 2;
    const int r    = lane & 3;
    const int lrow = lane & 15;
    const int lk8  = (lane >> 4) * 8;
    const int b  = blockIdx.z;
    const int n  = blockIdx.y;
    const int kh = n >> 2;
    const int t0 = blockIdx.x * 64;

    {
        const __half* qsrc = g_qh + ((size_t)(b * T_ + t0) * NQ + n) * HD;
#pragma unroll
        for (int j = 0; j < 8; ++j) {
            int f = tid + 128 * j;
            int row = f >> 4, c = f & 15;
            CP_ASYNC16(qbase + row * 272 + c * 16,
                       qsrc + (size_t)row * (NQ * HD) + c * 8);
        }
    }
    CP_COMMIT();

    const int start = g_start[b];
    const int s_begin = start & ~63;
    const int ntiles = (t0 + 64 - s_begin) >> 6;

    auto load_kv = [&](int st, int s0) {
        uint32_t kb = kbase0 + st * 2 * FA_TILE_B;
        uint32_t vb = vbase0 + st * 2 * FA_TILE_B;
        const __half* ksrc = g_kh + ((size_t)(b * T_ + s0) * NKV + kh) * HD;
        const __half* vsrc = g_vh + ((size_t)(b * T_ + s0) * NKV + kh) * HD;
#pragma unroll
        for (int j = 0; j < 8; ++j) {
            int f = tid + 128 * j;
            int row = f >> 4, c = f & 15;
            CP_ASYNC16(kb + row * 272 + c * 16, ksrc + (size_t)row * (NKV * HD) + c * 8);
            CP_ASYNC16(vb + row * 272 + c * 16, vsrc + (size_t)row * (NKV * HD) + c * 8);
        }
    };

    if (ntiles > 0) load_kv(0, s_begin);
    CP_COMMIT();

    CP_WAIT1();
    __syncthreads();
    uint32_t qf[8][4];
#pragma unroll
    for (int kt = 0; kt < 8; ++kt) {
        uint32_t addr = qbase + (uint32_t)(wid * 16 + lrow) * 272 + (kt * 16 + lk8) * 2;
        LDSM4(qf[kt][0], qf[kt][1], qf[kt][2], qf[kt][3], addr);
    }

    const int tq0 = t0 + wid * 16 + g;
    const int tq1 = tq0 + 8;

    float m0 = NEG_INF, m1 = NEG_INF, l0 = 0.f, l1 = 0.f;
    float o[16][4];
#pragma unroll
    for (int i = 0; i < 16; ++i)
#pragma unroll
        for (int j = 0; j < 4; ++j) o[i][j] = 0.f;

    for (int it = 0; it < ntiles; ++it) {
        const int s0 = s_begin + it * 64;
        if (it + 1 < ntiles) load_kv((it + 1) & 1, s0 + 64);
        CP_COMMIT();
        CP_WAIT1();
        __syncthreads();

        const uint32_t kb = kbase0 + (it & 1) * 2 * FA_TILE_B;
        const uint32_t vb = vbase0 + (it & 1) * 2 * FA_TILE_B;

        // ---- S = Q @ K^T ----
        float sfr[8][4];
#pragma unroll
        for (int i = 0; i < 8; ++i)
#pragma unroll
            for (int j = 0; j < 4; ++j) sfr[i][j] = 0.f;

#pragma unroll
        for (int ks = 0; ks < 8; ++ks) {
            const int kcol = ks * 16 + lk8;
#pragma unroll
            for (int np = 0; np < 4; ++np) {
                uint32_t b0, b1, b2, b3;
                uint32_t addr = kb + (uint32_t)(np * 16 + lrow) * 272 + kcol * 2;
                LDSM4(b0, b1, b2, b3, addr);
                mma_f16(sfr[2 * np],     qf[ks][0], qf[ks][1], qf[ks][2], qf[ks][3], b0, b2);
                mma_f16(sfr[2 * np + 1], qf[ks][0], qf[ks][1], qf[ks][2], qf[ks][3], b1, b3);
            }
        }

        // ---- mask + online softmax ----
        float mx0 = NEG_INF, mx1 = NEG_INF;
#pragma unroll
        for (int nt = 0; nt < 8; ++nt) {
#pragma unroll
            for (int c = 0; c < 2; ++c) {
                int s = s0 + nt * 8 + 2 * r + c;
                bool vs = (s >= start);
                float v0 = (vs && s <= tq0) ? sfr[nt][c]     : NEG_INF;
                float v1 = (vs && s <= tq1) ? sfr[nt][2 + c] : NEG_INF;
                sfr[nt][c]     = v0;
                sfr[nt][2 + c] = v1;
                mx0 = fmaxf(mx0, v0);
                mx1 = fmaxf(mx1, v1);
            }
        }
        mx0 = fmaxf(mx0, __shfl_xor_sync(0xffffffffu, mx0, 1));
        mx0 = fmaxf(mx0, __shfl_xor_sync(0xffffffffu, mx0, 2));
        mx1 = fmaxf(mx1, __shfl_xor_sync(0xffffffffu, mx1, 1));
        mx1 = fmaxf(mx1, __shfl_xor_sync(0xffffffffu, mx1, 2));

        float mn0 = fmaxf(m0, mx0), mn1 = fmaxf(m1, mx1);
        float mu0 = (mn0 == NEG_INF) ? 0.f : mn0;
        float mu1 = (mn1 == NEG_INF) ? 0.f : mn1;
        float alpha0 = (m0 == NEG_INF) ? ((mn0 == NEG_INF) ? 1.f : 0.f) : __expf(m0 - mn0);
        float alpha1 = (m1 == NEG_INF) ? ((mn1 == NEG_INF) ? 1.f : 0.f) : __expf(m1 - mn1);
        m0 = mn0; m1 = mn1;

        float ps0 = 0.f, ps1 = 0.f;
#pragma unroll
        for (int nt = 0; nt < 8; ++nt) {
#pragma unroll
            for (int c = 0; c < 2; ++c) {
                float p0 = __expf(sfr[nt][c]     - mu0);
                float p1 = __expf(sfr[nt][2 + c] - mu1);
                sfr[nt][c]     = p0;
                sfr[nt][2 + c] = p1;
                ps0 += p0; ps1 += p1;
            }
        }
        ps0 += __shfl_xor_sync(0xffffffffu, ps0, 1);
        ps0 += __shfl_xor_sync(0xffffffffu, ps0, 2);
        ps1 += __shfl_xor_sync(0xffffffffu, ps1, 1);
        ps1 += __shfl_xor_sync(0xffffffffu, ps1, 2);
        l0 = l0 * alpha0 + ps0;
        l1 = l1 * alpha1 + ps1;

#pragma unroll
        for (int nt = 0; nt < 16; ++nt) {
            o[nt][0] *= alpha0; o[nt][1] *= alpha0;
            o[nt][2] *= alpha1; o[nt][3] *= alpha1;
        }

        // ---- O += P @ V ----
#pragma unroll
        for (int kt = 0; kt < 4; ++kt) {
            uint32_t a0 = h2_as_u32(__floats2half2_rn(sfr[2 * kt][0],     sfr[2 * kt][1]));
            uint32_t a1 = h2_as_u32(__floats2half2_rn(sfr[2 * kt][2],     sfr[2 * kt][3]));
            uint32_t a2 = h2_as_u32(__floats2half2_rn(sfr[2 * kt + 1][0], sfr[2 * kt + 1][1]));
            uint32_t a3 = h2_as_u32(__floats2half2_rn(sfr[2 * kt + 1][2], sfr[2 * kt + 1][3]));
            const int mrow = lane >> 3, mi = lane & 7;
            const int key = kt * 16 + (mrow & 1) * 8 + mi;
#pragma unroll
            for (int dp = 0; dp < 8; ++dp) {
                uint32_t v0, v1, v2, v3;
                uint32_t addr = vb + (uint32_t)key * 272 + (dp * 16 + (mrow >> 1) * 8) * 2;
                LDSM4T(v0, v1, v2, v3, addr);
                mma_f16(o[2 * dp],     a0, a1, a2, a3, v0, v1);
                mma_f16(o[2 * dp + 1], a0, a1, a2, a3, v2, v3);
            }
        }
        __syncthreads();
    }

    // ---- epilogue ----
    float inv0 = (l0 > 0.f) ? (1.0f / l0) : 0.f;
    float inv1 = (l1 > 0.f) ? (1.0f / l1) : 0.f;
    __half* o0 = g_oh + ((size_t)(b * T_ + tq0) * NQ + n) * HD;
    __half* o1 = g_oh + ((size_t)(b * T_ + tq1) * NQ + n) * HD;
#pragma unroll
    for (int nt = 0; nt < 16; ++nt) {
        int col = nt * 8 + 2 * r;
        *reinterpret_cast<__half2*>(o0 + col) =
            __floats2half2_rn(o[nt][0] * inv0, o[nt][1] * inv0);
        *reinterpret_cast<__half2*>(o1 + col) =
            __floats2half2_rn(o[nt][2] * inv1, o[nt][3] * inv1);
    }
}

// ============================================================
// launch
// ============================================================
extern "C" void kernel_launch(void* const* d_in, const int* in_sizes, int n_in,
                              void* d_out, int out_size) {
    const float* x       = (const float*)d_in[0];
    const float* wq      = (const float*)d_in[1];
    const float* wk      = (const float*)d_in[2];
    const float* wv      = (const float*)d_in[3];
    const float* wo      = (const float*)d_in[4];
    const float* q_scale = (const float*)d_in[5];
    const float* k_scale = (const float*)d_in[6];
    const int*   seg     = (const int*)d_in[9];
    float* out = (float*)d_out;

    float  *pqkv;
    __half *poh, *pxh, *pwqkvh, *pwoh;
    cudaGetSymbolAddress((void**)&pqkv, g_qkv);
    cudaGetSymbolAddress((void**)&poh, g_oh);
    cudaGetSymbolAddress((void**)&pxh, g_xh);
    cudaGetSymbolAddress((void**)&pwqkvh, g_wqkvh);
    cudaGetSymbolAddress((void**)&pwoh, g_woh);

    cudaFuncSetAttribute(gemm_f16_kernel, cudaFuncAttributeMaxDynamicSharedMemorySize,
                         GEMM_SMEM);
    cudaFuncSetAttribute(fattn_kernel, cudaFuncAttributeMaxDynamicSharedMemorySize,
                         FA_SMEM);

    startfirst_kernel<<<B_, 256>>>(seg);

    f32_to_f16_kernel<<<(MTOT * D_ / 4) / 256, 256>>>(
        (const float4*)x, (__half2*)pxh);
    transpose_f16_kernel<<<dim3(D_ / 32, D_ / 32), dim3(32, 8)>>>(
        wq, pwqkvh, D_, NQ * HD);
    transpose_f16_kernel<<<dim3(NKV * HD / 32, D_ / 32), dim3(32, 8)>>>(
        wk, pwqkvh + (size_t)K_OFF * D_, D_, NKV * HD);
    transpose_f16_kernel<<<dim3(NKV * HD / 32, D_ / 32), dim3(32, 8)>>>(
        wv, pwqkvh + (size_t)V_OFF * D_, D_, NKV * HD);

    // fused q/k/v projection: N=6144, K=4096, f32 out
    gemm_f16_kernel<<<dim3(QKV_N / 128, MTOT / 128), 256, GEMM_SMEM>>>(
        pxh, pwqkvh, pqkv, QKV_N, D_);

    ropenorm_kernel<<<dim3(MTOT, NQ + 2 * NKV), 128>>>(q_scale, k_scale, seg);

    fattn_kernel<<<dim3(T_ / 64, NQ, B_), 128, FA_SMEM>>>();

    transpose_f16_kernel<<<dim3(D_ / 32, NQ * HD / 32), dim3(32, 8)>>>(
        wo, pwoh, NQ * HD, D_);

    // output projection
    gemm_f16_kernel<<<dim3(D_ / 128, MTOT / 128), 256, GEMM_SMEM>>>(
        poh, pwoh, out, D_, NQ * HD);
}

// round 9
// speedup vs baseline: 7.3392x; 1.0840x over previous
#include <cuda_runtime.h>
#include <cuda_fp16.h>
#include <math.h>
#include <stdint.h>

// Problem constants
#define B_   2
#define T_   1024
#define D_   4096
#define NQ   32
#define NKV  8
#define HD   128
#define MTOT (B_ * T_)      // 2048
#define QKV_N 6144          // 4096 q + 1024 k + 1024 v
#define K_OFF 4096
#define V_OFF 5120

#define NEG_INF (-INFINITY)

// -------- scratch (device globals; allocation-free) --------
__device__ __align__(256) __half g_qh[(size_t)MTOT * NQ * HD];    // 16 MB (q fp16, pre-scaled)
__device__ __align__(256) __half g_kh[(size_t)MTOT * NKV * HD];   //  4 MB
__device__ __align__(256) __half g_vh[(size_t)MTOT * NKV * HD];   //  4 MB
__device__ __align__(256) __half g_oh[(size_t)MTOT * NQ * HD];    // 16 MB (attn out, f16)
__device__ __align__(256) __half g_xh[(size_t)MTOT * D_];         // 16 MB (x, f16)
__device__ __align__(256) __half g_wqkvh[(size_t)QKV_N * D_];     // 48 MB ([n][k])
__device__ __align__(256) __half g_woh[(size_t)D_ * NQ * HD];     // 32 MB ([d][nh])
__device__ int g_start[B_];
__device__ int g_first[B_];

// ============================================================
// helpers
// ============================================================
__device__ __forceinline__ uint32_t smem_u32(const void* p) {
    uint32_t a;
    asm("{ .reg .u64 t; cvta.to.shared.u64 t, %1; cvt.u32.u64 %0, t; }" : "=r"(a) : "l"(p));
    return a;
}
__device__ __forceinline__ uint32_t h2_as_u32(__half2 h) {
    return *reinterpret_cast<uint32_t*>(&h);
}

#define CP_ASYNC16(saddr, gptr) \
    asm volatile("cp.async.cg.shared.global [%0], [%1], 16;" :: "r"(saddr), "l"(gptr) : "memory")
#define CP_COMMIT() asm volatile("cp.async.commit_group;" ::: "memory")
#define CP_WAIT1()  asm volatile("cp.async.wait_group 1;" ::: "memory")
#define CP_WAIT0()  asm volatile("cp.async.wait_group 0;" ::: "memory")

#define LDSM4(r0, r1, r2, r3, addr) \
    asm volatile("ldmatrix.sync.aligned.m8n8.x4.shared.b16 {%0,%1,%2,%3}, [%4];" \
        : "=r"(r0), "=r"(r1), "=r"(r2), "=r"(r3) : "r"(addr))
#define LDSM4T(r0, r1, r2, r3, addr) \
    asm volatile("ldmatrix.sync.aligned.m8n8.x4.trans.shared.b16 {%0,%1,%2,%3}, [%4];" \
        : "=r"(r0), "=r"(r1), "=r"(r2), "=r"(r3) : "r"(addr))

__device__ __forceinline__ void mma_f16(float c[4],
                                        uint32_t a0, uint32_t a1, uint32_t a2, uint32_t a3,
                                        uint32_t b0, uint32_t b1) {
    asm volatile(
        "mma.sync.aligned.m16n8k16.row.col.f32.f16.f16.f32 "
        "{%0,%1,%2,%3}, {%4,%5,%6,%7}, {%8,%9}, {%0,%1,%2,%3};"
        : "+f"(c[0]), "+f"(c[1]), "+f"(c[2]), "+f"(c[3])
        : "r"(a0), "r"(a1), "r"(a2), "r"(a3), "r"(b0), "r"(b1));
}

// ============================================================
// 1) segment scan
// ============================================================
__global__ void startfirst_kernel(const int* __restrict__ seg) {
    int b = blockIdx.x;
    const int* s = seg + (size_t)b * T_;
    __shared__ int sh_min, sh_max, sh_first;
    if (threadIdx.x == 0) { sh_min = T_; sh_max = INT_MIN; sh_first = T_; }
    __syncthreads();
    int lmin = T_, lmax = INT_MIN;
    for (int t = threadIdx.x; t < T_; t += blockDim.x) {
        int v = s[t];
        if (v != 0 && t < lmin) lmin = t;
        if (v > lmax) lmax = v;
    }
    atomicMin(&sh_min, lmin);
    atomicMax(&sh_max, lmax);
    __syncthreads();
    int mx = sh_max;
    int lfirst = T_;
    for (int t = threadIdx.x; t < T_; t += blockDim.x)
        if (s[t] == mx && t < lfirst) lfirst = t;
    atomicMin(&sh_first, lfirst);
    __syncthreads();
    if (threadIdx.x == 0) { g_start[b] = sh_min; g_first[b] = sh_first; }
}

// ============================================================
// 2) conversions
// ============================================================
__global__ void f32_to_f16_kernel(const float4* __restrict__ src, __half2* __restrict__ dst) {
    int i = blockIdx.x * blockDim.x + threadIdx.x;
    float4 v = src[i];
    dst[2 * i]     = __floats2half2_rn(v.x, v.y);
    dst[2 * i + 1] = __floats2half2_rn(v.z, v.w);
}

// transpose f32 [R][C] -> f16 [C][R]
__global__ void transpose_f16_kernel(const float* __restrict__ in, __half* __restrict__ out,
                                     int R, int C) {
    __shared__ float tile[32][33];
    int x  = blockIdx.x * 32 + threadIdx.x;
    int y0 = blockIdx.y * 32;
#pragma unroll
    for (int j = threadIdx.y; j < 32; j += 8)
        tile[j][threadIdx.x] = in[(size_t)(y0 + j) * C + x];
    __syncthreads();
    int ox  = y0 + threadIdx.x;
    int oy0 = blockIdx.x * 32;
#pragma unroll
    for (int j = threadIdx.y; j < 32; j += 8)
        out[(size_t)(oy0 + j) * R + ox] = __float2half(tile[threadIdx.x][j]);
}

// ============================================================
// 3) fp16 mma.sync GEMM, BK=64, 3-stage cp.async
//    FUSE=true: QKV epilogue (RMSNorm + RoPE + fp16 store to g_qh/g_kh/g_vh)
//    FUSE=false: plain f32 store to C
// ============================================================
#define H_STRIDE 72                           // halves per smem row (144 B)
#define TILE_BYTES (128 * H_STRIDE * 2)       // 18432
#define STAGE_BYTES (2 * TILE_BYTES)          // 36864
#define GSTAGES 3
#define GEMM_SMEM (GSTAGES * STAGE_BYTES)     // 110592

template <bool FUSE>
__global__ __launch_bounds__(256, 2)
void gemm_f16_kernel(const __half* __restrict__ A, const __half* __restrict__ Bt,
                     float* __restrict__ C, int N, int K,
                     const float* __restrict__ qscale, const float* __restrict__ kscale,
                     const int* __restrict__ seg) {
    extern __shared__ char smem[];
    const uint32_t sb = smem_u32(smem);
    const int tid  = threadIdx.x;
    const int wid  = tid >> 5;
    const int lane = tid & 31;
    const int g    = lane >> 2;
    const int r    = lane & 3;
    const int row0 = blockIdx.y * 128;
    const int col0 = blockIdx.x * 128;
    const int wm   = (wid >> 2) * 64;
    const int wn   = (wid & 3) * 32;
    const int lrow = lane & 15;
    const int lk8  = (lane >> 4) * 8;

    float acc[4][4][4];
#pragma unroll
    for (int a = 0; a < 4; ++a)
#pragma unroll
        for (int b = 0; b < 4; ++b)
#pragma unroll
            for (int c = 0; c < 4; ++c) acc[a][b][c] = 0.f;

    const int KS = K >> 6;   // BK = 64

    auto load_stage = [&](int st, int k0) {
        uint32_t abase = sb + st * STAGE_BYTES;
        uint32_t bbase = abase + TILE_BYTES;
#pragma unroll
        for (int j = 0; j < 4; ++j) {
            int f  = tid + 256 * j;     // 0..1023
            int rr = f >> 3, cc = f & 7;
            CP_ASYNC16(abase + rr * 144 + cc * 16,
                       A + (size_t)(row0 + rr) * K + k0 + cc * 8);
            CP_ASYNC16(bbase + rr * 144 + cc * 16,
                       Bt + (size_t)(col0 + rr) * K + k0 + cc * 8);
        }
    };

    auto compute_stage = [&](int st) {
        uint32_t abase = sb + st * STAGE_BYTES;
        uint32_t bbase = abase + TILE_BYTES;
#pragma unroll
        for (int ks = 0; ks < 4; ++ks) {
            const int kb = ks * 16 + lk8;
            uint32_t br[2][4];
#pragma unroll
            for (int ntp = 0; ntp < 2; ++ntp) {
                uint32_t addr = bbase + (uint32_t)(wn + ntp * 16 + lrow) * 144 + kb * 2;
                LDSM4(br[ntp][0], br[ntp][1], br[ntp][2], br[ntp][3], addr);
            }
#pragma unroll
            for (int mt = 0; mt < 4; ++mt) {
                uint32_t a0, a1, a2, a3;
                uint32_t addr = abase + (uint32_t)(wm + mt * 16 + lrow) * 144 + kb * 2;
                LDSM4(a0, a1, a2, a3, addr);
                mma_f16(acc[mt][0], a0, a1, a2, a3, br[0][0], br[0][2]);
                mma_f16(acc[mt][1], a0, a1, a2, a3, br[0][1], br[0][3]);
                mma_f16(acc[mt][2], a0, a1, a2, a3, br[1][0], br[1][2]);
                mma_f16(acc[mt][3], a0, a1, a2, a3, br[1][1], br[1][3]);
            }
        }
    };

    load_stage(0, 0);   CP_COMMIT();
    load_stage(1, 64);  CP_COMMIT();

    for (int i = 0; i < KS; ++i) {
        CP_WAIT1();
        __syncthreads();
        if (i + 2 < KS) load_stage((i + 2) % 3, (i + 2) << 6);
        CP_COMMIT();
        compute_stage(i % 3);
    }

    if (!FUSE) {
#pragma unroll
        for (int mt = 0; mt < 4; ++mt) {
            int mrow = row0 + wm + mt * 16;
#pragma unroll
            for (int nt = 0; nt < 4; ++nt) {
                int ncol = col0 + wn + nt * 8 + 2 * r;
                *reinterpret_cast<float2*>(&C[(size_t)(mrow + g) * N + ncol]) =
                    make_float2(acc[mt][nt][0], acc[mt][nt][1]);
                *reinterpret_cast<float2*>(&C[(size_t)(mrow + g + 8) * N + ncol]) =
                    make_float2(acc[mt][nt][2], acc[mt][nt][3]);
            }
        }
        return;
    }

    // ---- fused QKV epilogue: stage f32 acc to smem, then norm/rope/convert ----
    CP_WAIT0();
    __syncthreads();     // all pending cp.async done; smem free for staging
    float* S = reinterpret_cast<float*>(smem);   // 128 x 130 floats
#pragma unroll
    for (int mt = 0; mt < 4; ++mt) {
        int mr = wm + mt * 16 + g;
#pragma unroll
        for (int nt = 0; nt < 4; ++nt) {
            int nc = wn + nt * 8 + 2 * r;
            S[mr * 130 + nc]       = acc[mt][nt][0];
            S[mr * 130 + nc + 1]   = acc[mt][nt][1];
            S[(mr + 8) * 130 + nc]     = acc[mt][nt][2];
            S[(mr + 8) * 130 + nc + 1] = acc[mt][nt][3];
        }
    }
    __syncthreads();

    const int head = blockIdx.x;       // 0..47
    const int row  = tid >> 1;         // 0..127
    const int hsel = tid & 1;          // half: 0 -> cols 0..63, 1 -> cols 64..127
    const int bt   = row0 + row;
    const int b    = bt >> 10;
    const int t    = bt & (T_ - 1);
    const float* v = S + row * 130;

    if (head >= 40) {                  // V head: plain fp16 convert
        __half* dst = g_vh + ((size_t)bt * NKV + (head - 40)) * HD + hsel * 64;
#pragma unroll
        for (int c2 = 0; c2 < 64; c2 += 2)
            *reinterpret_cast<__half2*>(dst + c2) =
                __floats2half2_rn(v[hsel * 64 + c2], v[hsel * 64 + c2 + 1]);
        return;
    }

    // RMSNorm
    float ss = 0.f;
#pragma unroll
    for (int c2 = 0; c2 < 64; ++c2) {
        float x = v[hsel * 64 + c2];
        ss += x * x;
    }
    float tot  = ss + __shfl_xor_sync(0xffffffffu, ss, 1);
    float rinv = rsqrtf(tot * (1.0f / HD) + 1e-6f);

    int   segv  = seg[bt];
    int   first = g_first[b];
    float pos   = (segv != 0) ? (float)(t - first) : 1073741824.0f;

    const float* sc = (head < NQ) ? qscale : kscale;
    const float  oscale = (head < NQ) ? 0.08838834764831845f : 1.0f;
    __half* dst = (head < NQ)
        ? g_qh + ((size_t)bt * NQ + head) * HD
        : g_kh + ((size_t)bt * NKV + (head - NQ)) * HD;

#pragma unroll 8
    for (int c2 = 0; c2 < 64; c2 += 2) {
        float out[2];
#pragma unroll
        for (int u = 0; u < 2; ++u) {
            int c  = hsel * 64 + c2 + u;
            int k2 = c & 63;
            float invf = exp2f((-2.0f * (float)k2 / 128.0f) * 19.931568569324174f);
            float ang  = pos * invf;
            float s_ = sinf(ang), c_ = cosf(ang);
            float n_c = sc[c] * v[c] * rinv;
            float n_p = sc[c ^ 64] * v[c ^ 64] * rinv;
            out[u] = (hsel == 0) ? (n_c * c_ - n_p * s_) : (n_c * c_ + n_p * s_);
            out[u] *= oscale;
        }
        *reinterpret_cast<__half2*>(dst + hsel * 64 + c2) =
            __floats2half2_rn(out[0], out[1]);
    }
}

// ============================================================
// 4) flash attention: BM=64 q x BN=64 k, 4 warps, fp16 mma (as R8)
// ============================================================
#define FA_STRIDE 136
#define FA_TILE_B (64 * FA_STRIDE * 2)
#define FA_SMEM (5 * FA_TILE_B)

__global__ __launch_bounds__(128)
void fattn_kernel() {
    extern __shared__ char smem[];
    const uint32_t sb = smem_u32(smem);
    const uint32_t qbase = sb;
    const uint32_t kbase0 = sb + FA_TILE_B;
    const uint32_t vbase0 = sb + 2 * FA_TILE_B;

    const int tid  = threadIdx.x;
    const int wid  = tid >> 5;
    const int lane = tid & 31;
    const int g    = lane >> 2;
    const int r    = lane & 3;
    const int lrow = lane & 15;
    const int lk8  = (lane >> 4) * 8;
    const int b  = blockIdx.z;
    const int n  = blockIdx.y;
    const int kh = n >> 2;
    const int t0 = blockIdx.x * 64;

    {
        const __half* qsrc = g_qh + ((size_t)(b * T_ + t0) * NQ + n) * HD;
#pragma unroll
        for (int j = 0; j < 8; ++j) {
            int f = tid + 128 * j;
            int row = f >> 4, c = f & 15;
            CP_ASYNC16(qbase + row * 272 + c * 16,
                       qsrc + (size_t)row * (NQ * HD) + c * 8);
        }
    }
    CP_COMMIT();

    const int start = g_start[b];
    const int s_begin = start & ~63;
    const int ntiles = (t0 + 64 - s_begin) >> 6;

    auto load_kv = [&](int st, int s0) {
        uint32_t kb = kbase0 + st * 2 * FA_TILE_B;
        uint32_t vb = vbase0 + st * 2 * FA_TILE_B;
        const __half* ksrc = g_kh + ((size_t)(b * T_ + s0) * NKV + kh) * HD;
        const __half* vsrc = g_vh + ((size_t)(b * T_ + s0) * NKV + kh) * HD;
#pragma unroll
        for (int j = 0; j < 8; ++j) {
            int f = tid + 128 * j;
            int row = f >> 4, c = f & 15;
            CP_ASYNC16(kb + row * 272 + c * 16, ksrc + (size_t)row * (NKV * HD) + c * 8);
            CP_ASYNC16(vb + row * 272 + c * 16, vsrc + (size_t)row * (NKV * HD) + c * 8);
        }
    };

    if (ntiles > 0) load_kv(0, s_begin);
    CP_COMMIT();

    CP_WAIT1();
    __syncthreads();
    uint32_t qf[8][4];
#pragma unroll
    for (int kt = 0; kt < 8; ++kt) {
        uint32_t addr = qbase + (uint32_t)(wid * 16 + lrow) * 272 + (kt * 16 + lk8) * 2;
        LDSM4(qf[kt][0], qf[kt][1], qf[kt][2], qf[kt][3], addr);
    }

    const int tq0 = t0 + wid * 16 + g;
    const int tq1 = tq0 + 8;

    float m0 = NEG_INF, m1 = NEG_INF, l0 = 0.f, l1 = 0.f;
    float o[16][4];
#pragma unroll
    for (int i = 0; i < 16; ++i)
#pragma unroll
        for (int j = 0; j < 4; ++j) o[i][j] = 0.f;

    for (int it = 0; it < ntiles; ++it) {
        const int s0 = s_begin + it * 64;
        if (it + 1 < ntiles) load_kv((it + 1) & 1, s0 + 64);
        CP_COMMIT();
        CP_WAIT1();
        __syncthreads();

        const uint32_t kb = kbase0 + (it & 1) * 2 * FA_TILE_B;
        const uint32_t vb = vbase0 + (it & 1) * 2 * FA_TILE_B;

        float sfr[8][4];
#pragma unroll
        for (int i = 0; i < 8; ++i)
#pragma unroll
            for (int j = 0; j < 4; ++j) sfr[i][j] = 0.f;

#pragma unroll
        for (int ks = 0; ks < 8; ++ks) {
            const int kcol = ks * 16 + lk8;
#pragma unroll
            for (int np = 0; np < 4; ++np) {
                uint32_t b0, b1, b2, b3;
                uint32_t addr = kb + (uint32_t)(np * 16 + lrow) * 272 + kcol * 2;
                LDSM4(b0, b1, b2, b3, addr);
                mma_f16(sfr[2 * np],     qf[ks][0], qf[ks][1], qf[ks][2], qf[ks][3], b0, b2);
                mma_f16(sfr[2 * np + 1], qf[ks][0], qf[ks][1], qf[ks][2], qf[ks][3], b1, b3);
            }
        }

        float mx0 = NEG_INF, mx1 = NEG_INF;
#pragma unroll
        for (int nt = 0; nt < 8; ++nt) {
#pragma unroll
            for (int c = 0; c < 2; ++c) {
                int s = s0 + nt * 8 + 2 * r + c;
                bool vs = (s >= start);
                float v0 = (vs && s <= tq0) ? sfr[nt][c]     : NEG_INF;
                float v1 = (vs && s <= tq1) ? sfr[nt][2 + c] : NEG_INF;
                sfr[nt][c]     = v0;
                sfr[nt][2 + c] = v1;
                mx0 = fmaxf(mx0, v0);
                mx1 = fmaxf(mx1, v1);
            }
        }
        mx0 = fmaxf(mx0, __shfl_xor_sync(0xffffffffu, mx0, 1));
        mx0 = fmaxf(mx0, __shfl_xor_sync(0xffffffffu, mx0, 2));
        mx1 = fmaxf(mx1, __shfl_xor_sync(0xffffffffu, mx1, 1));
        mx1 = fmaxf(mx1, __shfl_xor_sync(0xffffffffu, mx1, 2));

        float mn0 = fmaxf(m0, mx0), mn1 = fmaxf(m1, mx1);
        float mu0 = (mn0 == NEG_INF) ? 0.f : mn0;
        float mu1 = (mn1 == NEG_INF) ? 0.f : mn1;
        float alpha0 = (m0 == NEG_INF) ? ((mn0 == NEG_INF) ? 1.f : 0.f) : __expf(m0 - mn0);
        float alpha1 = (m1 == NEG_INF) ? ((mn1 == NEG_INF) ? 1.f : 0.f) : __expf(m1 - mn1);
        m0 = mn0; m1 = mn1;

        float ps0 = 0.f, ps1 = 0.f;
#pragma unroll
        for (int nt = 0; nt < 8; ++nt) {
#pragma unroll
            for (int c = 0; c < 2; ++c) {
                float p0 = __expf(sfr[nt][c]     - mu0);
                float p1 = __expf(sfr[nt][2 + c] - mu1);
                sfr[nt][c]     = p0;
                sfr[nt][2 + c] = p1;
                ps0 += p0; ps1 += p1;
            }
        }
        ps0 += __shfl_xor_sync(0xffffffffu, ps0, 1);
        ps0 += __shfl_xor_sync(0xffffffffu, ps0, 2);
        ps1 += __shfl_xor_sync(0xffffffffu, ps1, 1);
        ps1 += __shfl_xor_sync(0xffffffffu, ps1, 2);
        l0 = l0 * alpha0 + ps0;
        l1 = l1 * alpha1 + ps1;

#pragma unroll
        for (int nt = 0; nt < 16; ++nt) {
            o[nt][0] *= alpha0; o[nt][1] *= alpha0;
            o[nt][2] *= alpha1; o[nt][3] *= alpha1;
        }

#pragma unroll
        for (int kt = 0; kt < 4; ++kt) {
            uint32_t a0 = h2_as_u32(__floats2half2_rn(sfr[2 * kt][0],     sfr[2 * kt][1]));
            uint32_t a1 = h2_as_u32(__floats2half2_rn(sfr[2 * kt][2],     sfr[2 * kt][3]));
            uint32_t a2 = h2_as_u32(__floats2half2_rn(sfr[2 * kt + 1][0], sfr[2 * kt + 1][1]));
            uint32_t a3 = h2_as_u32(__floats2half2_rn(sfr[2 * kt + 1][2], sfr[2 * kt + 1][3]));
            const int mrow = lane >> 3, mi = lane & 7;
            const int key = kt * 16 + (mrow & 1) * 8 + mi;
#pragma unroll
            for (int dp = 0; dp < 8; ++dp) {
                uint32_t v0, v1, v2, v3;
                uint32_t addr = vb + (uint32_t)key * 272 + (dp * 16 + (mrow >> 1) * 8) * 2;
                LDSM4T(v0, v1, v2, v3, addr);
                mma_f16(o[2 * dp],     a0, a1, a2, a3, v0, v1);
                mma_f16(o[2 * dp + 1], a0, a1, a2, a3, v2, v3);
            }
        }
        __syncthreads();
    }

    float inv0 = (l0 > 0.f) ? (1.0f / l0) : 0.f;
    float inv1 = (l1 > 0.f) ? (1.0f / l1) : 0.f;
    __half* o0 = g_oh + ((size_t)(b * T_ + tq0) * NQ + n) * HD;
    __half* o1 = g_oh + ((size_t)(b * T_ + tq1) * NQ + n) * HD;
#pragma unroll
    for (int nt = 0; nt < 16; ++nt) {
        int col = nt * 8 + 2 * r;
        *reinterpret_cast<__half2*>(o0 + col) =
            __floats2half2_rn(o[nt][0] * inv0, o[nt][1] * inv0);
        *reinterpret_cast<__half2*>(o1 + col) =
            __floats2half2_rn(o[nt][2] * inv1, o[nt][3] * inv1);
    }
}

// ============================================================
// launch
// ============================================================
extern "C" void kernel_launch(void* const* d_in, const int* in_sizes, int n_in,
                              void* d_out, int out_size) {
    const float* x       = (const float*)d_in[0];
    const float* wq      = (const float*)d_in[1];
    const float* wk      = (const float*)d_in[2];
    const float* wv      = (const float*)d_in[3];
    const float* wo      = (const float*)d_in[4];
    const float* q_scale = (const float*)d_in[5];
    const float* k_scale = (const float*)d_in[6];
    const int*   seg     = (const int*)d_in[9];
    float* out = (float*)d_out;

    __half *pxh, *pwqkvh, *pwoh, *poh;
    cudaGetSymbolAddress((void**)&pxh, g_xh);
    cudaGetSymbolAddress((void**)&pwqkvh, g_wqkvh);
    cudaGetSymbolAddress((void**)&pwoh, g_woh);
    cudaGetSymbolAddress((void**)&poh, g_oh);

    cudaFuncSetAttribute(gemm_f16_kernel<true>, cudaFuncAttributeMaxDynamicSharedMemorySize,
                         GEMM_SMEM);
    cudaFuncSetAttribute(gemm_f16_kernel<false>, cudaFuncAttributeMaxDynamicSharedMemorySize,
                         GEMM_SMEM);
    cudaFuncSetAttribute(fattn_kernel, cudaFuncAttributeMaxDynamicSharedMemorySize,
                         FA_SMEM);

    startfirst_kernel<<<B_, 256>>>(seg);

    f32_to_f16_kernel<<<(MTOT * D_ / 4) / 256, 256>>>(
        (const float4*)x, (__half2*)pxh);
    transpose_f16_kernel<<<dim3(D_ / 32, D_ / 32), dim3(32, 8)>>>(
        wq, pwqkvh, D_, NQ * HD);
    transpose_f16_kernel<<<dim3(NKV * HD / 32, D_ / 32), dim3(32, 8)>>>(
        wk, pwqkvh + (size_t)K_OFF * D_, D_, NKV * HD);
    transpose_f16_kernel<<<dim3(NKV * HD / 32, D_ / 32), dim3(32, 8)>>>(
        wv, pwqkvh + (size_t)V_OFF * D_, D_, NKV * HD);
    transpose_f16_kernel<<<dim3(D_ / 32, NQ * HD / 32), dim3(32, 8)>>>(
        wo, pwoh, NQ * HD, D_);

    // fused QKV projection + RMSNorm + RoPE + fp16 convert
    gemm_f16_kernel<true><<<dim3(QKV_N / 128, MTOT / 128), 256, GEMM_SMEM>>>(
        pxh, pwqkvh, nullptr, QKV_N, D_, q_scale, k_scale, seg);

    fattn_kernel<<<dim3(T_ / 64, NQ, B_), 128, FA_SMEM>>>();

    // output projection
    gemm_f16_kernel<false><<<dim3(D_ / 128, MTOT / 128), 256, GEMM_SMEM>>>(
        poh, pwoh, out, D_, NQ * HD, nullptr, nullptr, nullptr);
}

// round 10
// speedup vs baseline: 7.3908x; 1.0070x over previous
#include <cuda_runtime.h>
#include <cuda_fp16.h>
#include <math.h>
#include <stdint.h>

// Problem constants
#define B_   2
#define T_   1024
#define D_   4096
#define NQ   32
#define NKV  8
#define HD   128
#define MTOT (B_ * T_)      // 2048
#define QKV_N 6144          // 4096 q + 1024 k + 1024 v
#define K_OFF 4096
#define V_OFF 5120

#define NEG_INF (-INFINITY)

// -------- scratch (device globals; allocation-free) --------
__device__ __align__(256) __half g_qh[(size_t)MTOT * NQ * HD];    // 16 MB
__device__ __align__(256) __half g_kh[(size_t)MTOT * NKV * HD];   //  4 MB
__device__ __align__(256) __half g_vh[(size_t)MTOT * NKV * HD];   //  4 MB
__device__ __align__(256) __half g_oh[(size_t)MTOT * NQ * HD];    // 16 MB
__device__ __align__(256) __half g_xh[(size_t)MTOT * D_];         // 16 MB
__device__ __align__(256) __half g_wqkvh[(size_t)QKV_N * D_];     // 48 MB ([n][k])
__device__ __align__(256) __half g_woh[(size_t)D_ * NQ * HD];     // 32 MB ([d][nh])
__device__ int g_start[B_];
__device__ int g_first[B_];

// ============================================================
// helpers
// ============================================================
__device__ __forceinline__ uint32_t smem_u32(const void* p) {
    uint32_t a;
    asm("{ .reg .u64 t; cvta.to.shared.u64 t, %1; cvt.u32.u64 %0, t; }" : "=r"(a) : "l"(p));
    return a;
}
__device__ __forceinline__ uint32_t h2_as_u32(__half2 h) {
    return *reinterpret_cast<uint32_t*>(&h);
}

#define CP_ASYNC16(saddr, gptr) \
    asm volatile("cp.async.cg.shared.global [%0], [%1], 16;" :: "r"(saddr), "l"(gptr) : "memory")
#define CP_COMMIT() asm volatile("cp.async.commit_group;" ::: "memory")
#define CP_WAIT1()  asm volatile("cp.async.wait_group 1;" ::: "memory")
#define CP_WAIT0()  asm volatile("cp.async.wait_group 0;" ::: "memory")

#define LDSM4(r0, r1, r2, r3, addr) \
    asm volatile("ldmatrix.sync.aligned.m8n8.x4.shared.b16 {%0,%1,%2,%3}, [%4];" \
        : "=r"(r0), "=r"(r1), "=r"(r2), "=r"(r3) : "r"(addr))
#define LDSM4T(r0, r1, r2, r3, addr) \
    asm volatile("ldmatrix.sync.aligned.m8n8.x4.trans.shared.b16 {%0,%1,%2,%3}, [%4];" \
        : "=r"(r0), "=r"(r1), "=r"(r2), "=r"(r3) : "r"(addr))

__device__ __forceinline__ void mma_f16(float c[4],
                                        uint32_t a0, uint32_t a1, uint32_t a2, uint32_t a3,
                                        uint32_t b0, uint32_t b1) {
    asm volatile(
        "mma.sync.aligned.m16n8k16.row.col.f32.f16.f16.f32 "
        "{%0,%1,%2,%3}, {%4,%5,%6,%7}, {%8,%9}, {%0,%1,%2,%3};"
        : "+f"(c[0]), "+f"(c[1]), "+f"(c[2]), "+f"(c[3])
        : "r"(a0), "r"(a1), "r"(a2), "r"(a3), "r"(b0), "r"(b1));
}

// ============================================================
// 1) segment scan
// ============================================================
__global__ void startfirst_kernel(const int* __restrict__ seg) {
    int b = blockIdx.x;
    const int* s = seg + (size_t)b * T_;
    __shared__ int sh_min, sh_max, sh_first;
    if (threadIdx.x == 0) { sh_min = T_; sh_max = INT_MIN; sh_first = T_; }
    __syncthreads();
    int lmin = T_, lmax = INT_MIN;
    for (int t = threadIdx.x; t < T_; t += blockDim.x) {
        int v = s[t];
        if (v != 0 && t < lmin) lmin = t;
        if (v > lmax) lmax = v;
    }
    atomicMin(&sh_min, lmin);
    atomicMax(&sh_max, lmax);
    __syncthreads();
    int mx = sh_max;
    int lfirst = T_;
    for (int t = threadIdx.x; t < T_; t += blockDim.x)
        if (s[t] == mx && t < lfirst) lfirst = t;
    atomicMin(&sh_first, lfirst);
    __syncthreads();
    if (threadIdx.x == 0) { g_start[b] = sh_min; g_first[b] = sh_first; }
}

// ============================================================
// 2) conversions
// ============================================================
__global__ void f32_to_f16_kernel(const float4* __restrict__ src, __half2* __restrict__ dst) {
    int i = blockIdx.x * blockDim.x + threadIdx.x;
    float4 v = src[i];
    dst[2 * i]     = __floats2half2_rn(v.x, v.y);
    dst[2 * i + 1] = __floats2half2_rn(v.z, v.w);
}

// transpose f32 [R][C] -> f16 [C][R]
__global__ void transpose_f16_kernel(const float* __restrict__ in, __half* __restrict__ out,
                                     int R, int C) {
    __shared__ float tile[32][33];
    int x  = blockIdx.x * 32 + threadIdx.x;
    int y0 = blockIdx.y * 32;
#pragma unroll
    for (int j = threadIdx.y; j < 32; j += 8)
        tile[j][threadIdx.x] = in[(size_t)(y0 + j) * C + x];
    __syncthreads();
    int ox  = y0 + threadIdx.x;
    int oy0 = blockIdx.x * 32;
#pragma unroll
    for (int j = threadIdx.y; j < 32; j += 8)
        out[(size_t)(oy0 + j) * R + ox] = __float2half(tile[threadIdx.x][j]);
}

// ============================================================
// 3) fp16 mma.sync GEMM: BM=BN=128, BK=64, 4 warps (2x2), warp tile 64x64,
//    3-stage cp.async. FUSE=true: QKV epilogue (RMSNorm+RoPE+fp16)
// ============================================================
#define H_STRIDE 72                           // halves per smem row (144 B)
#define TILE_BYTES (128 * H_STRIDE * 2)       // 18432
#define STAGE_BYTES (2 * TILE_BYTES)          // 36864
#define GSTAGES 3
#define GEMM_SMEM (GSTAGES * STAGE_BYTES)     // 110592

template <bool FUSE>
__global__ __launch_bounds__(128, 2)
void gemm_f16_kernel(const __half* __restrict__ A, const __half* __restrict__ Bt,
                     float* __restrict__ C, int N, int K,
                     const float* __restrict__ qscale, const float* __restrict__ kscale,
                     const int* __restrict__ seg) {
    extern __shared__ char smem[];
    const uint32_t sb = smem_u32(smem);
    const int tid  = threadIdx.x;
    const int wid  = tid >> 5;
    const int lane = tid & 31;
    const int g    = lane >> 2;
    const int r    = lane & 3;
    const int row0 = blockIdx.y * 128;
    const int col0 = blockIdx.x * 128;
    const int wm   = (wid >> 1) * 64;    // 0 / 64
    const int wn   = (wid & 1) * 64;     // 0 / 64
    const int lrow = lane & 15;
    const int lk8  = (lane >> 4) * 8;

    float acc[4][8][4];
#pragma unroll
    for (int a = 0; a < 4; ++a)
#pragma unroll
        for (int b = 0; b < 8; ++b)
#pragma unroll
            for (int c = 0; c < 4; ++c) acc[a][b][c] = 0.f;

    const int KS = K >> 6;   // BK = 64

    auto load_stage = [&](int st, int k0) {
        uint32_t abase = sb + st * STAGE_BYTES;
        uint32_t bbase = abase + TILE_BYTES;
#pragma unroll
        for (int j = 0; j < 8; ++j) {
            int f  = tid + 128 * j;     // 0..1023
            int rr = f >> 3, cc = f & 7;
            CP_ASYNC16(abase + rr * 144 + cc * 16,
                       A + (size_t)(row0 + rr) * K + k0 + cc * 8);
            CP_ASYNC16(bbase + rr * 144 + cc * 16,
                       Bt + (size_t)(col0 + rr) * K + k0 + cc * 8);
        }
    };

    auto compute_stage = [&](int st) {
        uint32_t abase = sb + st * STAGE_BYTES;
        uint32_t bbase = abase + TILE_BYTES;
#pragma unroll
        for (int ks = 0; ks < 4; ++ks) {
            const int kb = ks * 16 + lk8;
            uint32_t br[4][4];
#pragma unroll
            for (int ntp = 0; ntp < 4; ++ntp) {
                uint32_t addr = bbase + (uint32_t)(wn + ntp * 16 + lrow) * 144 + kb * 2;
                LDSM4(br[ntp][0], br[ntp][1], br[ntp][2], br[ntp][3], addr);
            }
#pragma unroll
            for (int mt = 0; mt < 4; ++mt) {
                uint32_t a0, a1, a2, a3;
                uint32_t addr = abase + (uint32_t)(wm + mt * 16 + lrow) * 144 + kb * 2;
                LDSM4(a0, a1, a2, a3, addr);
#pragma unroll
                for (int ntp = 0; ntp < 4; ++ntp) {
                    mma_f16(acc[mt][2 * ntp],     a0, a1, a2, a3, br[ntp][0], br[ntp][2]);
                    mma_f16(acc[mt][2 * ntp + 1], a0, a1, a2, a3, br[ntp][1], br[ntp][3]);
                }
            }
        }
    };

    load_stage(0, 0);   CP_COMMIT();
    load_stage(1, 64);  CP_COMMIT();

    for (int i = 0; i < KS; ++i) {
        CP_WAIT1();
        __syncthreads();
        if (i + 2 < KS) load_stage((i + 2) % 3, (i + 2) << 6);
        CP_COMMIT();
        compute_stage(i % 3);
    }

    if (!FUSE) {
#pragma unroll
        for (int mt = 0; mt < 4; ++mt) {
            int mrow = row0 + wm + mt * 16;
#pragma unroll
            for (int nt = 0; nt < 8; ++nt) {
                int ncol = col0 + wn + nt * 8 + 2 * r;
                *reinterpret_cast<float2*>(&C[(size_t)(mrow + g) * N + ncol]) =
                    make_float2(acc[mt][nt][0], acc[mt][nt][1]);
                *reinterpret_cast<float2*>(&C[(size_t)(mrow + g + 8) * N + ncol]) =
                    make_float2(acc[mt][nt][2], acc[mt][nt][3]);
            }
        }
        return;
    }

    // ---- fused QKV epilogue ----
    CP_WAIT0();
    __syncthreads();
    float* S = reinterpret_cast<float*>(smem);   // 128 x 130 floats = 66560 B
#pragma unroll
    for (int mt = 0; mt < 4; ++mt) {
        int mr = wm + mt * 16 + g;
#pragma unroll
        for (int nt = 0; nt < 8; ++nt) {
            int nc = wn + nt * 8 + 2 * r;
            S[mr * 130 + nc]           = acc[mt][nt][0];
            S[mr * 130 + nc + 1]       = acc[mt][nt][1];
            S[(mr + 8) * 130 + nc]     = acc[mt][nt][2];
            S[(mr + 8) * 130 + nc + 1] = acc[mt][nt][3];
        }
    }
    __syncthreads();

    const int head = blockIdx.x;       // 0..47
    const int row  = tid;              // 0..127
    const int bt   = row0 + row;
    const int b    = bt >> 10;
    const int t    = bt & (T_ - 1);
    const float* v = S + row * 130;

    if (head >= 40) {                  // V head: plain fp16 convert
        __half* dst = g_vh + ((size_t)bt * NKV + (head - 40)) * HD;
#pragma unroll 16
        for (int c2 = 0; c2 < 128; c2 += 2)
            *reinterpret_cast<__half2*>(dst + c2) =
                __floats2half2_rn(v[c2], v[c2 + 1]);
        return;
    }

    // RMSNorm over full row
    float ss = 0.f;
#pragma unroll 16
    for (int c = 0; c < 128; ++c) ss += v[c] * v[c];
    float rinv = rsqrtf(ss * (1.0f / HD) + 1e-6f);

    int   segv  = seg[bt];
    int   first = g_first[b];
    float pos   = (segv != 0) ? (float)(t - first) : 1073741824.0f;

    const float* sc = (head < NQ) ? qscale : kscale;
    const float  oscale = (head < NQ) ? 0.08838834764831845f : 1.0f;
    __half* dst = (head < NQ)
        ? g_qh + ((size_t)bt * NQ + head) * HD
        : g_kh + ((size_t)bt * NKV + (head - NQ)) * HD;

#pragma unroll 8
    for (int c2 = 0; c2 < 64; c2 += 2) {
        float lo[2], hi[2];
#pragma unroll
        for (int u = 0; u < 2; ++u) {
            int c = c2 + u;
            float invf = exp2f((-2.0f * (float)c / 128.0f) * 19.931568569324174f);
            float ang  = pos * invf;
            float s_ = sinf(ang), c_ = cosf(ang);
            float n_lo = sc[c] * v[c] * rinv;
            float n_hi = sc[c + 64] * v[c + 64] * rinv;
            lo[u] = (n_lo * c_ - n_hi * s_) * oscale;
            hi[u] = (n_hi * c_ + n_lo * s_) * oscale;
        }
        *reinterpret_cast<__half2*>(dst + c2)      = __floats2half2_rn(lo[0], lo[1]);
        *reinterpret_cast<__half2*>(dst + 64 + c2) = __floats2half2_rn(hi[0], hi[1]);
    }
}

// ============================================================
// 4) flash attention: BM=64 q x BN=64 k, 4 warps, fp16 mma (as R8/R9)
// ============================================================
#define FA_STRIDE 136
#define FA_TILE_B (64 * FA_STRIDE * 2)
#define FA_SMEM (5 * FA_TILE_B)

__global__ __launch_bounds__(128)
void fattn_kernel() {
    extern __shared__ char smem[];
    const uint32_t sb = smem_u32(smem);
    const uint32_t qbase = sb;
    const uint32_t kbase0 = sb + FA_TILE_B;
    const uint32_t vbase0 = sb + 2 * FA_TILE_B;

    const int tid  = threadIdx.x;
    const int wid  = tid >> 5;
    const int lane = tid & 31;
    const int g    = lane >> 2;
    const int r    = lane & 3;
    const int lrow = lane & 15;
    const int lk8  = (lane >> 4) * 8;
    const int b  = blockIdx.z;
    const int n  = blockIdx.y;
    const int kh = n >> 2;
    const int t0 = blockIdx.x * 64;

    {
        const __half* qsrc = g_qh + ((size_t)(b * T_ + t0) * NQ + n) * HD;
#pragma unroll
        for (int j = 0; j < 8; ++j) {
            int f = tid + 128 * j;
            int row = f >> 4, c = f & 15;
            CP_ASYNC16(qbase + row * 272 + c * 16,
                       qsrc + (size_t)row * (NQ * HD) + c * 8);
        }
    }
    CP_COMMIT();

    const int start = g_start[b];
    const int s_begin = start & ~63;
    const int ntiles = (t0 + 64 - s_begin) >> 6;

    auto load_kv = [&](int st, int s0) {
        uint32_t kb = kbase0 + st * 2 * FA_TILE_B;
        uint32_t vb = vbase0 + st * 2 * FA_TILE_B;
        const __half* ksrc = g_kh + ((size_t)(b * T_ + s0) * NKV + kh) * HD;
        const __half* vsrc = g_vh + ((size_t)(b * T_ + s0) * NKV + kh) * HD;
#pragma unroll
        for (int j = 0; j < 8; ++j) {
            int f = tid + 128 * j;
            int row = f >> 4, c = f & 15;
            CP_ASYNC16(kb + row * 272 + c * 16, ksrc + (size_t)row * (NKV * HD) + c * 8);
            CP_ASYNC16(vb + row * 272 + c * 16, vsrc + (size_t)row * (NKV * HD) + c * 8);
        }
    };

    if (ntiles > 0) load_kv(0, s_begin);
    CP_COMMIT();

    CP_WAIT1();
    __syncthreads();
    uint32_t qf[8][4];
#pragma unroll
    for (int kt = 0; kt < 8; ++kt) {
        uint32_t addr = qbase + (uint32_t)(wid * 16 + lrow) * 272 + (kt * 16 + lk8) * 2;
        LDSM4(qf[kt][0], qf[kt][1], qf[kt][2], qf[kt][3], addr);
    }

    const int tq0 = t0 + wid * 16 + g;
    const int tq1 = tq0 + 8;

    float m0 = NEG_INF, m1 = NEG_INF, l0 = 0.f, l1 = 0.f;
    float o[16][4];
#pragma unroll
    for (int i = 0; i < 16; ++i)
#pragma unroll
        for (int j = 0; j < 4; ++j) o[i][j] = 0.f;

    for (int it = 0; it < ntiles; ++it) {
        const int s0 = s_begin + it * 64;
        if (it + 1 < ntiles) load_kv((it + 1) & 1, s0 + 64);
        CP_COMMIT();
        CP_WAIT1();
        __syncthreads();

        const uint32_t kb = kbase0 + (it & 1) * 2 * FA_TILE_B;
        const uint32_t vb = vbase0 + (it & 1) * 2 * FA_TILE_B;

        float sfr[8][4];
#pragma unroll
        for (int i = 0; i < 8; ++i)
#pragma unroll
            for (int j = 0; j < 4; ++j) sfr[i][j] = 0.f;

#pragma unroll
        for (int ks = 0; ks < 8; ++ks) {
            const int kcol = ks * 16 + lk8;
#pragma unroll
            for (int np = 0; np < 4; ++np) {
                uint32_t b0, b1, b2, b3;
                uint32_t addr = kb + (uint32_t)(np * 16 + lrow) * 272 + kcol * 2;
                LDSM4(b0, b1, b2, b3, addr);
                mma_f16(sfr[2 * np],     qf[ks][0], qf[ks][1], qf[ks][2], qf[ks][3], b0, b2);
                mma_f16(sfr[2 * np + 1], qf[ks][0], qf[ks][1], qf[ks][2], qf[ks][3], b1, b3);
            }
        }

        float mx0 = NEG_INF, mx1 = NEG_INF;
#pragma unroll
        for (int nt = 0; nt < 8; ++nt) {
#pragma unroll
            for (int c = 0; c < 2; ++c) {
                int s = s0 + nt * 8 + 2 * r + c;
                bool vs = (s >= start);
                float v0 = (vs && s <= tq0) ? sfr[nt][c]     : NEG_INF;
                float v1 = (vs && s <= tq1) ? sfr[nt][2 + c] : NEG_INF;
                sfr[nt][c]     = v0;
                sfr[nt][2 + c] = v1;
                mx0 = fmaxf(mx0, v0);
                mx1 = fmaxf(mx1, v1);
            }
        }
        mx0 = fmaxf(mx0, __shfl_xor_sync(0xffffffffu, mx0, 1));
        mx0 = fmaxf(mx0, __shfl_xor_sync(0xffffffffu, mx0, 2));
        mx1 = fmaxf(mx1, __shfl_xor_sync(0xffffffffu, mx1, 1));
        mx1 = fmaxf(mx1, __shfl_xor_sync(0xffffffffu, mx1, 2));

        float mn0 = fmaxf(m0, mx0), mn1 = fmaxf(m1, mx1);
        float mu0 = (mn0 == NEG_INF) ? 0.f : mn0;
        float mu1 = (mn1 == NEG_INF) ? 0.f : mn1;
        float alpha0 = (m0 == NEG_INF) ? ((mn0 == NEG_INF) ? 1.f : 0.f) : __expf(m0 - mn0);
        float alpha1 = (m1 == NEG_INF) ? ((mn1 == NEG_INF) ? 1.f : 0.f) : __expf(m1 - mn1);
        m0 = mn0; m1 = mn1;

        float ps0 = 0.f, ps1 = 0.f;
#pragma unroll
        for (int nt = 0; nt < 8; ++nt) {
#pragma unroll
            for (int c = 0; c < 2; ++c) {
                float p0 = __expf(sfr[nt][c]     - mu0);
                float p1 = __expf(sfr[nt][2 + c] - mu1);
                sfr[nt][c]     = p0;
                sfr[nt][2 + c] = p1;
                ps0 += p0; ps1 += p1;
            }
        }
        ps0 += __shfl_xor_sync(0xffffffffu, ps0, 1);
        ps0 += __shfl_xor_sync(0xffffffffu, ps0, 2);
        ps1 += __shfl_xor_sync(0xffffffffu, ps1, 1);
        ps1 += __shfl_xor_sync(0xffffffffu, ps1, 2);
        l0 = l0 * alpha0 + ps0;
        l1 = l1 * alpha1 + ps1;

#pragma unroll
        for (int nt = 0; nt < 16; ++nt) {
            o[nt][0] *= alpha0; o[nt][1] *= alpha0;
            o[nt][2] *= alpha1; o[nt][3] *= alpha1;
        }

#pragma unroll
        for (int kt = 0; kt < 4; ++kt) {
            uint32_t a0 = h2_as_u32(__floats2half2_rn(sfr[2 * kt][0],     sfr[2 * kt][1]));
            uint32_t a1 = h2_as_u32(__floats2half2_rn(sfr[2 * kt][2],     sfr[2 * kt][3]));
            uint32_t a2 = h2_as_u32(__floats2half2_rn(sfr[2 * kt + 1][0], sfr[2 * kt + 1][1]));
            uint32_t a3 = h2_as_u32(__floats2half2_rn(sfr[2 * kt + 1][2], sfr[2 * kt + 1][3]));
            const int mrow = lane >> 3, mi = lane & 7;
            const int key = kt * 16 + (mrow & 1) * 8 + mi;
#pragma unroll
            for (int dp = 0; dp < 8; ++dp) {
                uint32_t v0, v1, v2, v3;
                uint32_t addr = vb + (uint32_t)key * 272 + (dp * 16 + (mrow >> 1) * 8) * 2;
                LDSM4T(v0, v1, v2, v3, addr);
                mma_f16(o[2 * dp],     a0, a1, a2, a3, v0, v1);
                mma_f16(o[2 * dp + 1], a0, a1, a2, a3, v2, v3);
            }
        }
        __syncthreads();
    }

    float inv0 = (l0 > 0.f) ? (1.0f / l0) : 0.f;
    float inv1 = (l1 > 0.f) ? (1.0f / l1) : 0.f;
    __half* o0 = g_oh + ((size_t)(b * T_ + tq0) * NQ + n) * HD;
    __half* o1 = g_oh + ((size_t)(b * T_ + tq1) * NQ + n) * HD;
#pragma unroll
    for (int nt = 0; nt < 16; ++nt) {
        int col = nt * 8 + 2 * r;
        *reinterpret_cast<__half2*>(o0 + col) =
            __floats2half2_rn(o[nt][0] * inv0, o[nt][1] * inv0);
        *reinterpret_cast<__half2*>(o1 + col) =
            __floats2half2_rn(o[nt][2] * inv1, o[nt][3] * inv1);
    }
}

// ============================================================
// launch  (order chosen so ncu -s 5 -c 1 captures the QKV GEMM)
// ============================================================
extern "C" void kernel_launch(void* const* d_in, const int* in_sizes, int n_in,
                              void* d_out, int out_size) {
    const float* x       = (const float*)d_in[0];
    const float* wq      = (const float*)d_in[1];
    const float* wk      = (const float*)d_in[2];
    const float* wv      = (const float*)d_in[3];
    const float* wo      = (const float*)d_in[4];
    const float* q_scale = (const float*)d_in[5];
    const float* k_scale = (const float*)d_in[6];
    const int*   seg     = (const int*)d_in[9];
    float* out = (float*)d_out;

    __half *pxh, *pwqkvh, *pwoh, *poh;
    cudaGetSymbolAddress((void**)&pxh, g_xh);
    cudaGetSymbolAddress((void**)&pwqkvh, g_wqkvh);
    cudaGetSymbolAddress((void**)&pwoh, g_woh);
    cudaGetSymbolAddress((void**)&poh, g_oh);

    cudaFuncSetAttribute(gemm_f16_kernel<true>, cudaFuncAttributeMaxDynamicSharedMemorySize,
                         GEMM_SMEM);
    cudaFuncSetAttribute(gemm_f16_kernel<false>, cudaFuncAttributeMaxDynamicSharedMemorySize,
                         GEMM_SMEM);
    cudaFuncSetAttribute(fattn_kernel, cudaFuncAttributeMaxDynamicSharedMemorySize,
                         FA_SMEM);

    startfirst_kernel<<<B_, 256>>>(seg);                               // 0
    f32_to_f16_kernel<<<(MTOT * D_ / 4) / 256, 256>>>(
        (const float4*)x, (__half2*)pxh);                              // 1
    transpose_f16_kernel<<<dim3(D_ / 32, D_ / 32), dim3(32, 8)>>>(
        wq, pwqkvh, D_, NQ * HD);                                      // 2
    transpose_f16_kernel<<<dim3(NKV * HD / 32, D_ / 32), dim3(32, 8)>>>(
        wk, pwqkvh + (size_t)K_OFF * D_, D_, NKV * HD);                // 3
    transpose_f16_kernel<<<dim3(NKV * HD / 32, D_ / 32), dim3(32, 8)>>>(
        wv, pwqkvh + (size_t)V_OFF * D_, D_, NKV * HD);                // 4

    // 5: fused QKV projection + RMSNorm + RoPE + fp16 convert (ncu target)
    gemm_f16_kernel<true><<<dim3(QKV_N / 128, MTOT / 128), 128, GEMM_SMEM>>>(
        pxh, pwqkvh, nullptr, QKV_N, D_, q_scale, k_scale, seg);

    fattn_kernel<<<dim3(T_ / 64, NQ, B_), 128, FA_SMEM>>>();           // 6

    transpose_f16_kernel<<<dim3(D_ / 32, NQ * HD / 32), dim3(32, 8)>>>(
        wo, pwoh, NQ * HD, D_);                                        // 7

    // 8: output projection
    gemm_f16_kernel<false><<<dim3(D_ / 128, MTOT / 128), 128, GEMM_SMEM>>>(
        poh, pwoh, out, D_, NQ * HD, nullptr, nullptr, nullptr);
}

// round 11
// speedup vs baseline: 8.0742x; 1.0925x over previous
#include <cuda_runtime.h>
#include <cuda_fp16.h>
#include <math.h>
#include <stdint.h>

// Problem constants
#define B_   2
#define T_   1024
#define D_   4096
#define NQ   32
#define NKV  8
#define HD   128
#define MTOT (B_ * T_)      // 2048
#define QKV_N 6144          // 4096 q + 1024 k + 1024 v
#define K_OFF 4096
#define V_OFF 5120

#define NEG_INF (-INFINITY)

// -------- scratch (device globals; allocation-free) --------
__device__ __align__(256) __half g_qh[(size_t)MTOT * NQ * HD];    // 16 MB
__device__ __align__(256) __half g_kh[(size_t)MTOT * NKV * HD];   //  4 MB
__device__ __align__(256) __half g_vh[(size_t)MTOT * NKV * HD];   //  4 MB
__device__ __align__(256) __half g_oh[(size_t)MTOT * NQ * HD];    // 16 MB
__device__ __align__(256) __half g_xh[(size_t)MTOT * D_];         // 16 MB
__device__ __align__(256) __half g_wqkvh[(size_t)D_ * QKV_N];     // 48 MB ([k][n] natural)
__device__ __align__(256) __half g_woh[(size_t)NQ * HD * D_];     // 32 MB ([nh][d] natural)
__device__ int g_start[B_];
__device__ int g_first[B_];

// ============================================================
// helpers
// ============================================================
__device__ __forceinline__ uint32_t smem_u32(const void* p) {
    uint32_t a;
    asm("{ .reg .u64 t; cvta.to.shared.u64 t, %1; cvt.u32.u64 %0, t; }" : "=r"(a) : "l"(p));
    return a;
}
__device__ __forceinline__ uint32_t h2_as_u32(__half2 h) {
    return *reinterpret_cast<uint32_t*>(&h);
}

#define CP_ASYNC16(saddr, gptr) \
    asm volatile("cp.async.cg.shared.global [%0], [%1], 16;" :: "r"(saddr), "l"(gptr) : "memory")
#define CP_COMMIT() asm volatile("cp.async.commit_group;" ::: "memory")
#define CP_WAIT1()  asm volatile("cp.async.wait_group 1;" ::: "memory")
#define CP_WAIT0()  asm volatile("cp.async.wait_group 0;" ::: "memory")

#define LDSM4(r0, r1, r2, r3, addr) \
    asm volatile("ldmatrix.sync.aligned.m8n8.x4.shared.b16 {%0,%1,%2,%3}, [%4];" \
        : "=r"(r0), "=r"(r1), "=r"(r2), "=r"(r3) : "r"(addr))
#define LDSM4T(r0, r1, r2, r3, addr) \
    asm volatile("ldmatrix.sync.aligned.m8n8.x4.trans.shared.b16 {%0,%1,%2,%3}, [%4];" \
        : "=r"(r0), "=r"(r1), "=r"(r2), "=r"(r3) : "r"(addr))

__device__ __forceinline__ void mma_f16(float c[4],
                                        uint32_t a0, uint32_t a1, uint32_t a2, uint32_t a3,
                                        uint32_t b0, uint32_t b1) {
    asm volatile(
        "mma.sync.aligned.m16n8k16.row.col.f32.f16.f16.f32 "
        "{%0,%1,%2,%3}, {%4,%5,%6,%7}, {%8,%9}, {%0,%1,%2,%3};"
        : "+f"(c[0]), "+f"(c[1]), "+f"(c[2]), "+f"(c[3])
        : "r"(a0), "r"(a1), "r"(a2), "r"(a3), "r"(b0), "r"(b1));
}

// ============================================================
// 1) segment scan
// ============================================================
__global__ void startfirst_kernel(const int* __restrict__ seg) {
    int b = blockIdx.x;
    const int* s = seg + (size_t)b * T_;
    __shared__ int sh_min, sh_max, sh_first;
    if (threadIdx.x == 0) { sh_min = T_; sh_max = INT_MIN; sh_first = T_; }
    __syncthreads();
    int lmin = T_, lmax = INT_MIN;
    for (int t = threadIdx.x; t < T_; t += blockDim.x) {
        int v = s[t];
        if (v != 0 && t < lmin) lmin = t;
        if (v > lmax) lmax = v;
    }
    atomicMin(&sh_min, lmin);
    atomicMax(&sh_max, lmax);
    __syncthreads();
    int mx = sh_max;
    int lfirst = T_;
    for (int t = threadIdx.x; t < T_; t += blockDim.x)
        if (s[t] == mx && t < lfirst) lfirst = t;
    atomicMin(&sh_first, lfirst);
    __syncthreads();
    if (threadIdx.x == 0) { g_start[b] = sh_min; g_first[b] = sh_first; }
}

// ============================================================
// 2) conversions (element-wise; no transposes anywhere)
// ============================================================
__global__ void f32_to_f16_kernel(const float4* __restrict__ src, __half2* __restrict__ dst) {
    int i = blockIdx.x * blockDim.x + threadIdx.x;
    float4 v = src[i];
    dst[2 * i]     = __floats2half2_rn(v.x, v.y);
    dst[2 * i + 1] = __floats2half2_rn(v.z, v.w);
}

// pack wq|wk|wv rows into combined [D][6144] f16 buffer (all natural [k][n])
__global__ void pack_wqkv_f16_kernel(const float4* __restrict__ wq, const float4* __restrict__ wk,
                                     const float4* __restrict__ wv, __half2* __restrict__ dst) {
    int i = blockIdx.x * blockDim.x + threadIdx.x;   // over D * 1536 float4s
    int row = i / (QKV_N / 4);
    int c4  = i % (QKV_N / 4);
    float4 v;
    if (c4 < 1024)       v = wq[(size_t)row * 1024 + c4];
    else if (c4 < 1280)  v = wk[(size_t)row * 256 + (c4 - 1024)];
    else                 v = wv[(size_t)row * 256 + (c4 - 1280)];
    dst[2 * i]     = __floats2half2_rn(v.x, v.y);
    dst[2 * i + 1] = __floats2half2_rn(v.z, v.w);
}

// ============================================================
// 3) fp16 mma.sync GEMM: BM=BN=128, BK=64, 4 warps (2x2), warp tile 64x64,
//    3-stage cp.async. A: [M][K] f16. B: [K][N] f16 (natural layout,
//    trans-ldmatrix fragments). FUSE=true: QKV RMSNorm+RoPE+f16 epilogue.
// ============================================================
#define A_STRIDE_B 144                        // bytes per A smem row (72 halves)
#define B_STRIDE_B 272                        // bytes per B smem row (136 halves)
#define A_TILE_BYTES (128 * A_STRIDE_B)       // 18432
#define B_TILE_BYTES (64 * B_STRIDE_B)        // 17408
#define STAGE_BYTES (A_TILE_BYTES + B_TILE_BYTES) // 35840
#define GSTAGES 3
#define GEMM_SMEM (GSTAGES * STAGE_BYTES)     // 107520

template <bool FUSE>
__global__ __launch_bounds__(128, 2)
void gemm_f16_kernel(const __half* __restrict__ A, const __half* __restrict__ Bn,
                     float* __restrict__ C, int N, int K,
                     const float* __restrict__ qscale, const float* __restrict__ kscale,
                     const int* __restrict__ seg) {
    extern __shared__ char smem[];
    const uint32_t sb = smem_u32(smem);
    const int tid  = threadIdx.x;
    const int wid  = tid >> 5;
    const int lane = tid & 31;
    const int g    = lane >> 2;
    const int r    = lane & 3;
    const int row0 = blockIdx.y * 128;
    const int col0 = blockIdx.x * 128;
    const int wm   = (wid >> 1) * 64;    // 0 / 64
    const int wn   = (wid & 1) * 64;     // 0 / 64
    const int lrow = lane & 15;
    const int lk8  = (lane >> 4) * 8;
    const int mrow = lane >> 3;          // for trans-B fragments
    const int mi   = lane & 7;

    float acc[4][8][4];
#pragma unroll
    for (int a = 0; a < 4; ++a)
#pragma unroll
        for (int b = 0; b < 8; ++b)
#pragma unroll
            for (int c = 0; c < 4; ++c) acc[a][b][c] = 0.f;

    const int KS = K >> 6;   // BK = 64

    auto load_stage = [&](int st, int k0) {
        uint32_t abase = sb + st * STAGE_BYTES;
        uint32_t bbase = abase + A_TILE_BYTES;
        // A tile: 128 rows x 64 k (128B payload per row)
#pragma unroll
        for (int j = 0; j < 8; ++j) {
            int f  = tid + 128 * j;     // 0..1023
            int rr = f >> 3, cc = f & 7;
            CP_ASYNC16(abase + rr * A_STRIDE_B + cc * 16,
                       A + (size_t)(row0 + rr) * K + k0 + cc * 8);
        }
        // B tile: 64 k-rows x 128 n (256B payload per row)
#pragma unroll
        for (int j = 0; j < 8; ++j) {
            int f  = tid + 128 * j;     // 0..1023
            int rr = f >> 4, cc = f & 15;
            CP_ASYNC16(bbase + rr * B_STRIDE_B + cc * 16,
                       Bn + (size_t)(k0 + rr) * N + col0 + cc * 8);
        }
    };

    auto compute_stage = [&](int st) {
        uint32_t abase = sb + st * STAGE_BYTES;
        uint32_t bbase = abase + A_TILE_BYTES;
#pragma unroll
        for (int ks = 0; ks < 4; ++ks) {
            // B fragments via trans-ldmatrix on [k][n] rows (fattn V pattern)
            const int key = ks * 16 + (mrow & 1) * 8 + mi;   // k row in tile
            uint32_t br[4][4];
#pragma unroll
            for (int ntp = 0; ntp < 4; ++ntp) {
                uint32_t addr = bbase + (uint32_t)key * B_STRIDE_B
                              + (uint32_t)(wn + ntp * 16 + (mrow >> 1) * 8) * 2;
                LDSM4T(br[ntp][0], br[ntp][1], br[ntp][2], br[ntp][3], addr);
            }
            const int kb = ks * 16 + lk8;
#pragma unroll
            for (int mt = 0; mt < 4; ++mt) {
                uint32_t a0, a1, a2, a3;
                uint32_t addr = abase + (uint32_t)(wm + mt * 16 + lrow) * A_STRIDE_B + kb * 2;
                LDSM4(a0, a1, a2, a3, addr);
#pragma unroll
                for (int ntp = 0; ntp < 4; ++ntp) {
                    mma_f16(acc[mt][2 * ntp],     a0, a1, a2, a3, br[ntp][0], br[ntp][1]);
                    mma_f16(acc[mt][2 * ntp + 1], a0, a1, a2, a3, br[ntp][2], br[ntp][3]);
                }
            }
        }
    };

    load_stage(0, 0);   CP_COMMIT();
    load_stage(1, 64);  CP_COMMIT();

    for (int i = 0; i < KS; ++i) {
        CP_WAIT1();
        __syncthreads();
        if (i + 2 < KS) load_stage((i + 2) % 3, (i + 2) << 6);
        CP_COMMIT();
        compute_stage(i % 3);
    }

    if (!FUSE) {
#pragma unroll
        for (int mt = 0; mt < 4; ++mt) {
            int mrowg = row0 + wm + mt * 16;
#pragma unroll
            for (int nt = 0; nt < 8; ++nt) {
                int ncol = col0 + wn + nt * 8 + 2 * r;
                *reinterpret_cast<float2*>(&C[(size_t)(mrowg + g) * N + ncol]) =
                    make_float2(acc[mt][nt][0], acc[mt][nt][1]);
                *reinterpret_cast<float2*>(&C[(size_t)(mrowg + g + 8) * N + ncol]) =
                    make_float2(acc[mt][nt][2], acc[mt][nt][3]);
            }
        }
        return;
    }

    // ---- fused QKV epilogue: RMSNorm + RoPE + fp16 stores ----
    CP_WAIT0();
    __syncthreads();
    float* S = reinterpret_cast<float*>(smem);   // 128 x 130 floats
#pragma unroll
    for (int mt = 0; mt < 4; ++mt) {
        int mr = wm + mt * 16 + g;
#pragma unroll
        for (int nt = 0; nt < 8; ++nt) {
            int nc = wn + nt * 8 + 2 * r;
            S[mr * 130 + nc]           = acc[mt][nt][0];
            S[mr * 130 + nc + 1]       = acc[mt][nt][1];
            S[(mr + 8) * 130 + nc]     = acc[mt][nt][2];
            S[(mr + 8) * 130 + nc + 1] = acc[mt][nt][3];
        }
    }
    __syncthreads();

    const int head = blockIdx.x;       // 0..47
    const int row  = tid;              // 0..127
    const int bt   = row0 + row;
    const int b    = bt >> 10;
    const int t    = bt & (T_ - 1);
    const float* v = S + row * 130;

    if (head >= 40) {                  // V head: plain fp16 convert
        __half* dst = g_vh + ((size_t)bt * NKV + (head - 40)) * HD;
#pragma unroll 16
        for (int c2 = 0; c2 < 128; c2 += 2)
            *reinterpret_cast<__half2*>(dst + c2) =
                __floats2half2_rn(v[c2], v[c2 + 1]);
        return;
    }

    float ss = 0.f;
#pragma unroll 16
    for (int c = 0; c < 128; ++c) ss += v[c] * v[c];
    float rinv = rsqrtf(ss * (1.0f / HD) + 1e-6f);

    int   segv  = seg[bt];
    int   first = g_first[b];
    float pos   = (segv != 0) ? (float)(t - first) : 1073741824.0f;

    const float* sc = (head < NQ) ? qscale : kscale;
    const float  oscale = (head < NQ) ? 0.08838834764831845f : 1.0f;
    __half* dst = (head < NQ)
        ? g_qh + ((size_t)bt * NQ + head) * HD
        : g_kh + ((size_t)bt * NKV + (head - NQ)) * HD;

#pragma unroll 8
    for (int c2 = 0; c2 < 64; c2 += 2) {
        float lo[2], hi[2];
#pragma unroll
        for (int u = 0; u < 2; ++u) {
            int c = c2 + u;
            float invf = exp2f((-2.0f * (float)c / 128.0f) * 19.931568569324174f);
            float ang  = pos * invf;
            float s_ = sinf(ang), c_ = cosf(ang);
            float n_lo = sc[c] * v[c] * rinv;
            float n_hi = sc[c + 64] * v[c + 64] * rinv;
            lo[u] = (n_lo * c_ - n_hi * s_) * oscale;
            hi[u] = (n_hi * c_ + n_lo * s_) * oscale;
        }
        *reinterpret_cast<__half2*>(dst + c2)      = __floats2half2_rn(lo[0], lo[1]);
        *reinterpret_cast<__half2*>(dst + 64 + c2) = __floats2half2_rn(hi[0], hi[1]);
    }
}

// ============================================================
// 4) flash attention (unchanged from R8/R9)
// ============================================================
#define FA_STRIDE 136
#define FA_TILE_B (64 * FA_STRIDE * 2)
#define FA_SMEM (5 * FA_TILE_B)

__global__ __launch_bounds__(128)
void fattn_kernel() {
    extern __shared__ char smem[];
    const uint32_t sb = smem_u32(smem);
    const uint32_t qbase = sb;
    const uint32_t kbase0 = sb + FA_TILE_B;
    const uint32_t vbase0 = sb + 2 * FA_TILE_B;

    const int tid  = threadIdx.x;
    const int wid  = tid >> 5;
    const int lane = tid & 31;
    const int g    = lane >> 2;
    const int r    = lane & 3;
    const int lrow = lane & 15;
    const int lk8  = (lane >> 4) * 8;
    const int b  = blockIdx.z;
    const int n  = blockIdx.y;
    const int kh = n >> 2;
    const int t0 = blockIdx.x * 64;

    {
        const __half* qsrc = g_qh + ((size_t)(b * T_ + t0) * NQ + n) * HD;
#pragma unroll
        for (int j = 0; j < 8; ++j) {
            int f = tid + 128 * j;
            int row = f >> 4, c = f & 15;
            CP_ASYNC16(qbase + row * 272 + c * 16,
                       qsrc + (size_t)row * (NQ * HD) + c * 8);
        }
    }
    CP_COMMIT();

    const int start = g_start[b];
    const int s_begin = start & ~63;
    const int ntiles = (t0 + 64 - s_begin) >> 6;

    auto load_kv = [&](int st, int s0) {
        uint32_t kb = kbase0 + st * 2 * FA_TILE_B;
        uint32_t vb = vbase0 + st * 2 * FA_TILE_B;
        const __half* ksrc = g_kh + ((size_t)(b * T_ + s0) * NKV + kh) * HD;
        const __half* vsrc = g_vh + ((size_t)(b * T_ + s0) * NKV + kh) * HD;
#pragma unroll
        for (int j = 0; j < 8; ++j) {
            int f = tid + 128 * j;
            int row = f >> 4, c = f & 15;
            CP_ASYNC16(kb + row * 272 + c * 16, ksrc + (size_t)row * (NKV * HD) + c * 8);
            CP_ASYNC16(vb + row * 272 + c * 16, vsrc + (size_t)row * (NKV * HD) + c * 8);
        }
    };

    if (ntiles > 0) load_kv(0, s_begin);
    CP_COMMIT();

    CP_WAIT1();
    __syncthreads();
    uint32_t qf[8][4];
#pragma unroll
    for (int kt = 0; kt < 8; ++kt) {
        uint32_t addr = qbase + (uint32_t)(wid * 16 + lrow) * 272 + (kt * 16 + lk8) * 2;
        LDSM4(qf[kt][0], qf[kt][1], qf[kt][2], qf[kt][3], addr);
    }

    const int tq0 = t0 + wid * 16 + g;
    const int tq1 = tq0 + 8;

    float m0 = NEG_INF, m1 = NEG_INF, l0 = 0.f, l1 = 0.f;
    float o[16][4];
#pragma unroll
    for (int i = 0; i < 16; ++i)
#pragma unroll
        for (int j = 0; j < 4; ++j) o[i][j] = 0.f;

    for (int it = 0; it < ntiles; ++it) {
        const int s0 = s_begin + it * 64;
        if (it + 1 < ntiles) load_kv((it + 1) & 1, s0 + 64);
        CP_COMMIT();
        CP_WAIT1();
        __syncthreads();

        const uint32_t kb = kbase0 + (it & 1) * 2 * FA_TILE_B;
        const uint32_t vb = vbase0 + (it & 1) * 2 * FA_TILE_B;

        float sfr[8][4];
#pragma unroll
        for (int i = 0; i < 8; ++i)
#pragma unroll
            for (int j = 0; j < 4; ++j) sfr[i][j] = 0.f;

#pragma unroll
        for (int ks = 0; ks < 8; ++ks) {
            const int kcol = ks * 16 + lk8;
#pragma unroll
            for (int np = 0; np < 4; ++np) {
                uint32_t b0, b1, b2, b3;
                uint32_t addr = kb + (uint32_t)(np * 16 + lrow) * 272 + kcol * 2;
                LDSM4(b0, b1, b2, b3, addr);
                mma_f16(sfr[2 * np],     qf[ks][0], qf[ks][1], qf[ks][2], qf[ks][3], b0, b2);
                mma_f16(sfr[2 * np + 1], qf[ks][0], qf[ks][1], qf[ks][2], qf[ks][3], b1, b3);
            }
        }

        float mx0 = NEG_INF, mx1 = NEG_INF;
#pragma unroll
        for (int nt = 0; nt < 8; ++nt) {
#pragma unroll
            for (int c = 0; c < 2; ++c) {
                int s = s0 + nt * 8 + 2 * r + c;
                bool vs = (s >= start);
                float v0 = (vs && s <= tq0) ? sfr[nt][c]     : NEG_INF;
                float v1 = (vs && s <= tq1) ? sfr[nt][2 + c] : NEG_INF;
                sfr[nt][c]     = v0;
                sfr[nt][2 + c] = v1;
                mx0 = fmaxf(mx0, v0);
                mx1 = fmaxf(mx1, v1);
            }
        }
        mx0 = fmaxf(mx0, __shfl_xor_sync(0xffffffffu, mx0, 1));
        mx0 = fmaxf(mx0, __shfl_xor_sync(0xffffffffu, mx0, 2));
        mx1 = fmaxf(mx1, __shfl_xor_sync(0xffffffffu, mx1, 1));
        mx1 = fmaxf(mx1, __shfl_xor_sync(0xffffffffu, mx1, 2));

        float mn0 = fmaxf(m0, mx0), mn1 = fmaxf(m1, mx1);
        float mu0 = (mn0 == NEG_INF) ? 0.f : mn0;
        float mu1 = (mn1 == NEG_INF) ? 0.f : mn1;
        float alpha0 = (m0 == NEG_INF) ? ((mn0 == NEG_INF) ? 1.f : 0.f) : __expf(m0 - mn0);
        float alpha1 = (m1 == NEG_INF) ? ((mn1 == NEG_INF) ? 1.f : 0.f) : __expf(m1 - mn1);
        m0 = mn0; m1 = mn1;

        float ps0 = 0.f, ps1 = 0.f;
#pragma unroll
        for (int nt = 0; nt < 8; ++nt) {
#pragma unroll
            for (int c = 0; c < 2; ++c) {
                float p0 = __expf(sfr[nt][c]     - mu0);
                float p1 = __expf(sfr[nt][2 + c] - mu1);
                sfr[nt][c]     = p0;
                sfr[nt][2 + c] = p1;
                ps0 += p0; ps1 += p1;
            }
        }
        ps0 += __shfl_xor_sync(0xffffffffu, ps0, 1);
        ps0 += __shfl_xor_sync(0xffffffffu, ps0, 2);
        ps1 += __shfl_xor_sync(0xffffffffu, ps1, 1);
        ps1 += __shfl_xor_sync(0xffffffffu, ps1, 2);
        l0 = l0 * alpha0 + ps0;
        l1 = l1 * alpha1 + ps1;

#pragma unroll
        for (int nt = 0; nt < 16; ++nt) {
            o[nt][0] *= alpha0; o[nt][1] *= alpha0;
            o[nt][2] *= alpha1; o[nt][3] *= alpha1;
        }

#pragma unroll
        for (int kt = 0; kt < 4; ++kt) {
            uint32_t a0 = h2_as_u32(__floats2half2_rn(sfr[2 * kt][0],     sfr[2 * kt][1]));
            uint32_t a1 = h2_as_u32(__floats2half2_rn(sfr[2 * kt][2],     sfr[2 * kt][3]));
            uint32_t a2 = h2_as_u32(__floats2half2_rn(sfr[2 * kt + 1][0], sfr[2 * kt + 1][1]));
            uint32_t a3 = h2_as_u32(__floats2half2_rn(sfr[2 * kt + 1][2], sfr[2 * kt + 1][3]));
            const int mrow = lane >> 3, mi = lane & 7;
            const int key = kt * 16 + (mrow & 1) * 8 + mi;
#pragma unroll
            for (int dp = 0; dp < 8; ++dp) {
                uint32_t v0, v1, v2, v3;
                uint32_t addr = vb + (uint32_t)key * 272 + (dp * 16 + (mrow >> 1) * 8) * 2;
                LDSM4T(v0, v1, v2, v3, addr);
                mma_f16(o[2 * dp],     a0, a1, a2, a3, v0, v1);
                mma_f16(o[2 * dp + 1], a0, a1, a2, a3, v2, v3);
            }
        }
        __syncthreads();
    }

    float inv0 = (l0 > 0.f) ? (1.0f / l0) : 0.f;
    float inv1 = (l1 > 0.f) ? (1.0f / l1) : 0.f;
    __half* o0 = g_oh + ((size_t)(b * T_ + tq0) * NQ + n) * HD;
    __half* o1 = g_oh + ((size_t)(b * T_ + tq1) * NQ + n) * HD;
#pragma unroll
    for (int nt = 0; nt < 16; ++nt) {
        int col = nt * 8 + 2 * r;
        *reinterpret_cast<__half2*>(o0 + col) =
            __floats2half2_rn(o[nt][0] * inv0, o[nt][1] * inv0);
        *reinterpret_cast<__half2*>(o1 + col) =
            __floats2half2_rn(o[nt][2] * inv1, o[nt][3] * inv1);
    }
}

// ============================================================
// launch
// ============================================================
extern "C" void kernel_launch(void* const* d_in, const int* in_sizes, int n_in,
                              void* d_out, int out_size) {
    const float* x       = (const float*)d_in[0];
    const float* wq      = (const float*)d_in[1];
    const float* wk      = (const float*)d_in[2];
    const float* wv      = (const float*)d_in[3];
    const float* wo      = (const float*)d_in[4];
    const float* q_scale = (const float*)d_in[5];
    const float* k_scale = (const float*)d_in[6];
    const int*   seg     = (const int*)d_in[9];
    float* out = (float*)d_out;

    __half *pxh, *pwqkvh, *pwoh, *poh;
    cudaGetSymbolAddress((void**)&pxh, g_xh);
    cudaGetSymbolAddress((void**)&pwqkvh, g_wqkvh);
    cudaGetSymbolAddress((void**)&pwoh, g_woh);
    cudaGetSymbolAddress((void**)&poh, g_oh);

    cudaFuncSetAttribute(gemm_f16_kernel<true>, cudaFuncAttributeMaxDynamicSharedMemorySize,
                         GEMM_SMEM);
    cudaFuncSetAttribute(gemm_f16_kernel<false>, cudaFuncAttributeMaxDynamicSharedMemorySize,
                         GEMM_SMEM);
    cudaFuncSetAttribute(fattn_kernel, cudaFuncAttributeMaxDynamicSharedMemorySize,
                         FA_SMEM);

    startfirst_kernel<<<B_, 256>>>(seg);                               // 0
    f32_to_f16_kernel<<<(MTOT * D_ / 4) / 256, 256>>>(
        (const float4*)x, (__half2*)pxh);                              // 1: x
    pack_wqkv_f16_kernel<<<((size_t)D_ * QKV_N / 4) / 256, 256>>>(
        (const float4*)wq, (const float4*)wk, (const float4*)wv,
        (__half2*)pwqkvh);                                             // 2: wq|wk|wv
    f32_to_f16_kernel<<<((size_t)NQ * HD * D_ / 4) / 256, 256>>>(
        (const float4*)wo, (__half2*)pwoh);                            // 3: wo

    // 4: fused QKV projection + RMSNorm + RoPE + fp16 convert
    gemm_f16_kernel<true><<<dim3(QKV_N / 128, MTOT / 128), 128, GEMM_SMEM>>>(
        pxh, pwqkvh, nullptr, QKV_N, D_, q_scale, k_scale, seg);

    fattn_kernel<<<dim3(T_ / 64, NQ, B_), 128, FA_SMEM>>>();           // 5

    // 6: output projection (wo natural [nh][d] = [K][N])
    gemm_f16_kernel<false><<<dim3(D_ / 128, MTOT / 128), 128, GEMM_SMEM>>>(
        poh, pwoh, out, D_, NQ * HD, nullptr, nullptr, nullptr);
}

// round 12
// speedup vs baseline: 8.3001x; 1.0280x over previous
#include <cuda_runtime.h>
#include <cuda_fp16.h>
#include <math.h>
#include <stdint.h>

// Problem constants
#define B_   2
#define T_   1024
#define D_   4096
#define NQ   32
#define NKV  8
#define HD   128
#define MTOT (B_ * T_)      // 2048
#define QKV_N 6144          // 4096 q + 1024 k + 1024 v
#define K_OFF 4096
#define V_OFF 5120

#define NEG_INF (-INFINITY)
#define PERSIST_GRID 296     // 148 SMs x 2 CTAs

// -------- scratch (device globals; allocation-free) --------
__device__ __align__(256) __half g_qh[(size_t)MTOT * NQ * HD];    // 16 MB
__device__ __align__(256) __half g_kh[(size_t)MTOT * NKV * HD];   //  4 MB
__device__ __align__(256) __half g_vh[(size_t)MTOT * NKV * HD];   //  4 MB
__device__ __align__(256) __half g_oh[(size_t)MTOT * NQ * HD];    // 16 MB
__device__ __align__(256) __half g_xh[(size_t)MTOT * D_];         // 16 MB
__device__ __align__(256) __half g_wqkvh[(size_t)D_ * QKV_N];     // 48 MB ([k][n] natural)
__device__ __align__(256) __half g_woh[(size_t)NQ * HD * D_];     // 32 MB ([nh][d] natural)
__device__ int g_start[B_];
__device__ int g_first[B_];

// ============================================================
// helpers
// ============================================================
__device__ __forceinline__ uint32_t smem_u32(const void* p) {
    uint32_t a;
    asm("{ .reg .u64 t; cvta.to.shared.u64 t, %1; cvt.u32.u64 %0, t; }" : "=r"(a) : "l"(p));
    return a;
}
__device__ __forceinline__ uint32_t h2_as_u32(__half2 h) {
    return *reinterpret_cast<uint32_t*>(&h);
}

#define CP_ASYNC16(saddr, gptr) \
    asm volatile("cp.async.cg.shared.global [%0], [%1], 16;" :: "r"(saddr), "l"(gptr) : "memory")
#define CP_COMMIT() asm volatile("cp.async.commit_group;" ::: "memory")
#define CP_WAIT1()  asm volatile("cp.async.wait_group 1;" ::: "memory")
#define CP_WAIT0()  asm volatile("cp.async.wait_group 0;" ::: "memory")

#define LDSM4(r0, r1, r2, r3, addr) \
    asm volatile("ldmatrix.sync.aligned.m8n8.x4.shared.b16 {%0,%1,%2,%3}, [%4];" \
        : "=r"(r0), "=r"(r1), "=r"(r2), "=r"(r3) : "r"(addr))
#define LDSM4T(r0, r1, r2, r3, addr) \
    asm volatile("ldmatrix.sync.aligned.m8n8.x4.trans.shared.b16 {%0,%1,%2,%3}, [%4];" \
        : "=r"(r0), "=r"(r1), "=r"(r2), "=r"(r3) : "r"(addr))

__device__ __forceinline__ void mma_f16(float c[4],
                                        uint32_t a0, uint32_t a1, uint32_t a2, uint32_t a3,
                                        uint32_t b0, uint32_t b1) {
    asm volatile(
        "mma.sync.aligned.m16n8k16.row.col.f32.f16.f16.f32 "
        "{%0,%1,%2,%3}, {%4,%5,%6,%7}, {%8,%9}, {%0,%1,%2,%3};"
        : "+f"(c[0]), "+f"(c[1]), "+f"(c[2]), "+f"(c[3])
        : "r"(a0), "r"(a1), "r"(a2), "r"(a3), "r"(b0), "r"(b1));
}

// ============================================================
// 1) segment scan
// ============================================================
__global__ void startfirst_kernel(const int* __restrict__ seg) {
    int b = blockIdx.x;
    const int* s = seg + (size_t)b * T_;
    __shared__ int sh_min, sh_max, sh_first;
    if (threadIdx.x == 0) { sh_min = T_; sh_max = INT_MIN; sh_first = T_; }
    __syncthreads();
    int lmin = T_, lmax = INT_MIN;
    for (int t = threadIdx.x; t < T_; t += blockDim.x) {
        int v = s[t];
        if (v != 0 && t < lmin) lmin = t;
        if (v > lmax) lmax = v;
    }
    atomicMin(&sh_min, lmin);
    atomicMax(&sh_max, lmax);
    __syncthreads();
    int mx = sh_max;
    int lfirst = T_;
    for (int t = threadIdx.x; t < T_; t += blockDim.x)
        if (s[t] == mx && t < lfirst) lfirst = t;
    atomicMin(&sh_first, lfirst);
    __syncthreads();
    if (threadIdx.x == 0) { g_start[b] = sh_min; g_first[b] = sh_first; }
}

// ============================================================
// 2) conversions (element-wise)
// ============================================================
__global__ void f32_to_f16_kernel(const float4* __restrict__ src, __half2* __restrict__ dst) {
    int i = blockIdx.x * blockDim.x + threadIdx.x;
    float4 v = src[i];
    dst[2 * i]     = __floats2half2_rn(v.x, v.y);
    dst[2 * i + 1] = __floats2half2_rn(v.z, v.w);
}

__global__ void pack_wqkv_f16_kernel(const float4* __restrict__ wq, const float4* __restrict__ wk,
                                     const float4* __restrict__ wv, __half2* __restrict__ dst) {
    int i = blockIdx.x * blockDim.x + threadIdx.x;   // over D * 1536 float4s
    int row = i / (QKV_N / 4);
    int c4  = i % (QKV_N / 4);
    float4 v;
    if (c4 < 1024)       v = wq[(size_t)row * 1024 + c4];
    else if (c4 < 1280)  v = wk[(size_t)row * 256 + (c4 - 1024)];
    else                 v = wv[(size_t)row * 256 + (c4 - 1280)];
    dst[2 * i]     = __floats2half2_rn(v.x, v.y);
    dst[2 * i + 1] = __floats2half2_rn(v.z, v.w);
}

// ============================================================
// 3) fp16 mma.sync GEMM, persistent-CTA tile loop.
//    BM=BN=128, BK=64, 4 warps (2x2), warp tile 64x64, 3-stage cp.async.
//    A: [M][K] f16. B: [K][N] f16 natural (trans-ldmatrix fragments).
//    FUSE=true: QKV RMSNorm+RoPE+f16 epilogue.
// ============================================================
#define A_STRIDE_B 144
#define B_STRIDE_B 272
#define A_TILE_BYTES (128 * A_STRIDE_B)       // 18432
#define B_TILE_BYTES (64 * B_STRIDE_B)        // 17408
#define STAGE_BYTES (A_TILE_BYTES + B_TILE_BYTES) // 35840
#define GSTAGES 3
#define GEMM_SMEM (GSTAGES * STAGE_BYTES)     // 107520

template <bool FUSE>
__global__ __launch_bounds__(128, 2)
void gemm_f16_kernel(const __half* __restrict__ A, const __half* __restrict__ Bn,
                     float* __restrict__ C, int N, int K, int ntiles, int grid_nx,
                     const float* __restrict__ qscale, const float* __restrict__ kscale,
                     const int* __restrict__ seg) {
    extern __shared__ char smem[];
    const uint32_t sb = smem_u32(smem);
    const int tid  = threadIdx.x;
    const int wid  = tid >> 5;
    const int lane = tid & 31;
    const int g    = lane >> 2;
    const int r    = lane & 3;
    const int wm   = (wid >> 1) * 64;
    const int wn   = (wid & 1) * 64;
    const int lrow = lane & 15;
    const int lk8  = (lane >> 4) * 8;
    const int mrow = lane >> 3;
    const int mi   = lane & 7;
    const int KS = K >> 6;   // BK = 64

    for (int tile = blockIdx.x; tile < ntiles; tile += gridDim.x) {
        const int bx = tile % grid_nx;
        const int by = tile / grid_nx;
        const int row0 = by * 128;
        const int col0 = bx * 128;

        float acc[4][8][4];
#pragma unroll
        for (int a = 0; a < 4; ++a)
#pragma unroll
            for (int b = 0; b < 8; ++b)
#pragma unroll
                for (int c = 0; c < 4; ++c) acc[a][b][c] = 0.f;

        auto load_stage = [&](int st, int k0) {
            uint32_t abase = sb + st * STAGE_BYTES;
            uint32_t bbase = abase + A_TILE_BYTES;
#pragma unroll
            for (int j = 0; j < 8; ++j) {
                int f  = tid + 128 * j;
                int rr = f >> 3, cc = f & 7;
                CP_ASYNC16(abase + rr * A_STRIDE_B + cc * 16,
                           A + (size_t)(row0 + rr) * K + k0 + cc * 8);
            }
#pragma unroll
            for (int j = 0; j < 8; ++j) {
                int f  = tid + 128 * j;
                int rr = f >> 4, cc = f & 15;
                CP_ASYNC16(bbase + rr * B_STRIDE_B + cc * 16,
                           Bn + (size_t)(k0 + rr) * N + col0 + cc * 8);
            }
        };

        auto compute_stage = [&](int st) {
            uint32_t abase = sb + st * STAGE_BYTES;
            uint32_t bbase = abase + A_TILE_BYTES;
#pragma unroll
            for (int ks = 0; ks < 4; ++ks) {
                const int key = ks * 16 + (mrow & 1) * 8 + mi;
                uint32_t br[4][4];
#pragma unroll
                for (int ntp = 0; ntp < 4; ++ntp) {
                    uint32_t addr = bbase + (uint32_t)key * B_STRIDE_B
                                  + (uint32_t)(wn + ntp * 16 + (mrow >> 1) * 8) * 2;
                    LDSM4T(br[ntp][0], br[ntp][1], br[ntp][2], br[ntp][3], addr);
                }
                const int kb = ks * 16 + lk8;
#pragma unroll
                for (int mt = 0; mt < 4; ++mt) {
                    uint32_t a0, a1, a2, a3;
                    uint32_t addr = abase + (uint32_t)(wm + mt * 16 + lrow) * A_STRIDE_B + kb * 2;
                    LDSM4(a0, a1, a2, a3, addr);
#pragma unroll
                    for (int ntp = 0; ntp < 4; ++ntp) {
                        mma_f16(acc[mt][2 * ntp],     a0, a1, a2, a3, br[ntp][0], br[ntp][1]);
                        mma_f16(acc[mt][2 * ntp + 1], a0, a1, a2, a3, br[ntp][2], br[ntp][3]);
                    }
                }
            }
        };

        load_stage(0, 0);   CP_COMMIT();
        load_stage(1, 64);  CP_COMMIT();

        for (int i = 0; i < KS; ++i) {
            CP_WAIT1();
            __syncthreads();
            if (i + 2 < KS) load_stage((i + 2) % 3, (i + 2) << 6);
            CP_COMMIT();
            compute_stage(i % 3);
        }

        if (!FUSE) {
#pragma unroll
            for (int mt = 0; mt < 4; ++mt) {
                int mrowg = row0 + wm + mt * 16;
#pragma unroll
                for (int nt = 0; nt < 8; ++nt) {
                    int ncol = col0 + wn + nt * 8 + 2 * r;
                    *reinterpret_cast<float2*>(&C[(size_t)(mrowg + g) * N + ncol]) =
                        make_float2(acc[mt][nt][0], acc[mt][nt][1]);
                    *reinterpret_cast<float2*>(&C[(size_t)(mrowg + g + 8) * N + ncol]) =
                        make_float2(acc[mt][nt][2], acc[mt][nt][3]);
                }
            }
            __syncthreads();   // smem stages reused by next tile
            continue;
        }

        // ---- fused QKV epilogue ----
        CP_WAIT0();
        __syncthreads();
        float* S = reinterpret_cast<float*>(smem);   // 128 x 130 floats
#pragma unroll
        for (int mt = 0; mt < 4; ++mt) {
            int mr = wm + mt * 16 + g;
#pragma unroll
            for (int nt = 0; nt < 8; ++nt) {
                int nc = wn + nt * 8 + 2 * r;
                S[mr * 130 + nc]           = acc[mt][nt][0];
                S[mr * 130 + nc + 1]       = acc[mt][nt][1];
                S[(mr + 8) * 130 + nc]     = acc[mt][nt][2];
                S[(mr + 8) * 130 + nc + 1] = acc[mt][nt][3];
            }
        }
        __syncthreads();

        const int head = bx;               // 0..47
        const int row  = tid;              // 0..127
        const int bt   = row0 + row;
        const int b    = bt >> 10;
        const int t    = bt & (T_ - 1);
        const float* v = S + row * 130;

        if (head >= 40) {                  // V head: plain fp16 convert
            __half* dst = g_vh + ((size_t)bt * NKV + (head - 40)) * HD;
#pragma unroll 16
            for (int c2 = 0; c2 < 128; c2 += 2)
                *reinterpret_cast<__half2*>(dst + c2) =
                    __floats2half2_rn(v[c2], v[c2 + 1]);
            __syncthreads();
            continue;
        }

        float ss = 0.f;
#pragma unroll 16
        for (int c = 0; c < 128; ++c) ss += v[c] * v[c];
        float rinv = rsqrtf(ss * (1.0f / HD) + 1e-6f);

        int   segv  = seg[bt];
        int   first = g_first[b];
        float pos   = (segv != 0) ? (float)(t - first) : 1073741824.0f;

        const float* sc = (head < NQ) ? qscale : kscale;
        const float  oscale = (head < NQ) ? 0.08838834764831845f : 1.0f;
        __half* dst = (head < NQ)
            ? g_qh + ((size_t)bt * NQ + head) * HD
            : g_kh + ((size_t)bt * NKV + (head - NQ)) * HD;

#pragma unroll 8
        for (int c2 = 0; c2 < 64; c2 += 2) {
            float lo[2], hi[2];
#pragma unroll
            for (int u = 0; u < 2; ++u) {
                int c = c2 + u;
                float invf = exp2f((-2.0f * (float)c / 128.0f) * 19.931568569324174f);
                float ang  = pos * invf;
                float s_ = sinf(ang), c_ = cosf(ang);
                float n_lo = sc[c] * v[c] * rinv;
                float n_hi = sc[c + 64] * v[c + 64] * rinv;
                lo[u] = (n_lo * c_ - n_hi * s_) * oscale;
                hi[u] = (n_hi * c_ + n_lo * s_) * oscale;
            }
            *reinterpret_cast<__half2*>(dst + c2)      = __floats2half2_rn(lo[0], lo[1]);
            *reinterpret_cast<__half2*>(dst + 64 + c2) = __floats2half2_rn(hi[0], hi[1]);
        }
        __syncthreads();   // smem reused by next tile
    }
}

// ============================================================
// 4) flash attention (unchanged from R8-R11)
// ============================================================
#define FA_STRIDE 136
#define FA_TILE_B (64 * FA_STRIDE * 2)
#define FA_SMEM (5 * FA_TILE_B)

__global__ __launch_bounds__(128)
void fattn_kernel() {
    extern __shared__ char smem[];
    const uint32_t sb = smem_u32(smem);
    const uint32_t qbase = sb;
    const uint32_t kbase0 = sb + FA_TILE_B;
    const uint32_t vbase0 = sb + 2 * FA_TILE_B;

    const int tid  = threadIdx.x;
    const int wid  = tid >> 5;
    const int lane = tid & 31;
    const int g    = lane >> 2;
    const int r    = lane & 3;
    const int lrow = lane & 15;
    const int lk8  = (lane >> 4) * 8;
    const int b  = blockIdx.z;
    const int n  = blockIdx.y;
    const int kh = n >> 2;
    const int t0 = blockIdx.x * 64;

    {
        const __half* qsrc = g_qh + ((size_t)(b * T_ + t0) * NQ + n) * HD;
#pragma unroll
        for (int j = 0; j < 8; ++j) {
            int f = tid + 128 * j;
            int row = f >> 4, c = f & 15;
            CP_ASYNC16(qbase + row * 272 + c * 16,
                       qsrc + (size_t)row * (NQ * HD) + c * 8);
        }
    }
    CP_COMMIT();

    const int start = g_start[b];
    const int s_begin = start & ~63;
    const int ntiles = (t0 + 64 - s_begin) >> 6;

    auto load_kv = [&](int st, int s0) {
        uint32_t kb = kbase0 + st * 2 * FA_TILE_B;
        uint32_t vb = vbase0 + st * 2 * FA_TILE_B;
        const __half* ksrc = g_kh + ((size_t)(b * T_ + s0) * NKV + kh) * HD;
        const __half* vsrc = g_vh + ((size_t)(b * T_ + s0) * NKV + kh) * HD;
#pragma unroll
        for (int j = 0; j < 8; ++j) {
            int f = tid + 128 * j;
            int row = f >> 4, c = f & 15;
            CP_ASYNC16(kb + row * 272 + c * 16, ksrc + (size_t)row * (NKV * HD) + c * 8);
            CP_ASYNC16(vb + row * 272 + c * 16, vsrc + (size_t)row * (NKV * HD) + c * 8);
        }
    };

    if (ntiles > 0) load_kv(0, s_begin);
    CP_COMMIT();

    CP_WAIT1();
    __syncthreads();
    uint32_t qf[8][4];
#pragma unroll
    for (int kt = 0; kt < 8; ++kt) {
        uint32_t addr = qbase + (uint32_t)(wid * 16 + lrow) * 272 + (kt * 16 + lk8) * 2;
        LDSM4(qf[kt][0], qf[kt][1], qf[kt][2], qf[kt][3], addr);
    }

    const int tq0 = t0 + wid * 16 + g;
    const int tq1 = tq0 + 8;

    float m0 = NEG_INF, m1 = NEG_INF, l0 = 0.f, l1 = 0.f;
    float o[16][4];
#pragma unroll
    for (int i = 0; i < 16; ++i)
#pragma unroll
        for (int j = 0; j < 4; ++j) o[i][j] = 0.f;

    for (int it = 0; it < ntiles; ++it) {
        const int s0 = s_begin + it * 64;
        if (it + 1 < ntiles) load_kv((it + 1) & 1, s0 + 64);
        CP_COMMIT();
        CP_WAIT1();
        __syncthreads();

        const uint32_t kb = kbase0 + (it & 1) * 2 * FA_TILE_B;
        const uint32_t vb = vbase0 + (it & 1) * 2 * FA_TILE_B;

        float sfr[8][4];
#pragma unroll
        for (int i = 0; i < 8; ++i)
#pragma unroll
            for (int j = 0; j < 4; ++j) sfr[i][j] = 0.f;

#pragma unroll
        for (int ks = 0; ks < 8; ++ks) {
            const int kcol = ks * 16 + lk8;
#pragma unroll
            for (int np = 0; np < 4; ++np) {
                uint32_t b0, b1, b2, b3;
                uint32_t addr = kb + (uint32_t)(np * 16 + lrow) * 272 + kcol * 2;
                LDSM4(b0, b1, b2, b3, addr);
                mma_f16(sfr[2 * np],     qf[ks][0], qf[ks][1], qf[ks][2], qf[ks][3], b0, b2);
                mma_f16(sfr[2 * np + 1], qf[ks][0], qf[ks][1], qf[ks][2], qf[ks][3], b1, b3);
            }
        }

        float mx0 = NEG_INF, mx1 = NEG_INF;
#pragma unroll
        for (int nt = 0; nt < 8; ++nt) {
#pragma unroll
            for (int c = 0; c < 2; ++c) {
                int s = s0 + nt * 8 + 2 * r + c;
                bool vs = (s >= start);
                float v0 = (vs && s <= tq0) ? sfr[nt][c]     : NEG_INF;
                float v1 = (vs && s <= tq1) ? sfr[nt][2 + c] : NEG_INF;
                sfr[nt][c]     = v0;
                sfr[nt][2 + c] = v1;
                mx0 = fmaxf(mx0, v0);
                mx1 = fmaxf(mx1, v1);
            }
        }
        mx0 = fmaxf(mx0, __shfl_xor_sync(0xffffffffu, mx0, 1));
        mx0 = fmaxf(mx0, __shfl_xor_sync(0xffffffffu, mx0, 2));
        mx1 = fmaxf(mx1, __shfl_xor_sync(0xffffffffu, mx1, 1));
        mx1 = fmaxf(mx1, __shfl_xor_sync(0xffffffffu, mx1, 2));

        float mn0 = fmaxf(m0, mx0), mn1 = fmaxf(m1, mx1);
        float mu0 = (mn0 == NEG_INF) ? 0.f : mn0;
        float mu1 = (mn1 == NEG_INF) ? 0.f : mn1;
        float alpha0 = (m0 == NEG_INF) ? ((mn0 == NEG_INF) ? 1.f : 0.f) : __expf(m0 - mn0);
        float alpha1 = (m1 == NEG_INF) ? ((mn1 == NEG_INF) ? 1.f : 0.f) : __expf(m1 - mn1);
        m0 = mn0; m1 = mn1;

        float ps0 = 0.f, ps1 = 0.f;
#pragma unroll
        for (int nt = 0; nt < 8; ++nt) {
#pragma unroll
            for (int c = 0; c < 2; ++c) {
                float p0 = __expf(sfr[nt][c]     - mu0);
                float p1 = __expf(sfr[nt][2 + c] - mu1);
                sfr[nt][c]     = p0;
                sfr[nt][2 + c] = p1;
                ps0 += p0; ps1 += p1;
            }
        }
        ps0 += __shfl_xor_sync(0xffffffffu, ps0, 1);
        ps0 += __shfl_xor_sync(0xffffffffu, ps0, 2);
        ps1 += __shfl_xor_sync(0xffffffffu, ps1, 1);
        ps1 += __shfl_xor_sync(0xffffffffu, ps1, 2);
        l0 = l0 * alpha0 + ps0;
        l1 = l1 * alpha1 + ps1;

#pragma unroll
        for (int nt = 0; nt < 16; ++nt) {
            o[nt][0] *= alpha0; o[nt][1] *= alpha0;
            o[nt][2] *= alpha1; o[nt][3] *= alpha1;
        }

#pragma unroll
        for (int kt = 0; kt < 4; ++kt) {
            uint32_t a0 = h2_as_u32(__floats2half2_rn(sfr[2 * kt][0],     sfr[2 * kt][1]));
            uint32_t a1 = h2_as_u32(__floats2half2_rn(sfr[2 * kt][2],     sfr[2 * kt][3]));
            uint32_t a2 = h2_as_u32(__floats2half2_rn(sfr[2 * kt + 1][0], sfr[2 * kt + 1][1]));
            uint32_t a3 = h2_as_u32(__floats2half2_rn(sfr[2 * kt + 1][2], sfr[2 * kt + 1][3]));
            const int mrow = lane >> 3, mi = lane & 7;
            const int key = kt * 16 + (mrow & 1) * 8 + mi;
#pragma unroll
            for (int dp = 0; dp < 8; ++dp) {
                uint32_t v0, v1, v2, v3;
                uint32_t addr = vb + (uint32_t)key * 272 + (dp * 16 + (mrow >> 1) * 8) * 2;
                LDSM4T(v0, v1, v2, v3, addr);
                mma_f16(o[2 * dp],     a0, a1, a2, a3, v0, v1);
                mma_f16(o[2 * dp + 1], a0, a1, a2, a3, v2, v3);
            }
        }
        __syncthreads();
    }

    float inv0 = (l0 > 0.f) ? (1.0f / l0) : 0.f;
    float inv1 = (l1 > 0.f) ? (1.0f / l1) : 0.f;
    __half* o0 = g_oh + ((size_t)(b * T_ + tq0) * NQ + n) * HD;
    __half* o1 = g_oh + ((size_t)(b * T_ + tq1) * NQ + n) * HD;
#pragma unroll
    for (int nt = 0; nt < 16; ++nt) {
        int col = nt * 8 + 2 * r;
        *reinterpret_cast<__half2*>(o0 + col) =
            __floats2half2_rn(o[nt][0] * inv0, o[nt][1] * inv0);
        *reinterpret_cast<__half2*>(o1 + col) =
            __floats2half2_rn(o[nt][2] * inv1, o[nt][3] * inv1);
    }
}

// ============================================================
// launch
// ============================================================
extern "C" void kernel_launch(void* const* d_in, const int* in_sizes, int n_in,
                              void* d_out, int out_size) {
    const float* x       = (const float*)d_in[0];
    const float* wq      = (const float*)d_in[1];
    const float* wk      = (const float*)d_in[2];
    const float* wv      = (const float*)d_in[3];
    const float* wo      = (const float*)d_in[4];
    const float* q_scale = (const float*)d_in[5];
    const float* k_scale = (const float*)d_in[6];
    const int*   seg     = (const int*)d_in[9];
    float* out = (float*)d_out;

    __half *pxh, *pwqkvh, *pwoh, *poh;
    cudaGetSymbolAddress((void**)&pxh, g_xh);
    cudaGetSymbolAddress((void**)&pwqkvh, g_wqkvh);
    cudaGetSymbolAddress((void**)&pwoh, g_woh);
    cudaGetSymbolAddress((void**)&poh, g_oh);

    cudaFuncSetAttribute(gemm_f16_kernel<true>, cudaFuncAttributeMaxDynamicSharedMemorySize,
                         GEMM_SMEM);
    cudaFuncSetAttribute(gemm_f16_kernel<false>, cudaFuncAttributeMaxDynamicSharedMemorySize,
                         GEMM_SMEM);
    cudaFuncSetAttribute(fattn_kernel, cudaFuncAttributeMaxDynamicSharedMemorySize,
                         FA_SMEM);

    startfirst_kernel<<<B_, 256>>>(seg);
    f32_to_f16_kernel<<<(MTOT * D_ / 4) / 256, 256>>>(
        (const float4*)x, (__half2*)pxh);
    pack_wqkv_f16_kernel<<<((size_t)D_ * QKV_N / 4) / 256, 256>>>(
        (const float4*)wq, (const float4*)wk, (const float4*)wv,
        (__half2*)pwqkvh);
    f32_to_f16_kernel<<<((size_t)NQ * HD * D_ / 4) / 256, 256>>>(
        (const float4*)wo, (__half2*)pwoh);

    // fused QKV projection + RMSNorm + RoPE (persistent: 768 tiles on 296 CTAs)
    gemm_f16_kernel<true><<<PERSIST_GRID, 128, GEMM_SMEM>>>(
        pxh, pwqkvh, nullptr, QKV_N, D_, (QKV_N / 128) * (MTOT / 128), QKV_N / 128,
        q_scale, k_scale, seg);

    fattn_kernel<<<dim3(T_ / 64, NQ, B_), 128, FA_SMEM>>>();

    // output projection (persistent: 512 tiles on 296 CTAs)
    gemm_f16_kernel<false><<<PERSIST_GRID, 128, GEMM_SMEM>>>(
        poh, pwoh, out, D_, NQ * HD, (D_ / 128) * (MTOT / 128), D_ / 128,
        nullptr, nullptr, nullptr);
}